// round 10
// baseline (speedup 1.0000x reference)
#include <cuda_runtime.h>
#include <cuda_bf16.h>
#include <math.h>

#define B 8
#define C 192
#define HEADS 4
#define HD 48
#define HGT 128
#define WID 128
#define NPIX 16384
#define CTXD 256
#define HID 510
#define FFN2 1020
#define NSPLIT 32
#define KPC (C / 2)        // 96 k-pairs for Cin=192
#define KPH 256            // 256 k-pairs for padded gelu (510->512)
#define QKVP (3 * C / 2)   // 288 pairs in qkv
#define FFP  (FFN2 / 2)    // 510 pairs in ffn intermediate

// ---------------- scratch (static device globals; allocation-free) ----------------
__device__ unsigned g_xn_pk [B * KPC * NPIX];   // layernorm output, bf16 k-pair packed
__device__ unsigned g_buf1_pk[B * FFP * NPIX];  // conv1x1 outputs, packed channel pairs
__device__ unsigned g_buf2_pk[B * QKVP * NPIX]; // qkv dwconv output, packed
__device__ unsigned g_mid_pk[B * KPC * NPIX];   // out_local + out_global, packed bf16
__device__ float    g_x2  [B * C    * NPIX];    // x after attention branch (fp32 anchor)
__device__ unsigned g_gelu_pk[B * KPH * NPIX];  // gelu(y1)*y2, bf16 packed, padded
__device__ unsigned g_wqkv_pk [3 * C * KPC];
__device__ unsigned g_wffin_pk[FFN2  * KPC];
__device__ unsigned g_wproj_pk[C * KPC];
__device__ unsigned g_wout_pk [C * KPH];
__device__ float g_attn_part[B * HEADS * NSPLIT * HD * HD];
__device__ float g_attn[B * HEADS * HD * HD];
__device__ float g_temp [B * HEADS];
__device__ float g_vgate[B * C];
__device__ float g_invq [B * C];
__device__ float g_invk [B * C];
__device__ float g_ssq_part[B * 3 * C * 16];

// ---------------- helpers ----------------
__device__ __forceinline__ unsigned pack_bf2(float lo, float hi) {
    __nv_bfloat162 h = __floats2bfloat162_rn(lo, hi);
    return *reinterpret_cast<unsigned*>(&h);
}
__device__ __forceinline__ float2 up2(unsigned u) {
    __nv_bfloat162 h = *reinterpret_cast<__nv_bfloat162*>(&u);
    return make_float2(__bfloat162float(h.x), __bfloat162float(h.y));
}
__device__ __forceinline__ void mma_bf16(float* d, const unsigned* a, const unsigned* b) {
    asm volatile(
        "mma.sync.aligned.m16n8k16.row.col.f32.bf16.bf16.f32 "
        "{%0,%1,%2,%3}, {%4,%5,%6,%7}, {%8,%9}, {%0,%1,%2,%3};\n"
        : "+f"(d[0]), "+f"(d[1]), "+f"(d[2]), "+f"(d[3])
        : "r"(a[0]), "r"(a[1]), "r"(a[2]), "r"(a[3]), "r"(b[0]), "r"(b[1]));
}
__device__ __forceinline__ unsigned smem_u32(const void* p) {
    return (unsigned)__cvta_generic_to_shared(p);
}
__device__ __forceinline__ void cp16(unsigned dst, const void* src) {
    asm volatile("cp.async.cg.shared.global [%0], [%1], 16;" :: "r"(dst), "l"(src));
}
__device__ __forceinline__ void cp16p(unsigned dst, const void* src, bool pred) {
    int sz = pred ? 16 : 0;
    asm volatile("cp.async.cg.shared.global [%0], [%1], 16, %2;" :: "r"(dst), "l"(src), "r"(sz));
}
__device__ __forceinline__ void cp_commit() { asm volatile("cp.async.commit_group;"); }
template <int N>
__device__ __forceinline__ void cp_wait() { asm volatile("cp.async.wait_group %0;" :: "n"(N)); }

// ---------------- context adapters ----------------
__global__ void ctx_kernel(const float* __restrict__ ctx,
                           const float* __restrict__ ta_w1, const float* __restrict__ ta_b1,
                           const float* __restrict__ ta_w2, const float* __restrict__ ta_b2,
                           const float* __restrict__ vg_w,  const float* __restrict__ vg_b,
                           const float* __restrict__ base_temp) {
    __shared__ float sctx[CTXD];
    __shared__ float hid[HD];
    int b = blockIdx.x, t = threadIdx.x;
    sctx[t] = ctx[b * CTXD + t];
    __syncthreads();
    if (t < HD) {
        float s = ta_b1[t];
        for (int k = 0; k < CTXD; k++) s += sctx[k] * ta_w1[t * CTXD + k];
        hid[t] = fmaxf(s, 0.f);
    }
    __syncthreads();
    if (t < HEADS) {
        float s = ta_b2[t];
        for (int k = 0; k < HD; k++) s += hid[k] * ta_w2[t * HD + k];
        float f = 1.f / (1.f + expf(-s)) * 2.f + 0.5f;
        g_temp[b * HEADS + t] = base_temp[t] * f;
    }
    if (t < C) {
        float s = vg_b[t];
        for (int k = 0; k < CTXD; k++) s += sctx[k] * vg_w[t * CTXD + k];
        g_vgate[b * C + t] = 1.f / (1.f + expf(-s));
    }
}

// ---------------- weight packing (fp32 -> bf16 k-pairs) ----------------
__global__ void pack_w_kernel(const float* __restrict__ src, unsigned* __restrict__ dst,
                              int O, int Cin, int Kp) {
    int i = blockIdx.x * 256 + threadIdx.x;
    if (i >= O * Kp) return;
    int o = i / Kp, p = i % Kp;
    float f0 = (2 * p     < Cin) ? src[(size_t)o * Cin + 2 * p]     : 0.f;
    float f1 = (2 * p + 1 < Cin) ? src[(size_t)o * Cin + 2 * p + 1] : 0.f;
    dst[i] = pack_bf2(f0, f1);
}

// ---------------- layernorm over channels -> packed bf16 ----------------
__global__ void ln_kernel(const float* __restrict__ x, const float* __restrict__ w,
                          const float* __restrict__ bias, unsigned* __restrict__ out) {
    int tid = blockIdx.x * 256 + threadIdx.x;   // B*NPIX threads
    int b = tid >> 14, n = tid & (NPIX - 1);
    const float* xp = x + (size_t)b * C * NPIX + n;
    float s = 0.f, ss = 0.f;
    #pragma unroll 8
    for (int c = 0; c < C; c++) { float v = xp[(size_t)c * NPIX]; s += v; ss += v * v; }
    const float ic = 1.f / C;
    float mu = s * ic;
    float rstd = rsqrtf(ss * ic - mu * mu + 1e-5f);
    unsigned* op = out + (size_t)b * KPC * NPIX + n;
    #pragma unroll 4
    for (int p = 0; p < KPC; p++) {
        float v0 = (xp[(size_t)(2 * p)     * NPIX] - mu) * rstd * w[2 * p]     + bias[2 * p];
        float v1 = (xp[(size_t)(2 * p + 1) * NPIX] - mu) * rstd * w[2 * p + 1] + bias[2 * p + 1];
        op[(size_t)p * NPIX] = pack_bf2(v0, v1);
    }
}

// ============ bf16 GEMM core (shared macro body) ============
#define GEMM_BODY(MMAOP)                                                          \
    int b  = blockIdx.z;                                                          \
    int o0 = blockIdx.y * 64;                                                     \
    int n0 = blockIdx.x * 256;                                                    \
    const unsigned* Xb = Xpk + (size_t)b * Kpairs * NPIX + n0;                    \
    int tid  = threadIdx.x;                                                       \
    int warp = tid >> 5, lane = tid & 31;                                         \
    int wm = warp >> 2, wn = warp & 3;                                            \
    int mrow = lane >> 2, kq = lane & 3;                                          \
    float acc[2][8][4];                                                           \
    _Pragma("unroll") for (int mt = 0; mt < 2; mt++)                              \
        _Pragma("unroll") for (int nt = 0; nt < 8; nt++)                          \
            _Pragma("unroll") for (int q = 0; q < 4; q++) acc[mt][nt][q] = 0.f;   \
    int am  = tid >> 2;                                                           \
    int ak4 = (tid & 3) * 4;                                                      \
    bool apred = (o0 + am) < O;                                                   \
    const unsigned* aSrcBase = Apk + (size_t)(o0 + am) * Kpairs + ak4;            \
    int ktiles = Kpairs >> 4;                                                     \
    auto LOAD = [&](int kt, int buf) {                                            \
        int p0 = kt << 4;                                                         \
        cp16p(smem_u32(&sA[buf][am][ak4]), aSrcBase + p0, apred);                 \
        _Pragma("unroll") for (int i = 0; i < 4; i++) {                           \
            int e = tid + i * 256;                                                \
            int kk = e >> 6;                                                      \
            int nn = (e & 63) * 4;                                                \
            cp16(smem_u32(&sB[buf][kk][nn]), Xb + (size_t)(p0 + kk) * NPIX + nn); \
        }                                                                         \
        cp_commit();                                                              \
    };                                                                            \
    LOAD(0, 0);                                                                   \
    for (int kt = 0; kt < ktiles; kt++) {                                         \
        int cur = kt & 1;                                                         \
        if (kt + 1 < ktiles) { LOAD(kt + 1, cur ^ 1); cp_wait<1>(); }             \
        else cp_wait<0>();                                                        \
        __syncthreads();                                                          \
        _Pragma("unroll") for (int ks = 0; ks < 2; ks++) {                        \
            const int p0 = ks * 8;                                                \
            unsigned afr[2][4], bfr[8][2];                                        \
            _Pragma("unroll") for (int mt = 0; mt < 2; mt++) {                    \
                int m = wm * 32 + mt * 16 + mrow;                                 \
                afr[mt][0] = sA[cur][m    ][p0 + kq];                             \
                afr[mt][1] = sA[cur][m + 8][p0 + kq];                             \
                afr[mt][2] = sA[cur][m    ][p0 + kq + 4];                         \
                afr[mt][3] = sA[cur][m + 8][p0 + kq + 4];                         \
            }                                                                     \
            _Pragma("unroll") for (int nt = 0; nt < 8; nt++) {                    \
                int n = wn * 64 + nt * 8 + mrow;                                  \
                bfr[nt][0] = sB[cur][p0 + kq    ][n];                             \
                bfr[nt][1] = sB[cur][p0 + kq + 4][n];                             \
            }                                                                     \
            _Pragma("unroll") for (int mt = 0; mt < 2; mt++)                      \
                _Pragma("unroll") for (int nt = 0; nt < 8; nt++)                  \
                    MMAOP(acc[mt][nt], afr[mt], bfr[nt]);                         \
        }                                                                         \
        __syncthreads();                                                          \
    }

// fp32 output + optional fp32 residual (proj, ffn_out)
__global__ void __launch_bounds__(256) mma_gemm_bf16(const unsigned* __restrict__ Apk,
                                                     const unsigned* __restrict__ Xpk,
                                                     float* __restrict__ Y,
                                                     const float* __restrict__ Res,
                                                     int O, int Kpairs) {
    __shared__ unsigned sA[2][64][20];
    __shared__ unsigned sB[2][16][264];
    GEMM_BODY(mma_bf16)
    size_t base = (size_t)b * O * NPIX;
    #pragma unroll
    for (int mt = 0; mt < 2; mt++) {
        #pragma unroll
        for (int nt = 0; nt < 8; nt++) {
            int ncol = n0 + wn * 64 + nt * 8 + 2 * kq;
            int r0 = o0 + wm * 32 + mt * 16 + mrow;
            if (r0 < O) {
                size_t off = base + (size_t)r0 * NPIX + ncol;
                float2 rr = Res ? *reinterpret_cast<const float2*>(Res + off)
                                : make_float2(0.f, 0.f);
                *reinterpret_cast<float2*>(Y + off) =
                    make_float2(acc[mt][nt][0] + rr.x, acc[mt][nt][1] + rr.y);
            }
            int r1 = r0 + 8;
            if (r1 < O) {
                size_t off = base + (size_t)r1 * NPIX + ncol;
                float2 rr = Res ? *reinterpret_cast<const float2*>(Res + off)
                                : make_float2(0.f, 0.f);
                *reinterpret_cast<float2*>(Y + off) =
                    make_float2(acc[mt][nt][2] + rr.x, acc[mt][nt][3] + rr.y);
            }
        }
    }
}

// packed bf16 channel-pair output (qkv / ffn_in). O must be even.
__global__ void __launch_bounds__(256) mma_gemm_bf16_pk(const unsigned* __restrict__ Apk,
                                                        const unsigned* __restrict__ Xpk,
                                                        unsigned* __restrict__ Ypk,
                                                        int O, int Kpairs) {
    __shared__ unsigned sA[2][64][20];
    __shared__ unsigned sB[2][16][264];
    GEMM_BODY(mma_bf16)
    size_t base = (size_t)b * (O >> 1) * NPIX;
    bool writer = ((mrow & 1) == 0);
    #pragma unroll
    for (int mt = 0; mt < 2; mt++) {
        #pragma unroll
        for (int nt = 0; nt < 8; nt++) {
            int ncol = n0 + wn * 64 + nt * 8 + 2 * kq;
            int r0 = o0 + wm * 32 + mt * 16 + mrow;
            float p0 = __shfl_xor_sync(0xffffffffu, acc[mt][nt][0], 4);
            float p1 = __shfl_xor_sync(0xffffffffu, acc[mt][nt][1], 4);
            float p2 = __shfl_xor_sync(0xffffffffu, acc[mt][nt][2], 4);
            float p3 = __shfl_xor_sync(0xffffffffu, acc[mt][nt][3], 4);
            if (writer && r0 < O) {
                size_t off = base + (size_t)(r0 >> 1) * NPIX + ncol;
                *reinterpret_cast<uint2*>(Ypk + off) =
                    make_uint2(pack_bf2(acc[mt][nt][0], p0), pack_bf2(acc[mt][nt][1], p1));
            }
            if (writer && r0 + 8 < O) {
                size_t off = base + (size_t)((r0 + 8) >> 1) * NPIX + ncol;
                *reinterpret_cast<uint2*>(Ypk + off) =
                    make_uint2(pack_bf2(acc[mt][nt][2], p2), pack_bf2(acc[mt][nt][3], p3));
            }
        }
    }
}

// ---------------- depthwise 3x3 on packed pairs (dual-channel, 4 px / thread) ----------------
__device__ __forceinline__ void dw3x3_pk_v4(const unsigned* __restrict__ ip,
                                            const float* __restrict__ wp0,
                                            const float* __restrict__ wp1,
                                            int y, int x, float* a0, float* a1) {
    a0[0] = a0[1] = a0[2] = a0[3] = 0.f;
    a1[0] = a1[1] = a1[2] = a1[3] = 0.f;
    #pragma unroll
    for (int ky = 0; ky < 3; ky++) {
        int yy = y + ky - 1;
        if (yy < 0 || yy >= HGT) continue;
        const unsigned* row = ip + yy * WID + x;
        uint4 m = *reinterpret_cast<const uint4*>(row);
        unsigned lu = (x > 0)   ? row[-1] : 0u;
        unsigned ru = (x < 124) ? row[4]  : 0u;
        float2 L = up2(lu), X0 = up2(m.x), X1 = up2(m.y), X2 = up2(m.z), X3 = up2(m.w), R = up2(ru);
        float w00 = wp0[ky * 3], w01 = wp0[ky * 3 + 1], w02 = wp0[ky * 3 + 2];
        float w10 = wp1[ky * 3], w11 = wp1[ky * 3 + 1], w12 = wp1[ky * 3 + 2];
        a0[0] += L.x  * w00 + X0.x * w01 + X1.x * w02;
        a0[1] += X0.x * w00 + X1.x * w01 + X2.x * w02;
        a0[2] += X1.x * w00 + X2.x * w01 + X3.x * w02;
        a0[3] += X2.x * w00 + X3.x * w01 + R.x  * w02;
        a1[0] += L.y  * w10 + X0.y * w11 + X1.y * w12;
        a1[1] += X0.y * w10 + X1.y * w11 + X2.y * w12;
        a1[2] += X1.y * w10 + X2.y * w11 + X3.y * w12;
        a1[3] += X2.y * w10 + X3.y * w11 + R.y  * w12;
    }
}

// ---------------- qkv dwconv (packed->packed) + q/k sumsq partials ----------------
__global__ void dwconv_qkv_pk(const unsigned* __restrict__ in, const float* __restrict__ w,
                              unsigned* __restrict__ out) {
    __shared__ float red[256];
    int idx = blockIdx.x * 256 + threadIdx.x;   // B*QKVP*NPIX/4
    int n = (idx & (NPIX / 4 - 1)) * 4;
    int bp = idx >> 12;                          // b*QKVP + pair
    int p = bp % QKVP;                           // 0..287
    int y = n >> 7, x = n & 127;
    const unsigned* ip = in + (size_t)bp * NPIX;
    float a0[4], a1[4];
    dw3x3_pk_v4(ip, w + (2 * p) * 9, w + (2 * p + 1) * 9, y, x, a0, a1);
    unsigned o4[4];
    #pragma unroll
    for (int j = 0; j < 4; j++) o4[j] = pack_bf2(a0[j], a1[j]);
    *reinterpret_cast<uint4*>(out + (size_t)bp * NPIX + n) =
        make_uint4(o4[0], o4[1], o4[2], o4[3]);
    if (p < 2 * KPC) {   // q,k pairs (channels < 384)
        int b = bp / QKVP;
        float ss0 = 0.f, ss1 = 0.f;
        #pragma unroll
        for (int j = 0; j < 4; j++) {
            float2 v = up2(o4[j]);
            ss0 += v.x * v.x; ss1 += v.y * v.y;
        }
        int blk = blockIdx.x & 15;
        red[threadIdx.x] = ss0; __syncthreads();
        for (int s = 128; s > 0; s >>= 1) {
            if (threadIdx.x < s) red[threadIdx.x] += red[threadIdx.x + s];
            __syncthreads();
        }
        if (threadIdx.x == 0) g_ssq_part[((size_t)b * 3 * C + 2 * p) * 16 + blk] = red[0];
        __syncthreads();
        red[threadIdx.x] = ss1; __syncthreads();
        for (int s = 128; s > 0; s >>= 1) {
            if (threadIdx.x < s) red[threadIdx.x] += red[threadIdx.x + s];
            __syncthreads();
        }
        if (threadIdx.x == 0) g_ssq_part[((size_t)b * 3 * C + 2 * p + 1) * 16 + blk] = red[0];
    }
}

__global__ void inv_kernel() {
    int i = blockIdx.x * 256 + threadIdx.x;
    if (i >= 2 * B * C) return;
    int isK = i >= B * C;
    int lin = isK ? i - B * C : i;
    int b = lin / C, c = lin % C;
    int bc = b * 3 * C + (isK ? C : 0) + c;
    float s = 0.f;
    #pragma unroll
    for (int j = 0; j < 16; j++) s += g_ssq_part[(size_t)bc * 16 + j];
    float inv = 1.f / fmaxf(sqrtf(s), 1e-12f);
    (isK ? g_invk : g_invq)[b * C + c] = inv;
}

// ---------------- fused FFN dwconv + gelu gate (packed -> packed) ----------------
__global__ void dwgelu_pk_kernel(const unsigned* __restrict__ in, const float* __restrict__ w,
                                 unsigned* __restrict__ outg) {
    int idx = blockIdx.x * 256 + threadIdx.x;   // B * KPH * NPIX/4 threads
    int n = (idx & (NPIX / 4 - 1)) * 4;
    int bc = idx >> 12;                          // b*KPH + pair
    int p = bc & (KPH - 1), b = bc >> 8;
    unsigned* op = outg + (size_t)bc * NPIX + n;
    if (p == KPH - 1) {
        *reinterpret_cast<uint4*>(op) = make_uint4(0u, 0u, 0u, 0u);
        return;
    }
    int c = 2 * p;
    int y = n >> 7, x = n & 127;
    const unsigned* base = in + (size_t)b * FFP * NPIX;
    float a1a[4], a1b[4], a2a[4], a2b[4];
    dw3x3_pk_v4(base + (size_t)p * NPIX,         w + c * 9,         w + (c + 1) * 9,       y, x, a1a, a1b);
    dw3x3_pk_v4(base + (size_t)(p + 255) * NPIX, w + (c + HID) * 9, w + (c + 1 + HID) * 9, y, x, a2a, a2b);
    unsigned o4[4];
    #pragma unroll
    for (int j = 0; j < 4; j++) {
        float ga = 0.5f * a1a[j] * (1.f + erff(a1a[j] * 0.70710678118654752f)) * a2a[j];
        float gb = 0.5f * a1b[j] * (1.f + erff(a1b[j] * 0.70710678118654752f)) * a2b[j];
        o4[j] = pack_bf2(ga, gb);
    }
    *reinterpret_cast<uint4*>(op) = make_uint4(o4[0], o4[1], o4[2], o4[3]);
}

// ---------------- attention gram partials (packed q,k) ----------------
__global__ void attn_part_kernel() {
    __shared__ float sQ[HD][33], sK[HD][33];
    int bh = blockIdx.x / NSPLIT, sp = blockIdx.x % NSPLIT;
    int b = bh / HEADS, h = bh % HEADS;
    const unsigned* qpk = g_buf2_pk + ((size_t)b * QKVP + h * (HD / 2)) * NPIX;
    const unsigned* kpk = qpk + (size_t)KPC * NPIX;
    int t = threadIdx.x;
    int i0 = (t >> 4) * 3, j0 = (t & 15) * 3;
    float acc[3][3];
    #pragma unroll
    for (int a = 0; a < 3; a++)
        #pragma unroll
        for (int c2 = 0; c2 < 3; c2++) acc[a][c2] = 0.f;
    int n0 = sp * (NPIX / NSPLIT);
    for (int ch = 0; ch < NPIX / NSPLIT; ch += 32) {
        for (int e = t; e < (HD / 2) * 32; e += 256) {
            int p = e >> 5, nn = e & 31;
            float2 q2 = up2(qpk[(size_t)p * NPIX + n0 + ch + nn]);
            float2 k2 = up2(kpk[(size_t)p * NPIX + n0 + ch + nn]);
            sQ[2 * p][nn] = q2.x; sQ[2 * p + 1][nn] = q2.y;
            sK[2 * p][nn] = k2.x; sK[2 * p + 1][nn] = k2.y;
        }
        __syncthreads();
        #pragma unroll 4
        for (int kk = 0; kk < 32; kk++) {
            float qa[3], ka[3];
            #pragma unroll
            for (int a = 0; a < 3; a++) { qa[a] = sQ[i0 + a][kk]; ka[a] = sK[j0 + a][kk]; }
            #pragma unroll
            for (int a = 0; a < 3; a++)
                #pragma unroll
                for (int c2 = 0; c2 < 3; c2++) acc[a][c2] += qa[a] * ka[c2];
        }
        __syncthreads();
    }
    float* outp = g_attn_part + (size_t)blockIdx.x * HD * HD;
    #pragma unroll
    for (int a = 0; a < 3; a++)
        #pragma unroll
        for (int c2 = 0; c2 < 3; c2++) outp[(i0 + a) * HD + j0 + c2] = acc[a][c2];
}

// ---------------- softmax + fold norms/scale/temp/vgate ----------------
__global__ void softmax_kernel() {
    __shared__ float row[HD];
    __shared__ float mx, sm;
    int rid = blockIdx.x;
    int i  = rid % HD;
    int bh = rid / HD;
    int b = bh / HEADS, h = bh % HEADS;
    int t = threadIdx.x;
    const float scale = 0.14433756729740643f;
    if (t < HD) {
        float s = 0.f;
        const float* pp = g_attn_part + (size_t)bh * NSPLIT * HD * HD + i * HD + t;
        for (int sp = 0; sp < NSPLIT; sp++) s += pp[(size_t)sp * HD * HD];
        row[t] = s * g_invq[b * C + h * HD + i] * g_invk[b * C + h * HD + t]
                   * scale * g_temp[b * HEADS + h];
    }
    __syncthreads();
    if (t == 0) { float m = -1e30f; for (int j = 0; j < HD; j++) m = fmaxf(m, row[j]); mx = m; }
    __syncthreads();
    if (t < HD) row[t] = expf(row[t] - mx);
    __syncthreads();
    if (t == 0) { float s2 = 0.f; for (int j = 0; j < HD; j++) s2 += row[j]; sm = s2; }
    __syncthreads();
    if (t < HD)
        g_attn[(size_t)bh * HD * HD + i * HD + t] = row[t] / sm * g_vgate[b * C + h * HD + t];
}

// ---------------- fused: g_mid_pk = pack( dwconv(v, w_local) + attn @ v ) ----------------
// Thread layout: 192 active threads = 24 channel-pairs x 8 pixel-groups (8 px each).
__global__ void ogl_kernel(const float* __restrict__ w_local) {
    __shared__ float sA[HD * HD];
    __shared__ float sV[HD][65];
    int bh = blockIdx.y;
    int b = bh / HEADS, h = bh % HEADS;
    int n0 = blockIdx.x * 64;
    const unsigned* vpk = g_buf2_pk + ((size_t)b * QKVP + 2 * KPC + h * (HD / 2)) * NPIX;
    int t = threadIdx.x;
    for (int e = t; e < HD * HD; e += 256) sA[e] = g_attn[(size_t)bh * HD * HD + e];
    for (int e = t; e < (HD / 2) * 64; e += 256) {
        int p = e >> 6, n = e & 63;
        float2 v2 = up2(vpk[(size_t)p * NPIX + n0 + n]);
        sV[2 * p][n] = v2.x; sV[2 * p + 1][n] = v2.y;
    }
    __syncthreads();
    if (t >= 192) return;
    int p = t >> 3;            // channel pair 0..23
    int g = (t & 7) * 8;       // pixel offset 0..56
    int c0 = 2 * p;
    float acc0[8], acc1[8];
    #pragma unroll
    for (int q = 0; q < 8; q++) { acc0[q] = 0.f; acc1[q] = 0.f; }
    #pragma unroll 4
    for (int j = 0; j < HD; j++) {
        float a0 = sA[c0 * HD + j];
        float a1 = sA[(c0 + 1) * HD + j];
        #pragma unroll
        for (int q = 0; q < 8; q++) {
            float v = sV[j][g + q];
            acc0[q] += a0 * v;
            acc1[q] += a1 * v;
        }
    }
    // local depthwise conv for both channels of the pair, 8 px in two halves
    int nb = n0 + g;
    int y = nb >> 7, x = nb & 127;
    const float* wl0 = w_local + (h * HD + c0) * 9;
    const float* wl1 = wl0 + 9;
    float d0a[4], d1a[4], d0b[4], d1b[4];
    dw3x3_pk_v4(vpk + (size_t)p * NPIX, wl0, wl1, y, x,     d0a, d1a);
    dw3x3_pk_v4(vpk + (size_t)p * NPIX, wl0, wl1, y, x + 4, d0b, d1b);
    unsigned o[8];
    #pragma unroll
    for (int q = 0; q < 4; q++) {
        o[q]     = pack_bf2(acc0[q]     + d0a[q], acc1[q]     + d1a[q]);
        o[q + 4] = pack_bf2(acc0[q + 4] + d0b[q], acc1[q + 4] + d1b[q]);
    }
    unsigned* op = g_mid_pk + ((size_t)b * KPC + h * 24 + p) * NPIX + nb;
    *reinterpret_cast<uint4*>(op)     = make_uint4(o[0], o[1], o[2], o[3]);
    *reinterpret_cast<uint4*>(op + 4) = make_uint4(o[4], o[5], o[6], o[7]);
}

// ---------------- launch ----------------
extern "C" void kernel_launch(void* const* d_in, const int* in_sizes, int n_in,
                              void* d_out, int out_size) {
    const float* x        = (const float*)d_in[0];
    const float* ctx      = (const float*)d_in[1];
    const float* ln1_w    = (const float*)d_in[2];
    const float* ln1_b    = (const float*)d_in[3];
    const float* ln2_w    = (const float*)d_in[4];
    const float* ln2_b    = (const float*)d_in[5];
    const float* w_qkv    = (const float*)d_in[6];
    const float* w_qkv_dw = (const float*)d_in[7];
    const float* w_proj   = (const float*)d_in[8];
    const float* base_temp= (const float*)d_in[9];
    const float* ta_w1    = (const float*)d_in[10];
    const float* ta_b1    = (const float*)d_in[11];
    const float* ta_w2    = (const float*)d_in[12];
    const float* ta_b2    = (const float*)d_in[13];
    const float* vg_w     = (const float*)d_in[14];
    const float* vg_b     = (const float*)d_in[15];
    const float* w_local  = (const float*)d_in[16];
    const float* w_ffn_in = (const float*)d_in[17];
    const float* w_ffn_dw = (const float*)d_in[18];
    const float* w_ffn_out= (const float*)d_in[19];
    float* out = (float*)d_out;

    unsigned *p_xn, *p_buf1, *p_buf2, *p_mid, *p_gelu, *p_wqkv, *p_wffin, *p_wproj, *p_wout;
    float *p_x2;
    cudaGetSymbolAddress((void**)&p_xn,    g_xn_pk);
    cudaGetSymbolAddress((void**)&p_buf1,  g_buf1_pk);
    cudaGetSymbolAddress((void**)&p_buf2,  g_buf2_pk);
    cudaGetSymbolAddress((void**)&p_mid,   g_mid_pk);
    cudaGetSymbolAddress((void**)&p_x2,    g_x2);
    cudaGetSymbolAddress((void**)&p_gelu,  g_gelu_pk);
    cudaGetSymbolAddress((void**)&p_wqkv,  g_wqkv_pk);
    cudaGetSymbolAddress((void**)&p_wffin, g_wffin_pk);
    cudaGetSymbolAddress((void**)&p_wproj, g_wproj_pk);
    cudaGetSymbolAddress((void**)&p_wout,  g_wout_pk);

    ctx_kernel<<<B, 256>>>(ctx, ta_w1, ta_b1, ta_w2, ta_b2, vg_w, vg_b, base_temp);
    pack_w_kernel<<<(3 * C * KPC + 255) / 256, 256>>>(w_qkv, p_wqkv, 3 * C, C, KPC);
    pack_w_kernel<<<(FFN2 * KPC + 255) / 256, 256>>>(w_ffn_in, p_wffin, FFN2, C, KPC);
    pack_w_kernel<<<(C * KPC + 255) / 256, 256>>>(w_proj, p_wproj, C, C, KPC);
    pack_w_kernel<<<(C * KPH + 255) / 256, 256>>>(w_ffn_out, p_wout, C, HID, KPH);

    // LN1 -> packed bf16
    ln_kernel<<<(B * NPIX) / 256, 256>>>(x, ln1_w, ln1_b, p_xn);
    // qkv conv1x1 (576 x 192), bf16 -> packed pairs
    mma_gemm_bf16_pk<<<dim3(NPIX / 256, (3 * C) / 64, B), 256>>>(p_wqkv, p_xn, p_buf1, 3 * C, KPC);
    // qkv dwconv packed->packed + q/k sumsq partials
    dwconv_qkv_pk<<<(B * QKVP * NPIX / 4) / 256, 256>>>(p_buf1, w_qkv_dw, p_buf2);
    inv_kernel<<<(2 * B * C + 255) / 256, 256>>>();
    attn_part_kernel<<<B * HEADS * NSPLIT, 256>>>();
    softmax_kernel<<<B * HEADS * HD, 64>>>();
    // fused out_local + out_global -> g_mid packed bf16
    ogl_kernel<<<dim3(NPIX / 64, B * HEADS), 256>>>(w_local);
    // proj conv1x1 (bf16) + residual(x) -> g_x2 fp32
    mma_gemm_bf16<<<dim3(NPIX / 256, C / 64, B), 256>>>(p_wproj, p_mid, p_x2, x, C, KPC);
    // LN2 -> packed bf16
    ln_kernel<<<(B * NPIX) / 256, 256>>>(p_x2, ln2_w, ln2_b, p_xn);
    // ffn_in conv1x1 (1020 x 192), bf16 -> packed pairs
    mma_gemm_bf16_pk<<<dim3(NPIX / 256, (FFN2 + 63) / 64, B), 256>>>(p_wffin, p_xn, p_buf1, FFN2, KPC);
    // fused ffn dwconv + gelu gate, packed -> packed
    dwgelu_pk_kernel<<<(B * KPH * NPIX / 4) / 256, 256>>>(p_buf1, w_ffn_dw, p_gelu);
    // ffn_out conv1x1 (192 x 512 padded) + residual(g_x2) -> fp32 out
    mma_gemm_bf16<<<dim3(NPIX / 256, C / 64, B), 256>>>(p_wout, p_gelu, out, p_x2, C, KPH);
}

// round 11
// speedup vs baseline: 1.0114x; 1.0114x over previous
#include <cuda_runtime.h>
#include <cuda_bf16.h>
#include <math.h>

#define B 8
#define C 192
#define HEADS 4
#define HD 48
#define HGT 128
#define WID 128
#define NPIX 16384
#define CTXD 256
#define HID 510
#define FFN2 1020
#define NSPLIT 32
#define KPC (C / 2)        // 96 k-pairs for Cin=192
#define KPH 256            // 256 k-pairs for padded gelu (510->512)
#define QKVP (3 * C / 2)   // 288 pairs in qkv
#define FFP  (FFN2 / 2)    // 510 pairs in ffn intermediate

// ---------------- scratch (static device globals; allocation-free) ----------------
__device__ unsigned g_xn_pk [B * KPC * NPIX];   // layernorm output, bf16 k-pair packed
__device__ unsigned g_buf1_pk[B * FFP * NPIX];  // conv1x1 outputs, packed channel pairs
__device__ unsigned g_buf2_pk[B * QKVP * NPIX]; // qkv dwconv output, packed
__device__ unsigned g_mid_pk[B * KPC * NPIX];   // out_local + out_global, packed bf16
__device__ float    g_x2  [B * C    * NPIX];    // x after attention branch (fp32 anchor)
__device__ unsigned g_gelu_pk[B * KPH * NPIX];  // gelu(y1)*y2, bf16 packed, padded
__device__ unsigned g_wqkv_pk [3 * C * KPC];
__device__ unsigned g_wffin_pk[FFN2  * KPC];
__device__ unsigned g_wproj_pk[C * KPC];
__device__ unsigned g_wout_pk [C * KPH];
__device__ float g_attn_part[B * HEADS * NSPLIT * HD * HD];
__device__ float g_attn[B * HEADS * HD * HD];
__device__ float g_temp [B * HEADS];
__device__ float g_vgate[B * C];
__device__ float g_invq [B * C];
__device__ float g_invk [B * C];
__device__ float g_ssq_part[B * 3 * C * 16];

// ---------------- helpers ----------------
__device__ __forceinline__ unsigned pack_bf2(float lo, float hi) {
    __nv_bfloat162 h = __floats2bfloat162_rn(lo, hi);
    return *reinterpret_cast<unsigned*>(&h);
}
__device__ __forceinline__ float2 up2(unsigned u) {
    __nv_bfloat162 h = *reinterpret_cast<__nv_bfloat162*>(&u);
    return make_float2(__bfloat162float(h.x), __bfloat162float(h.y));
}
__device__ __forceinline__ void mma_bf16(float* d, const unsigned* a, const unsigned* b) {
    asm volatile(
        "mma.sync.aligned.m16n8k16.row.col.f32.bf16.bf16.f32 "
        "{%0,%1,%2,%3}, {%4,%5,%6,%7}, {%8,%9}, {%0,%1,%2,%3};\n"
        : "+f"(d[0]), "+f"(d[1]), "+f"(d[2]), "+f"(d[3])
        : "r"(a[0]), "r"(a[1]), "r"(a[2]), "r"(a[3]), "r"(b[0]), "r"(b[1]));
}
__device__ __forceinline__ unsigned smem_u32(const void* p) {
    return (unsigned)__cvta_generic_to_shared(p);
}
__device__ __forceinline__ void cp16(unsigned dst, const void* src) {
    asm volatile("cp.async.cg.shared.global [%0], [%1], 16;" :: "r"(dst), "l"(src));
}
__device__ __forceinline__ void cp16p(unsigned dst, const void* src, bool pred) {
    int sz = pred ? 16 : 0;
    asm volatile("cp.async.cg.shared.global [%0], [%1], 16, %2;" :: "r"(dst), "l"(src), "r"(sz));
}
__device__ __forceinline__ void cp_commit() { asm volatile("cp.async.commit_group;"); }
template <int N>
__device__ __forceinline__ void cp_wait() { asm volatile("cp.async.wait_group %0;" :: "n"(N)); }

// ---------------- context adapters ----------------
__global__ void ctx_kernel(const float* __restrict__ ctx,
                           const float* __restrict__ ta_w1, const float* __restrict__ ta_b1,
                           const float* __restrict__ ta_w2, const float* __restrict__ ta_b2,
                           const float* __restrict__ vg_w,  const float* __restrict__ vg_b,
                           const float* __restrict__ base_temp) {
    __shared__ float sctx[CTXD];
    __shared__ float hid[HD];
    int b = blockIdx.x, t = threadIdx.x;
    sctx[t] = ctx[b * CTXD + t];
    __syncthreads();
    if (t < HD) {
        float s = ta_b1[t];
        for (int k = 0; k < CTXD; k++) s += sctx[k] * ta_w1[t * CTXD + k];
        hid[t] = fmaxf(s, 0.f);
    }
    __syncthreads();
    if (t < HEADS) {
        float s = ta_b2[t];
        for (int k = 0; k < HD; k++) s += hid[k] * ta_w2[t * HD + k];
        float f = 1.f / (1.f + expf(-s)) * 2.f + 0.5f;
        g_temp[b * HEADS + t] = base_temp[t] * f;
    }
    if (t < C) {
        float s = vg_b[t];
        for (int k = 0; k < CTXD; k++) s += sctx[k] * vg_w[t * CTXD + k];
        g_vgate[b * C + t] = 1.f / (1.f + expf(-s));
    }
}

// ---------------- weight packing (fp32 -> bf16 k-pairs) ----------------
__global__ void pack_w_kernel(const float* __restrict__ src, unsigned* __restrict__ dst,
                              int O, int Cin, int Kp) {
    int i = blockIdx.x * 256 + threadIdx.x;
    if (i >= O * Kp) return;
    int o = i / Kp, p = i % Kp;
    float f0 = (2 * p     < Cin) ? src[(size_t)o * Cin + 2 * p]     : 0.f;
    float f1 = (2 * p + 1 < Cin) ? src[(size_t)o * Cin + 2 * p + 1] : 0.f;
    dst[i] = pack_bf2(f0, f1);
}

// ---------------- layernorm over channels -> packed bf16 ----------------
__global__ void ln_kernel(const float* __restrict__ x, const float* __restrict__ w,
                          const float* __restrict__ bias, unsigned* __restrict__ out) {
    int tid = blockIdx.x * 256 + threadIdx.x;   // B*NPIX threads
    int b = tid >> 14, n = tid & (NPIX - 1);
    const float* xp = x + (size_t)b * C * NPIX + n;
    float s = 0.f, ss = 0.f;
    #pragma unroll 8
    for (int c = 0; c < C; c++) { float v = xp[(size_t)c * NPIX]; s += v; ss += v * v; }
    const float ic = 1.f / C;
    float mu = s * ic;
    float rstd = rsqrtf(ss * ic - mu * mu + 1e-5f);
    unsigned* op = out + (size_t)b * KPC * NPIX + n;
    #pragma unroll 4
    for (int p = 0; p < KPC; p++) {
        float v0 = (xp[(size_t)(2 * p)     * NPIX] - mu) * rstd * w[2 * p]     + bias[2 * p];
        float v1 = (xp[(size_t)(2 * p + 1) * NPIX] - mu) * rstd * w[2 * p + 1] + bias[2 * p + 1];
        op[(size_t)p * NPIX] = pack_bf2(v0, v1);
    }
}

// ============ bf16 GEMM core (shared macro body) ============
#define GEMM_BODY(MMAOP)                                                          \
    int b  = blockIdx.z;                                                          \
    int o0 = blockIdx.y * 64;                                                     \
    int n0 = blockIdx.x * 256;                                                    \
    const unsigned* Xb = Xpk + (size_t)b * Kpairs * NPIX + n0;                    \
    int tid  = threadIdx.x;                                                       \
    int warp = tid >> 5, lane = tid & 31;                                         \
    int wm = warp >> 2, wn = warp & 3;                                            \
    int mrow = lane >> 2, kq = lane & 3;                                          \
    float acc[2][8][4];                                                           \
    _Pragma("unroll") for (int mt = 0; mt < 2; mt++)                              \
        _Pragma("unroll") for (int nt = 0; nt < 8; nt++)                          \
            _Pragma("unroll") for (int q = 0; q < 4; q++) acc[mt][nt][q] = 0.f;   \
    int am  = tid >> 2;                                                           \
    int ak4 = (tid & 3) * 4;                                                      \
    bool apred = (o0 + am) < O;                                                   \
    const unsigned* aSrcBase = Apk + (size_t)(o0 + am) * Kpairs + ak4;            \
    int ktiles = Kpairs >> 4;                                                     \
    auto LOAD = [&](int kt, int buf) {                                            \
        int p0 = kt << 4;                                                         \
        cp16p(smem_u32(&sA[buf][am][ak4]), aSrcBase + p0, apred);                 \
        _Pragma("unroll") for (int i = 0; i < 4; i++) {                           \
            int e = tid + i * 256;                                                \
            int kk = e >> 6;                                                      \
            int nn = (e & 63) * 4;                                                \
            cp16(smem_u32(&sB[buf][kk][nn]), Xb + (size_t)(p0 + kk) * NPIX + nn); \
        }                                                                         \
        cp_commit();                                                              \
    };                                                                            \
    LOAD(0, 0);                                                                   \
    for (int kt = 0; kt < ktiles; kt++) {                                         \
        int cur = kt & 1;                                                         \
        if (kt + 1 < ktiles) { LOAD(kt + 1, cur ^ 1); cp_wait<1>(); }             \
        else cp_wait<0>();                                                        \
        __syncthreads();                                                          \
        _Pragma("unroll") for (int ks = 0; ks < 2; ks++) {                        \
            const int p0 = ks * 8;                                                \
            unsigned afr[2][4], bfr[8][2];                                        \
            _Pragma("unroll") for (int mt = 0; mt < 2; mt++) {                    \
                int m = wm * 32 + mt * 16 + mrow;                                 \
                afr[mt][0] = sA[cur][m    ][p0 + kq];                             \
                afr[mt][1] = sA[cur][m + 8][p0 + kq];                             \
                afr[mt][2] = sA[cur][m    ][p0 + kq + 4];                         \
                afr[mt][3] = sA[cur][m + 8][p0 + kq + 4];                         \
            }                                                                     \
            _Pragma("unroll") for (int nt = 0; nt < 8; nt++) {                    \
                int n = wn * 64 + nt * 8 + mrow;                                  \
                bfr[nt][0] = sB[cur][p0 + kq    ][n];                             \
                bfr[nt][1] = sB[cur][p0 + kq + 4][n];                             \
            }                                                                     \
            _Pragma("unroll") for (int mt = 0; mt < 2; mt++)                      \
                _Pragma("unroll") for (int nt = 0; nt < 8; nt++)                  \
                    MMAOP(acc[mt][nt], afr[mt], bfr[nt]);                         \
        }                                                                         \
        __syncthreads();                                                          \
    }

// fp32 output + optional fp32 residual (proj, ffn_out)
__global__ void __launch_bounds__(256) mma_gemm_bf16(const unsigned* __restrict__ Apk,
                                                     const unsigned* __restrict__ Xpk,
                                                     float* __restrict__ Y,
                                                     const float* __restrict__ Res,
                                                     int O, int Kpairs) {
    __shared__ unsigned sA[2][64][20];
    __shared__ unsigned sB[2][16][264];
    GEMM_BODY(mma_bf16)
    size_t base = (size_t)b * O * NPIX;
    #pragma unroll
    for (int mt = 0; mt < 2; mt++) {
        #pragma unroll
        for (int nt = 0; nt < 8; nt++) {
            int ncol = n0 + wn * 64 + nt * 8 + 2 * kq;
            int r0 = o0 + wm * 32 + mt * 16 + mrow;
            if (r0 < O) {
                size_t off = base + (size_t)r0 * NPIX + ncol;
                float2 rr = Res ? *reinterpret_cast<const float2*>(Res + off)
                                : make_float2(0.f, 0.f);
                *reinterpret_cast<float2*>(Y + off) =
                    make_float2(acc[mt][nt][0] + rr.x, acc[mt][nt][1] + rr.y);
            }
            int r1 = r0 + 8;
            if (r1 < O) {
                size_t off = base + (size_t)r1 * NPIX + ncol;
                float2 rr = Res ? *reinterpret_cast<const float2*>(Res + off)
                                : make_float2(0.f, 0.f);
                *reinterpret_cast<float2*>(Y + off) =
                    make_float2(acc[mt][nt][2] + rr.x, acc[mt][nt][3] + rr.y);
            }
        }
    }
}

// packed bf16 channel-pair output (qkv / ffn_in). O must be even.
__global__ void __launch_bounds__(256) mma_gemm_bf16_pk(const unsigned* __restrict__ Apk,
                                                        const unsigned* __restrict__ Xpk,
                                                        unsigned* __restrict__ Ypk,
                                                        int O, int Kpairs) {
    __shared__ unsigned sA[2][64][20];
    __shared__ unsigned sB[2][16][264];
    GEMM_BODY(mma_bf16)
    size_t base = (size_t)b * (O >> 1) * NPIX;
    bool writer = ((mrow & 1) == 0);
    #pragma unroll
    for (int mt = 0; mt < 2; mt++) {
        #pragma unroll
        for (int nt = 0; nt < 8; nt++) {
            int ncol = n0 + wn * 64 + nt * 8 + 2 * kq;
            int r0 = o0 + wm * 32 + mt * 16 + mrow;
            float p0 = __shfl_xor_sync(0xffffffffu, acc[mt][nt][0], 4);
            float p1 = __shfl_xor_sync(0xffffffffu, acc[mt][nt][1], 4);
            float p2 = __shfl_xor_sync(0xffffffffu, acc[mt][nt][2], 4);
            float p3 = __shfl_xor_sync(0xffffffffu, acc[mt][nt][3], 4);
            if (writer && r0 < O) {
                size_t off = base + (size_t)(r0 >> 1) * NPIX + ncol;
                *reinterpret_cast<uint2*>(Ypk + off) =
                    make_uint2(pack_bf2(acc[mt][nt][0], p0), pack_bf2(acc[mt][nt][1], p1));
            }
            if (writer && r0 + 8 < O) {
                size_t off = base + (size_t)((r0 + 8) >> 1) * NPIX + ncol;
                *reinterpret_cast<uint2*>(Ypk + off) =
                    make_uint2(pack_bf2(acc[mt][nt][2], p2), pack_bf2(acc[mt][nt][3], p3));
            }
        }
    }
}

// ---------------- depthwise 3x3 on packed pairs (dual-channel, 4 px / thread) ----------------
__device__ __forceinline__ void dw3x3_pk_v4(const unsigned* __restrict__ ip,
                                            const float* __restrict__ wp0,
                                            const float* __restrict__ wp1,
                                            int y, int x, float* a0, float* a1) {
    a0[0] = a0[1] = a0[2] = a0[3] = 0.f;
    a1[0] = a1[1] = a1[2] = a1[3] = 0.f;
    #pragma unroll
    for (int ky = 0; ky < 3; ky++) {
        int yy = y + ky - 1;
        if (yy < 0 || yy >= HGT) continue;
        const unsigned* row = ip + yy * WID + x;
        uint4 m = *reinterpret_cast<const uint4*>(row);
        unsigned lu = (x > 0)   ? row[-1] : 0u;
        unsigned ru = (x < 124) ? row[4]  : 0u;
        float2 L = up2(lu), X0 = up2(m.x), X1 = up2(m.y), X2 = up2(m.z), X3 = up2(m.w), R = up2(ru);
        float w00 = wp0[ky * 3], w01 = wp0[ky * 3 + 1], w02 = wp0[ky * 3 + 2];
        float w10 = wp1[ky * 3], w11 = wp1[ky * 3 + 1], w12 = wp1[ky * 3 + 2];
        a0[0] += L.x  * w00 + X0.x * w01 + X1.x * w02;
        a0[1] += X0.x * w00 + X1.x * w01 + X2.x * w02;
        a0[2] += X1.x * w00 + X2.x * w01 + X3.x * w02;
        a0[3] += X2.x * w00 + X3.x * w01 + R.x  * w02;
        a1[0] += L.y  * w10 + X0.y * w11 + X1.y * w12;
        a1[1] += X0.y * w10 + X1.y * w11 + X2.y * w12;
        a1[2] += X1.y * w10 + X2.y * w11 + X3.y * w12;
        a1[3] += X2.y * w10 + X3.y * w11 + R.y  * w12;
    }
}

// ---------------- qkv dwconv (packed->packed) + q/k sumsq partials ----------------
__global__ void dwconv_qkv_pk(const unsigned* __restrict__ in, const float* __restrict__ w,
                              unsigned* __restrict__ out) {
    __shared__ float2 red2[256];
    int idx = blockIdx.x * 256 + threadIdx.x;   // B*QKVP*NPIX/4
    int n = (idx & (NPIX / 4 - 1)) * 4;
    int bp = idx >> 12;                          // b*QKVP + pair  (uniform per block)
    int p = bp % QKVP;                           // 0..287
    int y = n >> 7, x = n & 127;
    const unsigned* ip = in + (size_t)bp * NPIX;
    float a0[4], a1[4];
    dw3x3_pk_v4(ip, w + (2 * p) * 9, w + (2 * p + 1) * 9, y, x, a0, a1);
    unsigned o4[4];
    #pragma unroll
    for (int j = 0; j < 4; j++) o4[j] = pack_bf2(a0[j], a1[j]);
    *reinterpret_cast<uint4*>(out + (size_t)bp * NPIX + n) =
        make_uint4(o4[0], o4[1], o4[2], o4[3]);
    if (p < 2 * KPC) {   // q,k pairs (channels < 384)
        int b = bp / QKVP;
        float ss0 = 0.f, ss1 = 0.f;
        #pragma unroll
        for (int j = 0; j < 4; j++) {
            float2 v = up2(o4[j]);
            ss0 += v.x * v.x; ss1 += v.y * v.y;
        }
        red2[threadIdx.x] = make_float2(ss0, ss1);
        __syncthreads();
        for (int s = 128; s > 0; s >>= 1) {
            if (threadIdx.x < s) {
                red2[threadIdx.x].x += red2[threadIdx.x + s].x;
                red2[threadIdx.x].y += red2[threadIdx.x + s].y;
            }
            __syncthreads();
        }
        if (threadIdx.x == 0) {
            int blk = blockIdx.x & 15;
            g_ssq_part[((size_t)b * 3 * C + 2 * p) * 16 + blk]     = red2[0].x;
            g_ssq_part[((size_t)b * 3 * C + 2 * p + 1) * 16 + blk] = red2[0].y;
        }
    }
}

__global__ void inv_kernel() {
    int i = blockIdx.x * 256 + threadIdx.x;
    if (i >= 2 * B * C) return;
    int isK = i >= B * C;
    int lin = isK ? i - B * C : i;
    int b = lin / C, c = lin % C;
    int bc = b * 3 * C + (isK ? C : 0) + c;
    float s = 0.f;
    #pragma unroll
    for (int j = 0; j < 16; j++) s += g_ssq_part[(size_t)bc * 16 + j];
    float inv = 1.f / fmaxf(sqrtf(s), 1e-12f);
    (isK ? g_invk : g_invq)[b * C + c] = inv;
}

// ---------------- fused FFN dwconv + gelu gate (packed -> packed) ----------------
__global__ void dwgelu_pk_kernel(const unsigned* __restrict__ in, const float* __restrict__ w,
                                 unsigned* __restrict__ outg) {
    int idx = blockIdx.x * 256 + threadIdx.x;   // B * KPH * NPIX/4 threads
    int n = (idx & (NPIX / 4 - 1)) * 4;
    int bc = idx >> 12;                          // b*KPH + pair
    int p = bc & (KPH - 1), b = bc >> 8;
    unsigned* op = outg + (size_t)bc * NPIX + n;
    if (p == KPH - 1) {
        *reinterpret_cast<uint4*>(op) = make_uint4(0u, 0u, 0u, 0u);
        return;
    }
    int c = 2 * p;
    int y = n >> 7, x = n & 127;
    const unsigned* base = in + (size_t)b * FFP * NPIX;
    float a1a[4], a1b[4], a2a[4], a2b[4];
    dw3x3_pk_v4(base + (size_t)p * NPIX,         w + c * 9,         w + (c + 1) * 9,       y, x, a1a, a1b);
    dw3x3_pk_v4(base + (size_t)(p + 255) * NPIX, w + (c + HID) * 9, w + (c + 1 + HID) * 9, y, x, a2a, a2b);
    unsigned o4[4];
    #pragma unroll
    for (int j = 0; j < 4; j++) {
        float ga = 0.5f * a1a[j] * (1.f + erff(a1a[j] * 0.70710678118654752f)) * a2a[j];
        float gb = 0.5f * a1b[j] * (1.f + erff(a1b[j] * 0.70710678118654752f)) * a2b[j];
        o4[j] = pack_bf2(ga, gb);
    }
    *reinterpret_cast<uint4*>(op) = make_uint4(o4[0], o4[1], o4[2], o4[3]);
}

// ---------------- attention gram partials (packed q,k) ----------------
__global__ void attn_part_kernel() {
    __shared__ float sQ[HD][33], sK[HD][33];
    int bh = blockIdx.x / NSPLIT, sp = blockIdx.x % NSPLIT;
    int b = bh / HEADS, h = bh % HEADS;
    const unsigned* qpk = g_buf2_pk + ((size_t)b * QKVP + h * (HD / 2)) * NPIX;
    const unsigned* kpk = qpk + (size_t)KPC * NPIX;
    int t = threadIdx.x;
    int i0 = (t >> 4) * 3, j0 = (t & 15) * 3;
    float acc[3][3];
    #pragma unroll
    for (int a = 0; a < 3; a++)
        #pragma unroll
        for (int c2 = 0; c2 < 3; c2++) acc[a][c2] = 0.f;
    int n0 = sp * (NPIX / NSPLIT);
    for (int ch = 0; ch < NPIX / NSPLIT; ch += 32) {
        for (int e = t; e < (HD / 2) * 32; e += 256) {
            int p = e >> 5, nn = e & 31;
            float2 q2 = up2(qpk[(size_t)p * NPIX + n0 + ch + nn]);
            float2 k2 = up2(kpk[(size_t)p * NPIX + n0 + ch + nn]);
            sQ[2 * p][nn] = q2.x; sQ[2 * p + 1][nn] = q2.y;
            sK[2 * p][nn] = k2.x; sK[2 * p + 1][nn] = k2.y;
        }
        __syncthreads();
        #pragma unroll 4
        for (int kk = 0; kk < 32; kk++) {
            float qa[3], ka[3];
            #pragma unroll
            for (int a = 0; a < 3; a++) { qa[a] = sQ[i0 + a][kk]; ka[a] = sK[j0 + a][kk]; }
            #pragma unroll
            for (int a = 0; a < 3; a++)
                #pragma unroll
                for (int c2 = 0; c2 < 3; c2++) acc[a][c2] += qa[a] * ka[c2];
        }
        __syncthreads();
    }
    float* outp = g_attn_part + (size_t)blockIdx.x * HD * HD;
    #pragma unroll
    for (int a = 0; a < 3; a++)
        #pragma unroll
        for (int c2 = 0; c2 < 3; c2++) outp[(i0 + a) * HD + j0 + c2] = acc[a][c2];
}

// ---------------- softmax + fold norms/scale/temp/vgate ----------------
__global__ void softmax_kernel() {
    __shared__ float row[HD];
    __shared__ float mx, sm;
    int rid = blockIdx.x;
    int i  = rid % HD;
    int bh = rid / HD;
    int b = bh / HEADS, h = bh % HEADS;
    int t = threadIdx.x;
    const float scale = 0.14433756729740643f;
    if (t < HD) {
        float s = 0.f;
        const float* pp = g_attn_part + (size_t)bh * NSPLIT * HD * HD + i * HD + t;
        for (int sp = 0; sp < NSPLIT; sp++) s += pp[(size_t)sp * HD * HD];
        row[t] = s * g_invq[b * C + h * HD + i] * g_invk[b * C + h * HD + t]
                   * scale * g_temp[b * HEADS + h];
    }
    __syncthreads();
    if (t == 0) { float m = -1e30f; for (int j = 0; j < HD; j++) m = fmaxf(m, row[j]); mx = m; }
    __syncthreads();
    if (t < HD) row[t] = expf(row[t] - mx);
    __syncthreads();
    if (t == 0) { float s2 = 0.f; for (int j = 0; j < HD; j++) s2 += row[j]; sm = s2; }
    __syncthreads();
    if (t < HD)
        g_attn[(size_t)bh * HD * HD + i * HD + t] = row[t] / sm * g_vgate[b * C + h * HD + t];
}

// ---------------- fused: g_mid_pk = pack( dwconv(v, w_local) + attn @ v ) ----------------
// 384 threads = 24 channel-pairs x 16 pixel-groups x 4 px. 100% lane utilization.
__global__ void __launch_bounds__(384) ogl_kernel(const float* __restrict__ w_local) {
    __shared__ float sA[HD * HD];
    __shared__ float sV[HD][65];
    int bh = blockIdx.y;
    int b = bh / HEADS, h = bh % HEADS;
    int n0 = blockIdx.x * 64;
    const unsigned* vpk = g_buf2_pk + ((size_t)b * QKVP + 2 * KPC + h * (HD / 2)) * NPIX;
    int t = threadIdx.x;
    for (int e = t; e < HD * HD; e += 384) sA[e] = g_attn[(size_t)bh * HD * HD + e];
    for (int e = t; e < (HD / 2) * 64; e += 384) {
        int p = e >> 6, n = e & 63;
        float2 v2 = up2(vpk[(size_t)p * NPIX + n0 + n]);
        sV[2 * p][n] = v2.x; sV[2 * p + 1][n] = v2.y;
    }
    __syncthreads();
    int p = t >> 4;            // channel pair 0..23
    int g = (t & 15) * 4;      // pixel offset 0..60
    int c0 = 2 * p;
    float acc0[4], acc1[4];
    #pragma unroll
    for (int q = 0; q < 4; q++) { acc0[q] = 0.f; acc1[q] = 0.f; }
    #pragma unroll 4
    for (int j = 0; j < HD; j++) {
        float a0 = sA[c0 * HD + j];
        float a1 = sA[(c0 + 1) * HD + j];
        #pragma unroll
        for (int q = 0; q < 4; q++) {
            float v = sV[j][g + q];
            acc0[q] += a0 * v;
            acc1[q] += a1 * v;
        }
    }
    int nb = n0 + g;
    int y = nb >> 7, x = nb & 127;
    const float* wl0 = w_local + (h * HD + c0) * 9;
    float d0[4], d1[4];
    dw3x3_pk_v4(vpk + (size_t)p * NPIX, wl0, wl0 + 9, y, x, d0, d1);
    unsigned o[4];
    #pragma unroll
    for (int q = 0; q < 4; q++)
        o[q] = pack_bf2(acc0[q] + d0[q], acc1[q] + d1[q]);
    unsigned* op = g_mid_pk + ((size_t)b * KPC + h * 24 + p) * NPIX + nb;
    *reinterpret_cast<uint4*>(op) = make_uint4(o[0], o[1], o[2], o[3]);
}

// ---------------- launch ----------------
extern "C" void kernel_launch(void* const* d_in, const int* in_sizes, int n_in,
                              void* d_out, int out_size) {
    const float* x        = (const float*)d_in[0];
    const float* ctx      = (const float*)d_in[1];
    const float* ln1_w    = (const float*)d_in[2];
    const float* ln1_b    = (const float*)d_in[3];
    const float* ln2_w    = (const float*)d_in[4];
    const float* ln2_b    = (const float*)d_in[5];
    const float* w_qkv    = (const float*)d_in[6];
    const float* w_qkv_dw = (const float*)d_in[7];
    const float* w_proj   = (const float*)d_in[8];
    const float* base_temp= (const float*)d_in[9];
    const float* ta_w1    = (const float*)d_in[10];
    const float* ta_b1    = (const float*)d_in[11];
    const float* ta_w2    = (const float*)d_in[12];
    const float* ta_b2    = (const float*)d_in[13];
    const float* vg_w     = (const float*)d_in[14];
    const float* vg_b     = (const float*)d_in[15];
    const float* w_local  = (const float*)d_in[16];
    const float* w_ffn_in = (const float*)d_in[17];
    const float* w_ffn_dw = (const float*)d_in[18];
    const float* w_ffn_out= (const float*)d_in[19];
    float* out = (float*)d_out;

    unsigned *p_xn, *p_buf1, *p_buf2, *p_mid, *p_gelu, *p_wqkv, *p_wffin, *p_wproj, *p_wout;
    float *p_x2;
    cudaGetSymbolAddress((void**)&p_xn,    g_xn_pk);
    cudaGetSymbolAddress((void**)&p_buf1,  g_buf1_pk);
    cudaGetSymbolAddress((void**)&p_buf2,  g_buf2_pk);
    cudaGetSymbolAddress((void**)&p_mid,   g_mid_pk);
    cudaGetSymbolAddress((void**)&p_x2,    g_x2);
    cudaGetSymbolAddress((void**)&p_gelu,  g_gelu_pk);
    cudaGetSymbolAddress((void**)&p_wqkv,  g_wqkv_pk);
    cudaGetSymbolAddress((void**)&p_wffin, g_wffin_pk);
    cudaGetSymbolAddress((void**)&p_wproj, g_wproj_pk);
    cudaGetSymbolAddress((void**)&p_wout,  g_wout_pk);

    ctx_kernel<<<B, 256>>>(ctx, ta_w1, ta_b1, ta_w2, ta_b2, vg_w, vg_b, base_temp);
    pack_w_kernel<<<(3 * C * KPC + 255) / 256, 256>>>(w_qkv, p_wqkv, 3 * C, C, KPC);
    pack_w_kernel<<<(FFN2 * KPC + 255) / 256, 256>>>(w_ffn_in, p_wffin, FFN2, C, KPC);
    pack_w_kernel<<<(C * KPC + 255) / 256, 256>>>(w_proj, p_wproj, C, C, KPC);
    pack_w_kernel<<<(C * KPH + 255) / 256, 256>>>(w_ffn_out, p_wout, C, HID, KPH);

    // LN1 -> packed bf16
    ln_kernel<<<(B * NPIX) / 256, 256>>>(x, ln1_w, ln1_b, p_xn);
    // qkv conv1x1 (576 x 192), bf16 -> packed pairs
    mma_gemm_bf16_pk<<<dim3(NPIX / 256, (3 * C) / 64, B), 256>>>(p_wqkv, p_xn, p_buf1, 3 * C, KPC);
    // qkv dwconv packed->packed + q/k sumsq partials
    dwconv_qkv_pk<<<(B * QKVP * NPIX / 4) / 256, 256>>>(p_buf1, w_qkv_dw, p_buf2);
    inv_kernel<<<(2 * B * C + 255) / 256, 256>>>();
    attn_part_kernel<<<B * HEADS * NSPLIT, 256>>>();
    softmax_kernel<<<B * HEADS * HD, 64>>>();
    // fused out_local + out_global -> g_mid packed bf16 (384-thread full-utilization)
    ogl_kernel<<<dim3(NPIX / 64, B * HEADS), 384>>>(w_local);
    // proj conv1x1 (bf16) + residual(x) -> g_x2 fp32
    mma_gemm_bf16<<<dim3(NPIX / 256, C / 64, B), 256>>>(p_wproj, p_mid, p_x2, x, C, KPC);
    // LN2 -> packed bf16
    ln_kernel<<<(B * NPIX) / 256, 256>>>(p_x2, ln2_w, ln2_b, p_xn);
    // ffn_in conv1x1 (1020 x 192), bf16 -> packed pairs
    mma_gemm_bf16_pk<<<dim3(NPIX / 256, (FFN2 + 63) / 64, B), 256>>>(p_wffin, p_xn, p_buf1, FFN2, KPC);
    // fused ffn dwconv + gelu gate, packed -> packed
    dwgelu_pk_kernel<<<(B * KPH * NPIX / 4) / 256, 256>>>(p_buf1, w_ffn_dw, p_gelu);
    // ffn_out conv1x1 (192 x 512 padded) + residual(g_x2) -> fp32 out
    mma_gemm_bf16<<<dim3(NPIX / 256, C / 64, B), 256>>>(p_wout, p_gelu, out, p_x2, C, KPH);
}

// round 12
// speedup vs baseline: 1.0802x; 1.0680x over previous
#include <cuda_runtime.h>
#include <cuda_bf16.h>
#include <math.h>

#define B 8
#define C 192
#define HEADS 4
#define HD 48
#define HGT 128
#define WID 128
#define NPIX 16384
#define CTXD 256
#define HID 510
#define FFN2 1020
#define NSPLIT 32
#define KPC (C / 2)        // 96 k-pairs for Cin=192
#define KPH 256            // 256 k-pairs for padded gelu (510->512)
#define QKVP (3 * C / 2)   // 288 pairs in qkv
#define FFP  (FFN2 / 2)    // 510 pairs in ffn intermediate
#define LNPX 64            // pixels per LN block

// ---------------- scratch (static device globals; allocation-free) ----------------
__device__ unsigned g_xn_pk [B * KPC * NPIX];   // layernorm output, bf16 k-pair packed
__device__ unsigned g_buf1_pk[B * FFP * NPIX];  // conv1x1 outputs, packed channel pairs
__device__ unsigned g_buf2_pk[B * QKVP * NPIX]; // qkv dwconv output, packed
__device__ float    g_mid [B * C    * NPIX];    // out_local + out_global (fp32)
__device__ float    g_x2  [B * C    * NPIX];    // x after attention branch (fp32 anchor)
__device__ unsigned g_gelu_pk[B * KPH * NPIX];  // gelu(y1)*y2, bf16 packed, padded
__device__ unsigned g_wqkv_pk [3 * C * KPC];
__device__ unsigned g_wffin_pk[FFN2  * KPC];
__device__ unsigned g_wout_pk [C * KPH];
__device__ float g_attn_part[B * HEADS * NSPLIT * HD * HD];
__device__ float g_attn[B * HEADS * HD * HD];
__device__ float g_temp [B * HEADS];
__device__ float g_vgate[B * C];
__device__ float g_ssq_part[B * 3 * C * 16];

// ---------------- helpers ----------------
__device__ __forceinline__ unsigned pack_bf2(float lo, float hi) {
    __nv_bfloat162 h = __floats2bfloat162_rn(lo, hi);
    return *reinterpret_cast<unsigned*>(&h);
}
__device__ __forceinline__ float2 up2(unsigned u) {
    __nv_bfloat162 h = *reinterpret_cast<__nv_bfloat162*>(&u);
    return make_float2(__bfloat162float(h.x), __bfloat162float(h.y));
}
__device__ __forceinline__ void mma_bf16(float* d, const unsigned* a, const unsigned* b) {
    asm volatile(
        "mma.sync.aligned.m16n8k16.row.col.f32.bf16.bf16.f32 "
        "{%0,%1,%2,%3}, {%4,%5,%6,%7}, {%8,%9}, {%0,%1,%2,%3};\n"
        : "+f"(d[0]), "+f"(d[1]), "+f"(d[2]), "+f"(d[3])
        : "r"(a[0]), "r"(a[1]), "r"(a[2]), "r"(a[3]), "r"(b[0]), "r"(b[1]));
}
__device__ __forceinline__ void mma_tf32(float* d, const unsigned* a, const unsigned* b) {
    asm volatile(
        "mma.sync.aligned.m16n8k8.row.col.f32.tf32.tf32.f32 "
        "{%0,%1,%2,%3}, {%4,%5,%6,%7}, {%8,%9}, {%0,%1,%2,%3};\n"
        : "+f"(d[0]), "+f"(d[1]), "+f"(d[2]), "+f"(d[3])
        : "r"(a[0]), "r"(a[1]), "r"(a[2]), "r"(a[3]), "r"(b[0]), "r"(b[1]));
}
__device__ __forceinline__ unsigned smem_u32(const void* p) {
    return (unsigned)__cvta_generic_to_shared(p);
}
__device__ __forceinline__ void cp16(unsigned dst, const void* src) {
    asm volatile("cp.async.cg.shared.global [%0], [%1], 16;" :: "r"(dst), "l"(src));
}
__device__ __forceinline__ void cp16p(unsigned dst, const void* src, bool pred) {
    int sz = pred ? 16 : 0;
    asm volatile("cp.async.cg.shared.global [%0], [%1], 16, %2;" :: "r"(dst), "l"(src), "r"(sz));
}
__device__ __forceinline__ void cp_commit() { asm volatile("cp.async.commit_group;"); }
template <int N>
__device__ __forceinline__ void cp_wait() { asm volatile("cp.async.wait_group %0;" :: "n"(N)); }

// ---------------- context adapters ----------------
__global__ void ctx_kernel(const float* __restrict__ ctx,
                           const float* __restrict__ ta_w1, const float* __restrict__ ta_b1,
                           const float* __restrict__ ta_w2, const float* __restrict__ ta_b2,
                           const float* __restrict__ vg_w,  const float* __restrict__ vg_b,
                           const float* __restrict__ base_temp) {
    __shared__ float sctx[CTXD];
    __shared__ float hid[HD];
    int b = blockIdx.x, t = threadIdx.x;
    sctx[t] = ctx[b * CTXD + t];
    __syncthreads();
    if (t < HD) {
        float s = ta_b1[t];
        for (int k = 0; k < CTXD; k++) s += sctx[k] * ta_w1[t * CTXD + k];
        hid[t] = fmaxf(s, 0.f);
    }
    __syncthreads();
    if (t < HEADS) {
        float s = ta_b2[t];
        for (int k = 0; k < HD; k++) s += hid[k] * ta_w2[t * HD + k];
        float f = 1.f / (1.f + expf(-s)) * 2.f + 0.5f;
        g_temp[b * HEADS + t] = base_temp[t] * f;
    }
    if (t < C) {
        float s = vg_b[t];
        for (int k = 0; k < CTXD; k++) s += sctx[k] * vg_w[t * CTXD + k];
        g_vgate[b * C + t] = 1.f / (1.f + expf(-s));
    }
}

// ---------------- pack ALL weights in one launch ----------------
#define NW1 (3 * C * KPC)          // 55296
#define NW2 (FFN2 * KPC)           // 97920
#define NW3 (C * KPH)              // 49152
__global__ void pack_all_kernel(const float* __restrict__ wqkv,
                                const float* __restrict__ wffin,
                                const float* __restrict__ wout) {
    int i = blockIdx.x * 256 + threadIdx.x;
    if (i < NW1) {
        int o = i / KPC, p = i % KPC;
        g_wqkv_pk[i] = pack_bf2(wqkv[(size_t)o * C + 2 * p], wqkv[(size_t)o * C + 2 * p + 1]);
    } else if (i < NW1 + NW2) {
        int e = i - NW1;
        int o = e / KPC, p = e % KPC;
        g_wffin_pk[e] = pack_bf2(wffin[(size_t)o * C + 2 * p], wffin[(size_t)o * C + 2 * p + 1]);
    } else if (i < NW1 + NW2 + NW3) {
        int e = i - NW1 - NW2;
        int o = e / KPH, p = e % KPH;
        float f0 = (2 * p     < HID) ? wout[(size_t)o * HID + 2 * p]     : 0.f;
        float f1 = (2 * p + 1 < HID) ? wout[(size_t)o * HID + 2 * p + 1] : 0.f;
        g_wout_pk[e] = pack_bf2(f0, f1);
    }
}

// ---------------- layernorm: smem-staged, 64 px / block -> packed bf16 ----------------
__global__ void __launch_bounds__(256) ln_kernel(const float* __restrict__ x,
                                                 const float* __restrict__ w,
                                                 const float* __restrict__ bias,
                                                 unsigned* __restrict__ out) {
    __shared__ unsigned sXp[KPC][LNPX + 1];   // bf16 pairs, padded
    __shared__ float sRed[2][4][LNPX];
    __shared__ float sMu[LNPX], sRs[LNPX];
    int blk = blockIdx.x;                     // B*NPIX/LNPX = 2048 blocks
    int b = blk / (NPIX / LNPX);
    int n0 = (blk % (NPIX / LNPX)) * LNPX;
    int t = threadIdx.x;
    const float* xb = x + (size_t)b * C * NPIX + n0;
    // stage all channels (as bf16 pairs) for 64 pixels
    for (int e = t; e < KPC * LNPX; e += 256) {
        int p = e >> 6, j = e & 63;
        float v0 = xb[(size_t)(2 * p)     * NPIX + j];
        float v1 = xb[(size_t)(2 * p + 1) * NPIX + j];
        sXp[p][j] = pack_bf2(v0, v1);
    }
    __syncthreads();
    // stats: 4 threads per pixel, each over 24 pairs (48 channels)
    {
        int j = t >> 2, part = t & 3;
        float s = 0.f, ss = 0.f;
        #pragma unroll 4
        for (int p = part * 24; p < part * 24 + 24; p++) {
            float2 v = up2(sXp[p][j]);
            s += v.x + v.y;
            ss += v.x * v.x + v.y * v.y;
        }
        sRed[0][part][j] = s;
        sRed[1][part][j] = ss;
    }
    __syncthreads();
    if ((t & 3) == 0) {
        int j = t >> 2;
        float st  = sRed[0][0][j] + sRed[0][1][j] + sRed[0][2][j] + sRed[0][3][j];
        float sst = sRed[1][0][j] + sRed[1][1][j] + sRed[1][2][j] + sRed[1][3][j];
        const float ic = 1.f / C;
        float mu = st * ic;
        sMu[j] = mu;
        sRs[j] = rsqrtf(sst * ic - mu * mu + 1e-5f);
    }
    __syncthreads();
    unsigned* ob = out + (size_t)b * KPC * NPIX + n0;
    for (int e = t; e < KPC * LNPX; e += 256) {
        int p = e >> 6, j = e & 63;
        float2 v = up2(sXp[p][j]);
        float mu = sMu[j], rs = sRs[j];
        float v0 = (v.x - mu) * rs * w[2 * p]     + bias[2 * p];
        float v1 = (v.y - mu) * rs * w[2 * p + 1] + bias[2 * p + 1];
        ob[(size_t)p * NPIX + j] = pack_bf2(v0, v1);
    }
}

// ============ bf16 GEMM core (shared macro body) ============
#define GEMM_BODY(MMAOP)                                                          \
    int b  = blockIdx.z;                                                          \
    int o0 = blockIdx.y * 64;                                                     \
    int n0 = blockIdx.x * 256;                                                    \
    const unsigned* Xb = Xpk + (size_t)b * Kpairs * NPIX + n0;                    \
    int tid  = threadIdx.x;                                                       \
    int warp = tid >> 5, lane = tid & 31;                                         \
    int wm = warp >> 2, wn = warp & 3;                                            \
    int mrow = lane >> 2, kq = lane & 3;                                          \
    float acc[2][8][4];                                                           \
    _Pragma("unroll") for (int mt = 0; mt < 2; mt++)                              \
        _Pragma("unroll") for (int nt = 0; nt < 8; nt++)                          \
            _Pragma("unroll") for (int q = 0; q < 4; q++) acc[mt][nt][q] = 0.f;   \
    int am  = tid >> 2;                                                           \
    int ak4 = (tid & 3) * 4;                                                      \
    bool apred = (o0 + am) < O;                                                   \
    const unsigned* aSrcBase = Apk + (size_t)(o0 + am) * Kpairs + ak4;            \
    int ktiles = Kpairs >> 4;                                                     \
    auto LOAD = [&](int kt, int buf) {                                            \
        int p0 = kt << 4;                                                         \
        cp16p(smem_u32(&sA[buf][am][ak4]), aSrcBase + p0, apred);                 \
        _Pragma("unroll") for (int i = 0; i < 4; i++) {                           \
            int e = tid + i * 256;                                                \
            int kk = e >> 6;                                                      \
            int nn = (e & 63) * 4;                                                \
            cp16(smem_u32(&sB[buf][kk][nn]), Xb + (size_t)(p0 + kk) * NPIX + nn); \
        }                                                                         \
        cp_commit();                                                              \
    };                                                                            \
    LOAD(0, 0);                                                                   \
    for (int kt = 0; kt < ktiles; kt++) {                                         \
        int cur = kt & 1;                                                         \
        if (kt + 1 < ktiles) { LOAD(kt + 1, cur ^ 1); cp_wait<1>(); }             \
        else cp_wait<0>();                                                        \
        __syncthreads();                                                          \
        _Pragma("unroll") for (int ks = 0; ks < 2; ks++) {                        \
            const int p0 = ks * 8;                                                \
            unsigned afr[2][4], bfr[8][2];                                        \
            _Pragma("unroll") for (int mt = 0; mt < 2; mt++) {                    \
                int m = wm * 32 + mt * 16 + mrow;                                 \
                afr[mt][0] = sA[cur][m    ][p0 + kq];                             \
                afr[mt][1] = sA[cur][m + 8][p0 + kq];                             \
                afr[mt][2] = sA[cur][m    ][p0 + kq + 4];                         \
                afr[mt][3] = sA[cur][m + 8][p0 + kq + 4];                         \
            }                                                                     \
            _Pragma("unroll") for (int nt = 0; nt < 8; nt++) {                    \
                int n = wn * 64 + nt * 8 + mrow;                                  \
                bfr[nt][0] = sB[cur][p0 + kq    ][n];                             \
                bfr[nt][1] = sB[cur][p0 + kq + 4][n];                             \
            }                                                                     \
            _Pragma("unroll") for (int mt = 0; mt < 2; mt++)                      \
                _Pragma("unroll") for (int nt = 0; nt < 8; nt++)                  \
                    MMAOP(acc[mt][nt], afr[mt], bfr[nt]);                         \
        }                                                                         \
        __syncthreads();                                                          \
    }

// fp32 output + optional fp32 residual (ffn_out)
__global__ void __launch_bounds__(256) mma_gemm_bf16(const unsigned* __restrict__ Apk,
                                                     const unsigned* __restrict__ Xpk,
                                                     float* __restrict__ Y,
                                                     const float* __restrict__ Res,
                                                     int O, int Kpairs) {
    __shared__ unsigned sA[2][64][20];
    __shared__ unsigned sB[2][16][264];
    GEMM_BODY(mma_bf16)
    size_t base = (size_t)b * O * NPIX;
    #pragma unroll
    for (int mt = 0; mt < 2; mt++) {
        #pragma unroll
        for (int nt = 0; nt < 8; nt++) {
            int ncol = n0 + wn * 64 + nt * 8 + 2 * kq;
            int r0 = o0 + wm * 32 + mt * 16 + mrow;
            if (r0 < O) {
                size_t off = base + (size_t)r0 * NPIX + ncol;
                float2 rr = Res ? *reinterpret_cast<const float2*>(Res + off)
                                : make_float2(0.f, 0.f);
                *reinterpret_cast<float2*>(Y + off) =
                    make_float2(acc[mt][nt][0] + rr.x, acc[mt][nt][1] + rr.y);
            }
            int r1 = r0 + 8;
            if (r1 < O) {
                size_t off = base + (size_t)r1 * NPIX + ncol;
                float2 rr = Res ? *reinterpret_cast<const float2*>(Res + off)
                                : make_float2(0.f, 0.f);
                *reinterpret_cast<float2*>(Y + off) =
                    make_float2(acc[mt][nt][2] + rr.x, acc[mt][nt][3] + rr.y);
            }
        }
    }
}

// packed bf16 channel-pair output (qkv / ffn_in). O must be even.
__global__ void __launch_bounds__(256) mma_gemm_bf16_pk(const unsigned* __restrict__ Apk,
                                                        const unsigned* __restrict__ Xpk,
                                                        unsigned* __restrict__ Ypk,
                                                        int O, int Kpairs) {
    __shared__ unsigned sA[2][64][20];
    __shared__ unsigned sB[2][16][264];
    GEMM_BODY(mma_bf16)
    size_t base = (size_t)b * (O >> 1) * NPIX;
    bool writer = ((mrow & 1) == 0);
    #pragma unroll
    for (int mt = 0; mt < 2; mt++) {
        #pragma unroll
        for (int nt = 0; nt < 8; nt++) {
            int ncol = n0 + wn * 64 + nt * 8 + 2 * kq;
            int r0 = o0 + wm * 32 + mt * 16 + mrow;
            float p0 = __shfl_xor_sync(0xffffffffu, acc[mt][nt][0], 4);
            float p1 = __shfl_xor_sync(0xffffffffu, acc[mt][nt][1], 4);
            float p2 = __shfl_xor_sync(0xffffffffu, acc[mt][nt][2], 4);
            float p3 = __shfl_xor_sync(0xffffffffu, acc[mt][nt][3], 4);
            if (writer && r0 < O) {
                size_t off = base + (size_t)(r0 >> 1) * NPIX + ncol;
                *reinterpret_cast<uint2*>(Ypk + off) =
                    make_uint2(pack_bf2(acc[mt][nt][0], p0), pack_bf2(acc[mt][nt][1], p1));
            }
            if (writer && r0 + 8 < O) {
                size_t off = base + (size_t)((r0 + 8) >> 1) * NPIX + ncol;
                *reinterpret_cast<uint2*>(Ypk + off) =
                    make_uint2(pack_bf2(acc[mt][nt][2], p2), pack_bf2(acc[mt][nt][3], p3));
            }
        }
    }
}

// ---------------- tf32 GEMM (fp32 inputs) — proj only ----------------
__global__ void __launch_bounds__(256) mma_gemm(const float* __restrict__ Wm,
                                                const float* __restrict__ X,
                                                float* __restrict__ Y,
                                                const float* __restrict__ Res,
                                                int O, int Cin) {
    __shared__ float sA[2][64][20];
    __shared__ float sB[2][16][264];

    int b  = blockIdx.z;
    int o0 = blockIdx.y * 64;
    int n0 = blockIdx.x * 256;
    const float* Xb = X + (size_t)b * Cin * NPIX + n0;

    int tid  = threadIdx.x;
    int warp = tid >> 5, lane = tid & 31;
    int wm = warp >> 2, wn = warp & 3;
    int mrow = lane >> 2, kq = lane & 3;

    float acc[2][8][4];
    #pragma unroll
    for (int mt = 0; mt < 2; mt++)
        #pragma unroll
        for (int nt = 0; nt < 8; nt++)
            #pragma unroll
            for (int q = 0; q < 4; q++) acc[mt][nt][q] = 0.f;

    int am  = tid >> 2;
    int ak4 = (tid & 3) * 4;
    bool apred = (o0 + am) < O;
    const float* aSrcBase = Wm + (size_t)(o0 + am) * Cin + ak4;

    int ktiles = Cin >> 4;

    auto LOAD = [&](int kt, int buf) {
        int c0 = kt << 4;
        cp16p(smem_u32(&sA[buf][am][ak4]), aSrcBase + c0, apred);
        #pragma unroll
        for (int i = 0; i < 4; i++) {
            int e = tid + i * 256;
            int kk = e >> 6;
            int nn = (e & 63) * 4;
            cp16(smem_u32(&sB[buf][kk][nn]), Xb + (size_t)(c0 + kk) * NPIX + nn);
        }
        cp_commit();
    };

    LOAD(0, 0);
    for (int kt = 0; kt < ktiles; kt++) {
        int cur = kt & 1;
        if (kt + 1 < ktiles) { LOAD(kt + 1, cur ^ 1); cp_wait<1>(); }
        else cp_wait<0>();
        __syncthreads();

        const unsigned (*A)[20]   = reinterpret_cast<const unsigned (*)[20]>(sA[cur]);
        const unsigned (*Bs)[264] = reinterpret_cast<const unsigned (*)[264]>(sB[cur]);
        #pragma unroll
        for (int ks = 0; ks < 2; ks++) {
            const int k0 = ks * 8;
            unsigned afr[2][4], bfr[8][2];
            #pragma unroll
            for (int mt = 0; mt < 2; mt++) {
                int m = wm * 32 + mt * 16 + mrow;
                afr[mt][0] = A[m    ][k0 + kq];
                afr[mt][1] = A[m + 8][k0 + kq];
                afr[mt][2] = A[m    ][k0 + kq + 4];
                afr[mt][3] = A[m + 8][k0 + kq + 4];
            }
            #pragma unroll
            for (int nt = 0; nt < 8; nt++) {
                int n = wn * 64 + nt * 8 + mrow;
                bfr[nt][0] = Bs[k0 + kq    ][n];
                bfr[nt][1] = Bs[k0 + kq + 4][n];
            }
            #pragma unroll
            for (int mt = 0; mt < 2; mt++)
                #pragma unroll
                for (int nt = 0; nt < 8; nt++)
                    mma_tf32(acc[mt][nt], afr[mt], bfr[nt]);
        }
        __syncthreads();
    }

    size_t base = (size_t)b * O * NPIX;
    #pragma unroll
    for (int mt = 0; mt < 2; mt++) {
        #pragma unroll
        for (int nt = 0; nt < 8; nt++) {
            int ncol = n0 + wn * 64 + nt * 8 + 2 * kq;
            int r0 = o0 + wm * 32 + mt * 16 + mrow;
            if (r0 < O) {
                size_t off = base + (size_t)r0 * NPIX + ncol;
                float2 rr = Res ? *reinterpret_cast<const float2*>(Res + off)
                                : make_float2(0.f, 0.f);
                *reinterpret_cast<float2*>(Y + off) =
                    make_float2(acc[mt][nt][0] + rr.x, acc[mt][nt][1] + rr.y);
            }
            int r1 = r0 + 8;
            if (r1 < O) {
                size_t off = base + (size_t)r1 * NPIX + ncol;
                float2 rr = Res ? *reinterpret_cast<const float2*>(Res + off)
                                : make_float2(0.f, 0.f);
                *reinterpret_cast<float2*>(Y + off) =
                    make_float2(acc[mt][nt][2] + rr.x, acc[mt][nt][3] + rr.y);
            }
        }
    }
}

// ---------------- depthwise 3x3 on packed pairs (dual-channel, 4 px / thread) ----------------
__device__ __forceinline__ void dw3x3_pk_v4(const unsigned* __restrict__ ip,
                                            const float* __restrict__ wp0,
                                            const float* __restrict__ wp1,
                                            int y, int x, float* a0, float* a1) {
    a0[0] = a0[1] = a0[2] = a0[3] = 0.f;
    a1[0] = a1[1] = a1[2] = a1[3] = 0.f;
    #pragma unroll
    for (int ky = 0; ky < 3; ky++) {
        int yy = y + ky - 1;
        if (yy < 0 || yy >= HGT) continue;
        const unsigned* row = ip + yy * WID + x;
        uint4 m = *reinterpret_cast<const uint4*>(row);
        unsigned lu = (x > 0)   ? row[-1] : 0u;
        unsigned ru = (x < 124) ? row[4]  : 0u;
        float2 L = up2(lu), X0 = up2(m.x), X1 = up2(m.y), X2 = up2(m.z), X3 = up2(m.w), R = up2(ru);
        float w00 = wp0[ky * 3], w01 = wp0[ky * 3 + 1], w02 = wp0[ky * 3 + 2];
        float w10 = wp1[ky * 3], w11 = wp1[ky * 3 + 1], w12 = wp1[ky * 3 + 2];
        a0[0] += L.x  * w00 + X0.x * w01 + X1.x * w02;
        a0[1] += X0.x * w00 + X1.x * w01 + X2.x * w02;
        a0[2] += X1.x * w00 + X2.x * w01 + X3.x * w02;
        a0[3] += X2.x * w00 + X3.x * w01 + R.x  * w02;
        a1[0] += L.y  * w10 + X0.y * w11 + X1.y * w12;
        a1[1] += X0.y * w10 + X1.y * w11 + X2.y * w12;
        a1[2] += X1.y * w10 + X2.y * w11 + X3.y * w12;
        a1[3] += X2.y * w10 + X3.y * w11 + R.y  * w12;
    }
}

// single-channel from packed plane (for ogl local conv)
__device__ __forceinline__ void dw3x3_pk1_v4(const unsigned* __restrict__ ip, int hi,
                                             const float* __restrict__ wp,
                                             int y, int x, float* acc) {
    acc[0] = acc[1] = acc[2] = acc[3] = 0.f;
    #pragma unroll
    for (int ky = 0; ky < 3; ky++) {
        int yy = y + ky - 1;
        if (yy < 0 || yy >= HGT) continue;
        const unsigned* row = ip + yy * WID + x;
        uint4 m = *reinterpret_cast<const uint4*>(row);
        unsigned lu = (x > 0)   ? row[-1] : 0u;
        unsigned ru = (x < 124) ? row[4]  : 0u;
        float L, X0, X1, X2, X3, R;
        if (hi) {
            L = up2(lu).y; X0 = up2(m.x).y; X1 = up2(m.y).y; X2 = up2(m.z).y; X3 = up2(m.w).y; R = up2(ru).y;
        } else {
            L = up2(lu).x; X0 = up2(m.x).x; X1 = up2(m.y).x; X2 = up2(m.z).x; X3 = up2(m.w).x; R = up2(ru).x;
        }
        float w0 = wp[ky * 3], w1 = wp[ky * 3 + 1], w2 = wp[ky * 3 + 2];
        acc[0] += L  * w0 + X0 * w1 + X1 * w2;
        acc[1] += X0 * w0 + X1 * w1 + X2 * w2;
        acc[2] += X1 * w0 + X2 * w1 + X3 * w2;
        acc[3] += X2 * w0 + X3 * w1 + R  * w2;
    }
}

// ---------------- qkv dwconv (packed->packed) + q/k sumsq partials ----------------
__global__ void dwconv_qkv_pk(const unsigned* __restrict__ in, const float* __restrict__ w,
                              unsigned* __restrict__ out) {
    __shared__ float2 red2[256];
    int idx = blockIdx.x * 256 + threadIdx.x;   // B*QKVP*NPIX/4
    int n = (idx & (NPIX / 4 - 1)) * 4;
    int bp = idx >> 12;                          // b*QKVP + pair  (uniform per block)
    int p = bp % QKVP;                           // 0..287
    int y = n >> 7, x = n & 127;
    const unsigned* ip = in + (size_t)bp * NPIX;
    float a0[4], a1[4];
    dw3x3_pk_v4(ip, w + (2 * p) * 9, w + (2 * p + 1) * 9, y, x, a0, a1);
    unsigned o4[4];
    #pragma unroll
    for (int j = 0; j < 4; j++) o4[j] = pack_bf2(a0[j], a1[j]);
    *reinterpret_cast<uint4*>(out + (size_t)bp * NPIX + n) =
        make_uint4(o4[0], o4[1], o4[2], o4[3]);
    if (p < 2 * KPC) {   // q,k pairs (channels < 384)
        int b = bp / QKVP;
        float ss0 = 0.f, ss1 = 0.f;
        #pragma unroll
        for (int j = 0; j < 4; j++) {
            float2 v = up2(o4[j]);
            ss0 += v.x * v.x; ss1 += v.y * v.y;
        }
        red2[threadIdx.x] = make_float2(ss0, ss1);
        __syncthreads();
        for (int s = 128; s > 0; s >>= 1) {
            if (threadIdx.x < s) {
                red2[threadIdx.x].x += red2[threadIdx.x + s].x;
                red2[threadIdx.x].y += red2[threadIdx.x + s].y;
            }
            __syncthreads();
        }
        if (threadIdx.x == 0) {
            int blk = blockIdx.x & 15;
            g_ssq_part[((size_t)b * 3 * C + 2 * p) * 16 + blk]     = red2[0].x;
            g_ssq_part[((size_t)b * 3 * C + 2 * p + 1) * 16 + blk] = red2[0].y;
        }
    }
}

// ---------------- fused FFN dwconv + gelu gate (packed -> packed) ----------------
__global__ void dwgelu_pk_kernel(const unsigned* __restrict__ in, const float* __restrict__ w,
                                 unsigned* __restrict__ outg) {
    int idx = blockIdx.x * 256 + threadIdx.x;   // B * KPH * NPIX/4 threads
    int n = (idx & (NPIX / 4 - 1)) * 4;
    int bc = idx >> 12;                          // b*KPH + pair
    int p = bc & (KPH - 1), b = bc >> 8;
    unsigned* op = outg + (size_t)bc * NPIX + n;
    if (p == KPH - 1) {
        *reinterpret_cast<uint4*>(op) = make_uint4(0u, 0u, 0u, 0u);
        return;
    }
    int c = 2 * p;
    int y = n >> 7, x = n & 127;
    const unsigned* base = in + (size_t)b * FFP * NPIX;
    float a1a[4], a1b[4], a2a[4], a2b[4];
    dw3x3_pk_v4(base + (size_t)p * NPIX,         w + c * 9,         w + (c + 1) * 9,       y, x, a1a, a1b);
    dw3x3_pk_v4(base + (size_t)(p + 255) * NPIX, w + (c + HID) * 9, w + (c + 1 + HID) * 9, y, x, a2a, a2b);
    unsigned o4[4];
    #pragma unroll
    for (int j = 0; j < 4; j++) {
        float ga = 0.5f * a1a[j] * (1.f + erff(a1a[j] * 0.70710678118654752f)) * a2a[j];
        float gb = 0.5f * a1b[j] * (1.f + erff(a1b[j] * 0.70710678118654752f)) * a2b[j];
        o4[j] = pack_bf2(ga, gb);
    }
    *reinterpret_cast<uint4*>(op) = make_uint4(o4[0], o4[1], o4[2], o4[3]);
}

// ---------------- attention gram partials (packed q,k) ----------------
__global__ void attn_part_kernel() {
    __shared__ float sQ[HD][33], sK[HD][33];
    int bh = blockIdx.x / NSPLIT, sp = blockIdx.x % NSPLIT;
    int b = bh / HEADS, h = bh % HEADS;
    const unsigned* qpk = g_buf2_pk + ((size_t)b * QKVP + h * (HD / 2)) * NPIX;
    const unsigned* kpk = qpk + (size_t)KPC * NPIX;
    int t = threadIdx.x;
    int i0 = (t >> 4) * 3, j0 = (t & 15) * 3;
    float acc[3][3];
    #pragma unroll
    for (int a = 0; a < 3; a++)
        #pragma unroll
        for (int c2 = 0; c2 < 3; c2++) acc[a][c2] = 0.f;
    int n0 = sp * (NPIX / NSPLIT);
    for (int ch = 0; ch < NPIX / NSPLIT; ch += 32) {
        for (int e = t; e < (HD / 2) * 32; e += 256) {
            int p = e >> 5, nn = e & 31;
            float2 q2 = up2(qpk[(size_t)p * NPIX + n0 + ch + nn]);
            float2 k2 = up2(kpk[(size_t)p * NPIX + n0 + ch + nn]);
            sQ[2 * p][nn] = q2.x; sQ[2 * p + 1][nn] = q2.y;
            sK[2 * p][nn] = k2.x; sK[2 * p + 1][nn] = k2.y;
        }
        __syncthreads();
        #pragma unroll 4
        for (int kk = 0; kk < 32; kk++) {
            float qa[3], ka[3];
            #pragma unroll
            for (int a = 0; a < 3; a++) { qa[a] = sQ[i0 + a][kk]; ka[a] = sK[j0 + a][kk]; }
            #pragma unroll
            for (int a = 0; a < 3; a++)
                #pragma unroll
                for (int c2 = 0; c2 < 3; c2++) acc[a][c2] += qa[a] * ka[c2];
        }
        __syncthreads();
    }
    float* outp = g_attn_part + (size_t)blockIdx.x * HD * HD;
    #pragma unroll
    for (int a = 0; a < 3; a++)
        #pragma unroll
        for (int c2 = 0; c2 < 3; c2++) outp[(i0 + a) * HD + j0 + c2] = acc[a][c2];
}

// ---------------- softmax + inline inverse norms + fold scale/temp/vgate ----------------
__global__ void softmax_kernel() {
    __shared__ float row[HD];
    __shared__ float kinv[HD];
    __shared__ float mx, sm, qinv;
    int rid = blockIdx.x;
    int i  = rid % HD;
    int bh = rid / HD;
    int b = bh / HEADS, h = bh % HEADS;
    int t = threadIdx.x;
    const float scale = 0.14433756729740643f;
    // inverse k-norm for channel h*HD + t
    if (t < HD) {
        const float* pk = g_ssq_part + ((size_t)b * 3 * C + C + h * HD + t) * 16;
        float s = 0.f;
        #pragma unroll
        for (int j = 0; j < 16; j++) s += pk[j];
        kinv[t] = 1.f / fmaxf(sqrtf(s), 1e-12f);
    }
    if (t == 0) {
        const float* pq = g_ssq_part + ((size_t)b * 3 * C + h * HD + i) * 16;
        float s = 0.f;
        #pragma unroll
        for (int j = 0; j < 16; j++) s += pq[j];
        qinv = 1.f / fmaxf(sqrtf(s), 1e-12f);
    }
    __syncthreads();
    if (t < HD) {
        float s = 0.f;
        const float* pp = g_attn_part + (size_t)bh * NSPLIT * HD * HD + i * HD + t;
        for (int sp = 0; sp < NSPLIT; sp++) s += pp[(size_t)sp * HD * HD];
        row[t] = s * qinv * kinv[t] * scale * g_temp[b * HEADS + h];
    }
    __syncthreads();
    if (t == 0) { float m = -1e30f; for (int j = 0; j < HD; j++) m = fmaxf(m, row[j]); mx = m; }
    __syncthreads();
    if (t < HD) row[t] = expf(row[t] - mx);
    __syncthreads();
    if (t == 0) { float s2 = 0.f; for (int j = 0; j < HD; j++) s2 += row[j]; sm = s2; }
    __syncthreads();
    if (t < HD)
        g_attn[(size_t)bh * HD * HD + i * HD + t] = row[t] / sm * g_vgate[b * C + h * HD + t];
}

// ---------------- fused: g_mid = dwconv(v, w_local) + attn @ v  (packed v, fp32 out) ----------------
__global__ void ogl_kernel(const float* __restrict__ w_local) {
    __shared__ float sA[HD * HD];
    __shared__ float sV[HD][65];
    int bh = blockIdx.y;
    int b = bh / HEADS, h = bh % HEADS;
    int n0 = blockIdx.x * 64;
    const unsigned* vpk = g_buf2_pk + ((size_t)b * QKVP + 2 * KPC + h * (HD / 2)) * NPIX;
    int t = threadIdx.x;
    for (int e = t; e < HD * HD; e += 256) sA[e] = g_attn[(size_t)bh * HD * HD + e];
    for (int e = t; e < (HD / 2) * 64; e += 256) {
        int p = e >> 6, n = e & 63;
        float2 v2 = up2(vpk[(size_t)p * NPIX + n0 + n]);
        sV[2 * p][n] = v2.x; sV[2 * p + 1][n] = v2.y;
    }
    __syncthreads();
    int i0 = (t >> 4) * 3;
    int nl = (t & 15) * 4;
    float acc[3][4];
    #pragma unroll
    for (int a = 0; a < 3; a++)
        #pragma unroll
        for (int q = 0; q < 4; q++) acc[a][q] = 0.f;
    #pragma unroll 4
    for (int j = 0; j < HD; j++) {
        float vv[4];
        #pragma unroll
        for (int q = 0; q < 4; q++) vv[q] = sV[j][nl + q];
        #pragma unroll
        for (int a = 0; a < 3; a++) {
            float aa = sA[(i0 + a) * HD + j];
            #pragma unroll
            for (int q = 0; q < 4; q++) acc[a][q] += aa * vv[q];
        }
    }
    int y = (n0 + nl) >> 7, x = (n0 + nl) & 127;
    #pragma unroll
    for (int a = 0; a < 3; a++) {
        int ch = i0 + a;
        float d[4];
        dw3x3_pk1_v4(vpk + (size_t)(ch >> 1) * NPIX, ch & 1,
                     w_local + (h * HD + ch) * 9, y, x, d);
        #pragma unroll
        for (int q = 0; q < 4; q++) acc[a][q] += d[q];
    }
    float* op = g_mid + (size_t)b * C * NPIX + (size_t)(h * HD) * NPIX + n0;
    #pragma unroll
    for (int a = 0; a < 3; a++)
        #pragma unroll
        for (int q = 0; q < 4; q++)
            op[(size_t)(i0 + a) * NPIX + nl + q] = acc[a][q];
}

// ---------------- launch ----------------
extern "C" void kernel_launch(void* const* d_in, const int* in_sizes, int n_in,
                              void* d_out, int out_size) {
    const float* x        = (const float*)d_in[0];
    const float* ctx      = (const float*)d_in[1];
    const float* ln1_w    = (const float*)d_in[2];
    const float* ln1_b    = (const float*)d_in[3];
    const float* ln2_w    = (const float*)d_in[4];
    const float* ln2_b    = (const float*)d_in[5];
    const float* w_qkv    = (const float*)d_in[6];
    const float* w_qkv_dw = (const float*)d_in[7];
    const float* w_proj   = (const float*)d_in[8];
    const float* base_temp= (const float*)d_in[9];
    const float* ta_w1    = (const float*)d_in[10];
    const float* ta_b1    = (const float*)d_in[11];
    const float* ta_w2    = (const float*)d_in[12];
    const float* ta_b2    = (const float*)d_in[13];
    const float* vg_w     = (const float*)d_in[14];
    const float* vg_b     = (const float*)d_in[15];
    const float* w_local  = (const float*)d_in[16];
    const float* w_ffn_in = (const float*)d_in[17];
    const float* w_ffn_dw = (const float*)d_in[18];
    const float* w_ffn_out= (const float*)d_in[19];
    float* out = (float*)d_out;

    unsigned *p_xn, *p_buf1, *p_buf2, *p_gelu, *p_wqkv, *p_wffin, *p_wout;
    float *p_mid, *p_x2;
    cudaGetSymbolAddress((void**)&p_xn,    g_xn_pk);
    cudaGetSymbolAddress((void**)&p_buf1,  g_buf1_pk);
    cudaGetSymbolAddress((void**)&p_buf2,  g_buf2_pk);
    cudaGetSymbolAddress((void**)&p_mid,   g_mid);
    cudaGetSymbolAddress((void**)&p_x2,    g_x2);
    cudaGetSymbolAddress((void**)&p_gelu,  g_gelu_pk);
    cudaGetSymbolAddress((void**)&p_wqkv,  g_wqkv_pk);
    cudaGetSymbolAddress((void**)&p_wffin, g_wffin_pk);
    cudaGetSymbolAddress((void**)&p_wout,  g_wout_pk);

    ctx_kernel<<<B, 256>>>(ctx, ta_w1, ta_b1, ta_w2, ta_b2, vg_w, vg_b, base_temp);
    pack_all_kernel<<<(NW1 + NW2 + NW3 + 255) / 256, 256>>>(w_qkv, w_ffn_in, w_ffn_out);

    // LN1 -> packed bf16 (smem staged)
    ln_kernel<<<B * NPIX / LNPX, 256>>>(x, ln1_w, ln1_b, p_xn);
    // qkv conv1x1 (576 x 192), bf16 -> packed pairs
    mma_gemm_bf16_pk<<<dim3(NPIX / 256, (3 * C) / 64, B), 256>>>(p_wqkv, p_xn, p_buf1, 3 * C, KPC);
    // qkv dwconv packed->packed + q/k sumsq partials
    dwconv_qkv_pk<<<(B * QKVP * NPIX / 4) / 256, 256>>>(p_buf1, w_qkv_dw, p_buf2);
    attn_part_kernel<<<B * HEADS * NSPLIT, 256>>>();
    softmax_kernel<<<B * HEADS * HD, 64>>>();
    // fused out_local + out_global -> g_mid (fp32)
    ogl_kernel<<<dim3(NPIX / 64, B * HEADS), 256>>>(w_local);
    // proj conv1x1 + residual(x), tf32 (fp32 inputs) -> g_x2
    mma_gemm<<<dim3(NPIX / 256, C / 64, B), 256>>>(w_proj, p_mid, p_x2, x, C, C);
    // LN2 -> packed bf16 (smem staged)
    ln_kernel<<<B * NPIX / LNPX, 256>>>(p_x2, ln2_w, ln2_b, p_xn);
    // ffn_in conv1x1 (1020 x 192), bf16 -> packed pairs
    mma_gemm_bf16_pk<<<dim3(NPIX / 256, (FFN2 + 63) / 64, B), 256>>>(p_wffin, p_xn, p_buf1, FFN2, KPC);
    // fused ffn dwconv + gelu gate, packed -> packed
    dwgelu_pk_kernel<<<(B * KPH * NPIX / 4) / 256, 256>>>(p_buf1, w_ffn_dw, p_gelu);
    // ffn_out conv1x1 (192 x 512 padded) + residual(g_x2) -> fp32 out
    mma_gemm_bf16<<<dim3(NPIX / 256, C / 64, B), 256>>>(p_wout, p_gelu, out, p_x2, C, KPH);
}

// round 13
// speedup vs baseline: 1.1559x; 1.0702x over previous
#include <cuda_runtime.h>
#include <cuda_bf16.h>
#include <math.h>

#define B 8
#define C 192
#define HEADS 4
#define HD 48
#define HGT 128
#define WID 128
#define NPIX 16384
#define CTXD 256
#define HID 510
#define FFN2 1020
#define NSPLIT 32
#define KPC (C / 2)        // 96 k-pairs for Cin=192
#define KPH 256            // 256 k-pairs for padded gelu (510->512)
#define QKVP (3 * C / 2)   // 288 pairs in qkv
#define FFP  (FFN2 / 2)    // 510 pairs in ffn intermediate
#define LNPX 64            // pixels per LN block

// ---------------- scratch (static device globals; allocation-free) ----------------
__device__ unsigned g_xn_pk [B * KPC * NPIX];
__device__ unsigned g_buf1_pk[B * FFP * NPIX];
__device__ unsigned g_buf2_pk[B * QKVP * NPIX];
__device__ float    g_mid [B * C    * NPIX];
__device__ float    g_x2  [B * C    * NPIX];
__device__ unsigned g_gelu_pk[B * KPH * NPIX];
__device__ unsigned g_wqkv_pk [3 * C * KPC];
__device__ unsigned g_wffin_pk[FFN2  * KPC];
__device__ unsigned g_wout_pk [C * KPH];
__device__ float g_attn_part[B * HEADS * NSPLIT * HD * HD];
__device__ float g_attn[B * HEADS * HD * HD];
__device__ float g_temp [B * HEADS];
__device__ float g_vgate[B * C];
__device__ float g_ssq_part[B * 3 * C * 16];

// ---------------- helpers ----------------
__device__ __forceinline__ unsigned pack_bf2(float lo, float hi) {
    __nv_bfloat162 h = __floats2bfloat162_rn(lo, hi);
    return *reinterpret_cast<unsigned*>(&h);
}
__device__ __forceinline__ float2 up2(unsigned u) {
    __nv_bfloat162 h = *reinterpret_cast<__nv_bfloat162*>(&u);
    return make_float2(__bfloat162float(h.x), __bfloat162float(h.y));
}
__device__ __forceinline__ __nv_bfloat162 asbf2(unsigned u) {
    return *reinterpret_cast<__nv_bfloat162*>(&u);
}
__device__ __forceinline__ unsigned asu32(__nv_bfloat162 h) {
    return *reinterpret_cast<unsigned*>(&h);
}
__device__ __forceinline__ void mma_bf16(float* d, const unsigned* a, const unsigned* b) {
    asm volatile(
        "mma.sync.aligned.m16n8k16.row.col.f32.bf16.bf16.f32 "
        "{%0,%1,%2,%3}, {%4,%5,%6,%7}, {%8,%9}, {%0,%1,%2,%3};\n"
        : "+f"(d[0]), "+f"(d[1]), "+f"(d[2]), "+f"(d[3])
        : "r"(a[0]), "r"(a[1]), "r"(a[2]), "r"(a[3]), "r"(b[0]), "r"(b[1]));
}
__device__ __forceinline__ void mma_tf32(float* d, const unsigned* a, const unsigned* b) {
    asm volatile(
        "mma.sync.aligned.m16n8k8.row.col.f32.tf32.tf32.f32 "
        "{%0,%1,%2,%3}, {%4,%5,%6,%7}, {%8,%9}, {%0,%1,%2,%3};\n"
        : "+f"(d[0]), "+f"(d[1]), "+f"(d[2]), "+f"(d[3])
        : "r"(a[0]), "r"(a[1]), "r"(a[2]), "r"(a[3]), "r"(b[0]), "r"(b[1]));
}
__device__ __forceinline__ unsigned smem_u32(const void* p) {
    return (unsigned)__cvta_generic_to_shared(p);
}
__device__ __forceinline__ void cp16(unsigned dst, const void* src) {
    asm volatile("cp.async.cg.shared.global [%0], [%1], 16;" :: "r"(dst), "l"(src));
}
__device__ __forceinline__ void cp16p(unsigned dst, const void* src, bool pred) {
    int sz = pred ? 16 : 0;
    asm volatile("cp.async.cg.shared.global [%0], [%1], 16, %2;" :: "r"(dst), "l"(src), "r"(sz));
}
__device__ __forceinline__ void cp_commit() { asm volatile("cp.async.commit_group;"); }
template <int N>
__device__ __forceinline__ void cp_wait() { asm volatile("cp.async.wait_group %0;" :: "n"(N)); }

// ---------------- context adapters ----------------
__global__ void ctx_kernel(const float* __restrict__ ctx,
                           const float* __restrict__ ta_w1, const float* __restrict__ ta_b1,
                           const float* __restrict__ ta_w2, const float* __restrict__ ta_b2,
                           const float* __restrict__ vg_w,  const float* __restrict__ vg_b,
                           const float* __restrict__ base_temp) {
    __shared__ float sctx[CTXD];
    __shared__ float hid[HD];
    int b = blockIdx.x, t = threadIdx.x;
    sctx[t] = ctx[b * CTXD + t];
    __syncthreads();
    if (t < HD) {
        float s = ta_b1[t];
        for (int k = 0; k < CTXD; k++) s += sctx[k] * ta_w1[t * CTXD + k];
        hid[t] = fmaxf(s, 0.f);
    }
    __syncthreads();
    if (t < HEADS) {
        float s = ta_b2[t];
        for (int k = 0; k < HD; k++) s += hid[k] * ta_w2[t * HD + k];
        float f = 1.f / (1.f + expf(-s)) * 2.f + 0.5f;
        g_temp[b * HEADS + t] = base_temp[t] * f;
    }
    if (t < C) {
        float s = vg_b[t];
        for (int k = 0; k < CTXD; k++) s += sctx[k] * vg_w[t * CTXD + k];
        g_vgate[b * C + t] = 1.f / (1.f + expf(-s));
    }
}

// ---------------- pack ALL weights in one launch ----------------
#define NW1 (3 * C * KPC)
#define NW2 (FFN2 * KPC)
#define NW3 (C * KPH)
__global__ void pack_all_kernel(const float* __restrict__ wqkv,
                                const float* __restrict__ wffin,
                                const float* __restrict__ wout) {
    int i = blockIdx.x * 256 + threadIdx.x;
    if (i < NW1) {
        int o = i / KPC, p = i % KPC;
        g_wqkv_pk[i] = pack_bf2(wqkv[(size_t)o * C + 2 * p], wqkv[(size_t)o * C + 2 * p + 1]);
    } else if (i < NW1 + NW2) {
        int e = i - NW1;
        int o = e / KPC, p = e % KPC;
        g_wffin_pk[e] = pack_bf2(wffin[(size_t)o * C + 2 * p], wffin[(size_t)o * C + 2 * p + 1]);
    } else if (i < NW1 + NW2 + NW3) {
        int e = i - NW1 - NW2;
        int o = e / KPH, p = e % KPH;
        float f0 = (2 * p     < HID) ? wout[(size_t)o * HID + 2 * p]     : 0.f;
        float f1 = (2 * p + 1 < HID) ? wout[(size_t)o * HID + 2 * p + 1] : 0.f;
        g_wout_pk[e] = pack_bf2(f0, f1);
    }
}

// ---------------- layernorm: smem-staged, 64 px / block -> packed bf16 ----------------
__global__ void __launch_bounds__(256) ln_kernel(const float* __restrict__ x,
                                                 const float* __restrict__ w,
                                                 const float* __restrict__ bias,
                                                 unsigned* __restrict__ out) {
    __shared__ unsigned sXp[KPC][LNPX + 1];
    __shared__ float sRed[2][4][LNPX];
    __shared__ float sMu[LNPX], sRs[LNPX];
    int blk = blockIdx.x;
    int b = blk / (NPIX / LNPX);
    int n0 = (blk % (NPIX / LNPX)) * LNPX;
    int t = threadIdx.x;
    const float* xb = x + (size_t)b * C * NPIX + n0;
    for (int e = t; e < KPC * LNPX; e += 256) {
        int p = e >> 6, j = e & 63;
        float v0 = xb[(size_t)(2 * p)     * NPIX + j];
        float v1 = xb[(size_t)(2 * p + 1) * NPIX + j];
        sXp[p][j] = pack_bf2(v0, v1);
    }
    __syncthreads();
    {
        int j = t >> 2, part = t & 3;
        float s = 0.f, ss = 0.f;
        #pragma unroll 4
        for (int p = part * 24; p < part * 24 + 24; p++) {
            float2 v = up2(sXp[p][j]);
            s += v.x + v.y;
            ss += v.x * v.x + v.y * v.y;
        }
        sRed[0][part][j] = s;
        sRed[1][part][j] = ss;
    }
    __syncthreads();
    if ((t & 3) == 0) {
        int j = t >> 2;
        float st  = sRed[0][0][j] + sRed[0][1][j] + sRed[0][2][j] + sRed[0][3][j];
        float sst = sRed[1][0][j] + sRed[1][1][j] + sRed[1][2][j] + sRed[1][3][j];
        const float ic = 1.f / C;
        float mu = st * ic;
        sMu[j] = mu;
        sRs[j] = rsqrtf(sst * ic - mu * mu + 1e-5f);
    }
    __syncthreads();
    unsigned* ob = out + (size_t)b * KPC * NPIX + n0;
    for (int e = t; e < KPC * LNPX; e += 256) {
        int p = e >> 6, j = e & 63;
        float2 v = up2(sXp[p][j]);
        float mu = sMu[j], rs = sRs[j];
        float v0 = (v.x - mu) * rs * w[2 * p]     + bias[2 * p];
        float v1 = (v.y - mu) * rs * w[2 * p + 1] + bias[2 * p + 1];
        ob[(size_t)p * NPIX + j] = pack_bf2(v0, v1);
    }
}

// ============ bf16 GEMM core (shared macro body) ============
#define GEMM_BODY(MMAOP)                                                          \
    int b  = blockIdx.z;                                                          \
    int o0 = blockIdx.y * 64;                                                     \
    int n0 = blockIdx.x * 256;                                                    \
    const unsigned* Xb = Xpk + (size_t)b * Kpairs * NPIX + n0;                    \
    int tid  = threadIdx.x;                                                       \
    int warp = tid >> 5, lane = tid & 31;                                         \
    int wm = warp >> 2, wn = warp & 3;                                            \
    int mrow = lane >> 2, kq = lane & 3;                                          \
    float acc[2][8][4];                                                           \
    _Pragma("unroll") for (int mt = 0; mt < 2; mt++)                              \
        _Pragma("unroll") for (int nt = 0; nt < 8; nt++)                          \
            _Pragma("unroll") for (int q = 0; q < 4; q++) acc[mt][nt][q] = 0.f;   \
    int am  = tid >> 2;                                                           \
    int ak4 = (tid & 3) * 4;                                                      \
    bool apred = (o0 + am) < O;                                                   \
    const unsigned* aSrcBase = Apk + (size_t)(o0 + am) * Kpairs + ak4;            \
    int ktiles = Kpairs >> 4;                                                     \
    auto LOAD = [&](int kt, int buf) {                                            \
        int p0 = kt << 4;                                                         \
        cp16p(smem_u32(&sA[buf][am][ak4]), aSrcBase + p0, apred);                 \
        _Pragma("unroll") for (int i = 0; i < 4; i++) {                           \
            int e = tid + i * 256;                                                \
            int kk = e >> 6;                                                      \
            int nn = (e & 63) * 4;                                                \
            cp16(smem_u32(&sB[buf][kk][nn]), Xb + (size_t)(p0 + kk) * NPIX + nn); \
        }                                                                         \
        cp_commit();                                                              \
    };                                                                            \
    LOAD(0, 0);                                                                   \
    for (int kt = 0; kt < ktiles; kt++) {                                         \
        int cur = kt & 1;                                                         \
        if (kt + 1 < ktiles) { LOAD(kt + 1, cur ^ 1); cp_wait<1>(); }             \
        else cp_wait<0>();                                                        \
        __syncthreads();                                                          \
        _Pragma("unroll") for (int ks = 0; ks < 2; ks++) {                        \
            const int p0 = ks * 8;                                                \
            unsigned afr[2][4], bfr[8][2];                                        \
            _Pragma("unroll") for (int mt = 0; mt < 2; mt++) {                    \
                int m = wm * 32 + mt * 16 + mrow;                                 \
                afr[mt][0] = sA[cur][m    ][p0 + kq];                             \
                afr[mt][1] = sA[cur][m + 8][p0 + kq];                             \
                afr[mt][2] = sA[cur][m    ][p0 + kq + 4];                         \
                afr[mt][3] = sA[cur][m + 8][p0 + kq + 4];                         \
            }                                                                     \
            _Pragma("unroll") for (int nt = 0; nt < 8; nt++) {                    \
                int n = wn * 64 + nt * 8 + mrow;                                  \
                bfr[nt][0] = sB[cur][p0 + kq    ][n];                             \
                bfr[nt][1] = sB[cur][p0 + kq + 4][n];                             \
            }                                                                     \
            _Pragma("unroll") for (int mt = 0; mt < 2; mt++)                      \
                _Pragma("unroll") for (int nt = 0; nt < 8; nt++)                  \
                    MMAOP(acc[mt][nt], afr[mt], bfr[nt]);                         \
        }                                                                         \
        __syncthreads();                                                          \
    }

// fp32 output + optional fp32 residual (ffn_out)
__global__ void __launch_bounds__(256) mma_gemm_bf16(const unsigned* __restrict__ Apk,
                                                     const unsigned* __restrict__ Xpk,
                                                     float* __restrict__ Y,
                                                     const float* __restrict__ Res,
                                                     int O, int Kpairs) {
    __shared__ unsigned sA[2][64][20];
    __shared__ unsigned sB[2][16][264];
    GEMM_BODY(mma_bf16)
    size_t base = (size_t)b * O * NPIX;
    #pragma unroll
    for (int mt = 0; mt < 2; mt++) {
        #pragma unroll
        for (int nt = 0; nt < 8; nt++) {
            int ncol = n0 + wn * 64 + nt * 8 + 2 * kq;
            int r0 = o0 + wm * 32 + mt * 16 + mrow;
            if (r0 < O) {
                size_t off = base + (size_t)r0 * NPIX + ncol;
                float2 rr = Res ? *reinterpret_cast<const float2*>(Res + off)
                                : make_float2(0.f, 0.f);
                *reinterpret_cast<float2*>(Y + off) =
                    make_float2(acc[mt][nt][0] + rr.x, acc[mt][nt][1] + rr.y);
            }
            int r1 = r0 + 8;
            if (r1 < O) {
                size_t off = base + (size_t)r1 * NPIX + ncol;
                float2 rr = Res ? *reinterpret_cast<const float2*>(Res + off)
                                : make_float2(0.f, 0.f);
                *reinterpret_cast<float2*>(Y + off) =
                    make_float2(acc[mt][nt][2] + rr.x, acc[mt][nt][3] + rr.y);
            }
        }
    }
}

// packed bf16 channel-pair output (qkv / ffn_in). O must be even.
__global__ void __launch_bounds__(256) mma_gemm_bf16_pk(const unsigned* __restrict__ Apk,
                                                        const unsigned* __restrict__ Xpk,
                                                        unsigned* __restrict__ Ypk,
                                                        int O, int Kpairs) {
    __shared__ unsigned sA[2][64][20];
    __shared__ unsigned sB[2][16][264];
    GEMM_BODY(mma_bf16)
    size_t base = (size_t)b * (O >> 1) * NPIX;
    bool writer = ((mrow & 1) == 0);
    #pragma unroll
    for (int mt = 0; mt < 2; mt++) {
        #pragma unroll
        for (int nt = 0; nt < 8; nt++) {
            int ncol = n0 + wn * 64 + nt * 8 + 2 * kq;
            int r0 = o0 + wm * 32 + mt * 16 + mrow;
            float p0 = __shfl_xor_sync(0xffffffffu, acc[mt][nt][0], 4);
            float p1 = __shfl_xor_sync(0xffffffffu, acc[mt][nt][1], 4);
            float p2 = __shfl_xor_sync(0xffffffffu, acc[mt][nt][2], 4);
            float p3 = __shfl_xor_sync(0xffffffffu, acc[mt][nt][3], 4);
            if (writer && r0 < O) {
                size_t off = base + (size_t)(r0 >> 1) * NPIX + ncol;
                *reinterpret_cast<uint2*>(Ypk + off) =
                    make_uint2(pack_bf2(acc[mt][nt][0], p0), pack_bf2(acc[mt][nt][1], p1));
            }
            if (writer && r0 + 8 < O) {
                size_t off = base + (size_t)((r0 + 8) >> 1) * NPIX + ncol;
                *reinterpret_cast<uint2*>(Ypk + off) =
                    make_uint2(pack_bf2(acc[mt][nt][2], p2), pack_bf2(acc[mt][nt][3], p3));
            }
        }
    }
}

// ---------------- tf32 GEMM (fp32 inputs) — proj only ----------------
__global__ void __launch_bounds__(256) mma_gemm(const float* __restrict__ Wm,
                                                const float* __restrict__ X,
                                                float* __restrict__ Y,
                                                const float* __restrict__ Res,
                                                int O, int Cin) {
    __shared__ float sA[2][64][20];
    __shared__ float sB[2][16][264];

    int b  = blockIdx.z;
    int o0 = blockIdx.y * 64;
    int n0 = blockIdx.x * 256;
    const float* Xb = X + (size_t)b * Cin * NPIX + n0;

    int tid  = threadIdx.x;
    int warp = tid >> 5, lane = tid & 31;
    int wm = warp >> 2, wn = warp & 3;
    int mrow = lane >> 2, kq = lane & 3;

    float acc[2][8][4];
    #pragma unroll
    for (int mt = 0; mt < 2; mt++)
        #pragma unroll
        for (int nt = 0; nt < 8; nt++)
            #pragma unroll
            for (int q = 0; q < 4; q++) acc[mt][nt][q] = 0.f;

    int am  = tid >> 2;
    int ak4 = (tid & 3) * 4;
    bool apred = (o0 + am) < O;
    const float* aSrcBase = Wm + (size_t)(o0 + am) * Cin + ak4;

    int ktiles = Cin >> 4;

    auto LOAD = [&](int kt, int buf) {
        int c0 = kt << 4;
        cp16p(smem_u32(&sA[buf][am][ak4]), aSrcBase + c0, apred);
        #pragma unroll
        for (int i = 0; i < 4; i++) {
            int e = tid + i * 256;
            int kk = e >> 6;
            int nn = (e & 63) * 4;
            cp16(smem_u32(&sB[buf][kk][nn]), Xb + (size_t)(c0 + kk) * NPIX + nn);
        }
        cp_commit();
    };

    LOAD(0, 0);
    for (int kt = 0; kt < ktiles; kt++) {
        int cur = kt & 1;
        if (kt + 1 < ktiles) { LOAD(kt + 1, cur ^ 1); cp_wait<1>(); }
        else cp_wait<0>();
        __syncthreads();

        const unsigned (*A)[20]   = reinterpret_cast<const unsigned (*)[20]>(sA[cur]);
        const unsigned (*Bs)[264] = reinterpret_cast<const unsigned (*)[264]>(sB[cur]);
        #pragma unroll
        for (int ks = 0; ks < 2; ks++) {
            const int k0 = ks * 8;
            unsigned afr[2][4], bfr[8][2];
            #pragma unroll
            for (int mt = 0; mt < 2; mt++) {
                int m = wm * 32 + mt * 16 + mrow;
                afr[mt][0] = A[m    ][k0 + kq];
                afr[mt][1] = A[m + 8][k0 + kq];
                afr[mt][2] = A[m    ][k0 + kq + 4];
                afr[mt][3] = A[m + 8][k0 + kq + 4];
            }
            #pragma unroll
            for (int nt = 0; nt < 8; nt++) {
                int n = wn * 64 + nt * 8 + mrow;
                bfr[nt][0] = Bs[k0 + kq    ][n];
                bfr[nt][1] = Bs[k0 + kq + 4][n];
            }
            #pragma unroll
            for (int mt = 0; mt < 2; mt++)
                #pragma unroll
                for (int nt = 0; nt < 8; nt++)
                    mma_tf32(acc[mt][nt], afr[mt], bfr[nt]);
        }
        __syncthreads();
    }

    size_t base = (size_t)b * O * NPIX;
    #pragma unroll
    for (int mt = 0; mt < 2; mt++) {
        #pragma unroll
        for (int nt = 0; nt < 8; nt++) {
            int ncol = n0 + wn * 64 + nt * 8 + 2 * kq;
            int r0 = o0 + wm * 32 + mt * 16 + mrow;
            if (r0 < O) {
                size_t off = base + (size_t)r0 * NPIX + ncol;
                float2 rr = Res ? *reinterpret_cast<const float2*>(Res + off)
                                : make_float2(0.f, 0.f);
                *reinterpret_cast<float2*>(Y + off) =
                    make_float2(acc[mt][nt][0] + rr.x, acc[mt][nt][1] + rr.y);
            }
            int r1 = r0 + 8;
            if (r1 < O) {
                size_t off = base + (size_t)r1 * NPIX + ncol;
                float2 rr = Res ? *reinterpret_cast<const float2*>(Res + off)
                                : make_float2(0.f, 0.f);
                *reinterpret_cast<float2*>(Y + off) =
                    make_float2(acc[mt][nt][2] + rr.x, acc[mt][nt][3] + rr.y);
            }
        }
    }
}

// ---------------- bf16x2 dual-channel 3x3 depthwise (HFMA2), 4 px / thread ----------------
// sw: 9 bf162 taps (ch_lo, ch_hi). acc returned as bf162 per pixel.
__device__ __forceinline__ void dw3x3_h2_v4(const unsigned* __restrict__ ip,
                                            const __nv_bfloat162* __restrict__ sw,
                                            int y, int x, __nv_bfloat162* acc) {
    __nv_bfloat162 z = __float2bfloat162_rn(0.f);
    acc[0] = z; acc[1] = z; acc[2] = z; acc[3] = z;
    #pragma unroll
    for (int ky = 0; ky < 3; ky++) {
        int yy = y + ky - 1;
        if (yy < 0 || yy >= HGT) continue;
        const unsigned* row = ip + yy * WID + x;
        uint4 m = *reinterpret_cast<const uint4*>(row);
        unsigned lu = (x > 0)   ? row[-1] : 0u;
        unsigned ru = (x < 124) ? row[4]  : 0u;
        __nv_bfloat162 L = asbf2(lu), X0 = asbf2(m.x), X1 = asbf2(m.y),
                       X2 = asbf2(m.z), X3 = asbf2(m.w), R = asbf2(ru);
        __nv_bfloat162 w0 = sw[ky * 3], w1 = sw[ky * 3 + 1], w2 = sw[ky * 3 + 2];
        acc[0] = __hfma2(L,  w0, __hfma2(X0, w1, __hfma2(X1, w2, acc[0])));
        acc[1] = __hfma2(X0, w0, __hfma2(X1, w1, __hfma2(X2, w2, acc[1])));
        acc[2] = __hfma2(X1, w0, __hfma2(X2, w1, __hfma2(X3, w2, acc[2])));
        acc[3] = __hfma2(X2, w0, __hfma2(X3, w1, __hfma2(R,  w2, acc[3])));
    }
}

// single-channel from packed plane (for ogl local conv)
__device__ __forceinline__ void dw3x3_pk1_v4(const unsigned* __restrict__ ip, int hi,
                                             const float* __restrict__ wp,
                                             int y, int x, float* acc) {
    acc[0] = acc[1] = acc[2] = acc[3] = 0.f;
    #pragma unroll
    for (int ky = 0; ky < 3; ky++) {
        int yy = y + ky - 1;
        if (yy < 0 || yy >= HGT) continue;
        const unsigned* row = ip + yy * WID + x;
        uint4 m = *reinterpret_cast<const uint4*>(row);
        unsigned lu = (x > 0)   ? row[-1] : 0u;
        unsigned ru = (x < 124) ? row[4]  : 0u;
        float L, X0, X1, X2, X3, R;
        if (hi) {
            L = up2(lu).y; X0 = up2(m.x).y; X1 = up2(m.y).y; X2 = up2(m.z).y; X3 = up2(m.w).y; R = up2(ru).y;
        } else {
            L = up2(lu).x; X0 = up2(m.x).x; X1 = up2(m.y).x; X2 = up2(m.z).x; X3 = up2(m.w).x; R = up2(ru).x;
        }
        float w0 = wp[ky * 3], w1 = wp[ky * 3 + 1], w2 = wp[ky * 3 + 2];
        acc[0] += L  * w0 + X0 * w1 + X1 * w2;
        acc[1] += X0 * w0 + X1 * w1 + X2 * w2;
        acc[2] += X1 * w0 + X2 * w1 + X3 * w2;
        acc[3] += X2 * w0 + X3 * w1 + R  * w2;
    }
}

// ---------------- qkv dwconv (packed->packed, HFMA2) + q/k sumsq partials ----------------
__global__ void dwconv_qkv_pk(const unsigned* __restrict__ in, const float* __restrict__ w,
                              unsigned* __restrict__ out) {
    __shared__ float2 red2[256];
    __shared__ __nv_bfloat162 swt[9];
    int idx = blockIdx.x * 256 + threadIdx.x;   // B*QKVP*NPIX/4
    int n = (idx & (NPIX / 4 - 1)) * 4;
    int bp = idx >> 12;                          // uniform per block
    int p = bp % QKVP;
    if (threadIdx.x < 9)
        swt[threadIdx.x] = __floats2bfloat162_rn(w[(2 * p) * 9 + threadIdx.x],
                                                 w[(2 * p + 1) * 9 + threadIdx.x]);
    __syncthreads();
    int y = n >> 7, x = n & 127;
    const unsigned* ip = in + (size_t)bp * NPIX;
    __nv_bfloat162 acc[4];
    dw3x3_h2_v4(ip, swt, y, x, acc);
    unsigned o4[4];
    #pragma unroll
    for (int j = 0; j < 4; j++) o4[j] = asu32(acc[j]);
    *reinterpret_cast<uint4*>(out + (size_t)bp * NPIX + n) =
        make_uint4(o4[0], o4[1], o4[2], o4[3]);
    if (p < 2 * KPC) {   // q,k pairs
        int b = bp / QKVP;
        float ss0 = 0.f, ss1 = 0.f;
        #pragma unroll
        for (int j = 0; j < 4; j++) {
            float2 v = up2(o4[j]);
            ss0 += v.x * v.x; ss1 += v.y * v.y;
        }
        red2[threadIdx.x] = make_float2(ss0, ss1);
        __syncthreads();
        for (int s = 128; s > 0; s >>= 1) {
            if (threadIdx.x < s) {
                red2[threadIdx.x].x += red2[threadIdx.x + s].x;
                red2[threadIdx.x].y += red2[threadIdx.x + s].y;
            }
            __syncthreads();
        }
        if (threadIdx.x == 0) {
            int blk = blockIdx.x & 15;
            g_ssq_part[((size_t)b * 3 * C + 2 * p) * 16 + blk]     = red2[0].x;
            g_ssq_part[((size_t)b * 3 * C + 2 * p + 1) * 16 + blk] = red2[0].y;
        }
    }
}

// ---------------- fused FFN dwconv (HFMA2) + gelu gate (packed -> packed) ----------------
__global__ void dwgelu_pk_kernel(const unsigned* __restrict__ in, const float* __restrict__ w,
                                 unsigned* __restrict__ outg) {
    __shared__ __nv_bfloat162 swA[9], swB[9];
    int idx = blockIdx.x * 256 + threadIdx.x;   // B * KPH * NPIX/4
    int n = (idx & (NPIX / 4 - 1)) * 4;
    int bc = idx >> 12;                          // uniform per block
    int p = bc & (KPH - 1), b = bc >> 8;
    unsigned* op = outg + (size_t)bc * NPIX + n;
    if (p == KPH - 1) {                          // channels 510,511 -> zero pad
        *reinterpret_cast<uint4*>(op) = make_uint4(0u, 0u, 0u, 0u);
        return;
    }
    int c = 2 * p;
    if (threadIdx.x < 9) {
        swA[threadIdx.x] = __floats2bfloat162_rn(w[c * 9 + threadIdx.x],
                                                 w[(c + 1) * 9 + threadIdx.x]);
        swB[threadIdx.x] = __floats2bfloat162_rn(w[(c + HID) * 9 + threadIdx.x],
                                                 w[(c + 1 + HID) * 9 + threadIdx.x]);
    }
    __syncthreads();
    int y = n >> 7, x = n & 127;
    const unsigned* base = in + (size_t)b * FFP * NPIX;
    __nv_bfloat162 a1[4], a2[4];
    dw3x3_h2_v4(base + (size_t)p * NPIX,         swA, y, x, a1);
    dw3x3_h2_v4(base + (size_t)(p + 255) * NPIX, swB, y, x, a2);
    unsigned o4[4];
    #pragma unroll
    for (int j = 0; j < 4; j++) {
        float2 y1 = up2(asu32(a1[j]));
        float2 y2 = up2(asu32(a2[j]));
        float ga = 0.5f * y1.x * (1.f + erff(y1.x * 0.70710678118654752f)) * y2.x;
        float gb = 0.5f * y1.y * (1.f + erff(y1.y * 0.70710678118654752f)) * y2.y;
        o4[j] = pack_bf2(ga, gb);
    }
    *reinterpret_cast<uint4*>(op) = make_uint4(o4[0], o4[1], o4[2], o4[3]);
}

// ---------------- attention gram partials (packed q,k) ----------------
__global__ void attn_part_kernel() {
    __shared__ float sQ[HD][33], sK[HD][33];
    int bh = blockIdx.x / NSPLIT, sp = blockIdx.x % NSPLIT;
    int b = bh / HEADS, h = bh % HEADS;
    const unsigned* qpk = g_buf2_pk + ((size_t)b * QKVP + h * (HD / 2)) * NPIX;
    const unsigned* kpk = qpk + (size_t)KPC * NPIX;
    int t = threadIdx.x;
    int i0 = (t >> 4) * 3, j0 = (t & 15) * 3;
    float acc[3][3];
    #pragma unroll
    for (int a = 0; a < 3; a++)
        #pragma unroll
        for (int c2 = 0; c2 < 3; c2++) acc[a][c2] = 0.f;
    int n0 = sp * (NPIX / NSPLIT);
    for (int ch = 0; ch < NPIX / NSPLIT; ch += 32) {
        for (int e = t; e < (HD / 2) * 32; e += 256) {
            int p = e >> 5, nn = e & 31;
            float2 q2 = up2(qpk[(size_t)p * NPIX + n0 + ch + nn]);
            float2 k2 = up2(kpk[(size_t)p * NPIX + n0 + ch + nn]);
            sQ[2 * p][nn] = q2.x; sQ[2 * p + 1][nn] = q2.y;
            sK[2 * p][nn] = k2.x; sK[2 * p + 1][nn] = k2.y;
        }
        __syncthreads();
        #pragma unroll 4
        for (int kk = 0; kk < 32; kk++) {
            float qa[3], ka[3];
            #pragma unroll
            for (int a = 0; a < 3; a++) { qa[a] = sQ[i0 + a][kk]; ka[a] = sK[j0 + a][kk]; }
            #pragma unroll
            for (int a = 0; a < 3; a++)
                #pragma unroll
                for (int c2 = 0; c2 < 3; c2++) acc[a][c2] += qa[a] * ka[c2];
        }
        __syncthreads();
    }
    float* outp = g_attn_part + (size_t)blockIdx.x * HD * HD;
    #pragma unroll
    for (int a = 0; a < 3; a++)
        #pragma unroll
        for (int c2 = 0; c2 < 3; c2++) outp[(i0 + a) * HD + j0 + c2] = acc[a][c2];
}

// ---------------- softmax + inline inverse norms + fold scale/temp/vgate ----------------
__global__ void softmax_kernel() {
    __shared__ float row[HD];
    __shared__ float kinv[HD];
    __shared__ float mx, sm, qinv;
    int rid = blockIdx.x;
    int i  = rid % HD;
    int bh = rid / HD;
    int b = bh / HEADS, h = bh % HEADS;
    int t = threadIdx.x;
    const float scale = 0.14433756729740643f;
    if (t < HD) {
        const float* pk = g_ssq_part + ((size_t)b * 3 * C + C + h * HD + t) * 16;
        float s = 0.f;
        #pragma unroll
        for (int j = 0; j < 16; j++) s += pk[j];
        kinv[t] = 1.f / fmaxf(sqrtf(s), 1e-12f);
    }
    if (t == 0) {
        const float* pq = g_ssq_part + ((size_t)b * 3 * C + h * HD + i) * 16;
        float s = 0.f;
        #pragma unroll
        for (int j = 0; j < 16; j++) s += pq[j];
        qinv = 1.f / fmaxf(sqrtf(s), 1e-12f);
    }
    __syncthreads();
    if (t < HD) {
        float s = 0.f;
        const float* pp = g_attn_part + (size_t)bh * NSPLIT * HD * HD + i * HD + t;
        for (int sp = 0; sp < NSPLIT; sp++) s += pp[(size_t)sp * HD * HD];
        row[t] = s * qinv * kinv[t] * scale * g_temp[b * HEADS + h];
    }
    __syncthreads();
    if (t == 0) { float m = -1e30f; for (int j = 0; j < HD; j++) m = fmaxf(m, row[j]); mx = m; }
    __syncthreads();
    if (t < HD) row[t] = expf(row[t] - mx);
    __syncthreads();
    if (t == 0) { float s2 = 0.f; for (int j = 0; j < HD; j++) s2 += row[j]; sm = s2; }
    __syncthreads();
    if (t < HD)
        g_attn[(size_t)bh * HD * HD + i * HD + t] = row[t] / sm * g_vgate[b * C + h * HD + t];
}

// ---------------- fused: g_mid = dwconv(v, w_local) + attn @ v  (packed v, fp32 out) ----------------
__global__ void ogl_kernel(const float* __restrict__ w_local) {
    __shared__ float sA[HD * HD];
    __shared__ float sV[HD][65];
    int bh = blockIdx.y;
    int b = bh / HEADS, h = bh % HEADS;
    int n0 = blockIdx.x * 64;
    const unsigned* vpk = g_buf2_pk + ((size_t)b * QKVP + 2 * KPC + h * (HD / 2)) * NPIX;
    int t = threadIdx.x;
    for (int e = t; e < HD * HD; e += 256) sA[e] = g_attn[(size_t)bh * HD * HD + e];
    for (int e = t; e < (HD / 2) * 64; e += 256) {
        int p = e >> 6, n = e & 63;
        float2 v2 = up2(vpk[(size_t)p * NPIX + n0 + n]);
        sV[2 * p][n] = v2.x; sV[2 * p + 1][n] = v2.y;
    }
    __syncthreads();
    int i0 = (t >> 4) * 3;
    int nl = (t & 15) * 4;
    float acc[3][4];
    #pragma unroll
    for (int a = 0; a < 3; a++)
        #pragma unroll
        for (int q = 0; q < 4; q++) acc[a][q] = 0.f;
    #pragma unroll 4
    for (int j = 0; j < HD; j++) {
        float vv[4];
        #pragma unroll
        for (int q = 0; q < 4; q++) vv[q] = sV[j][nl + q];
        #pragma unroll
        for (int a = 0; a < 3; a++) {
            float aa = sA[(i0 + a) * HD + j];
            #pragma unroll
            for (int q = 0; q < 4; q++) acc[a][q] += aa * vv[q];
        }
    }
    int y = (n0 + nl) >> 7, x = (n0 + nl) & 127;
    #pragma unroll
    for (int a = 0; a < 3; a++) {
        int ch = i0 + a;
        float d[4];
        dw3x3_pk1_v4(vpk + (size_t)(ch >> 1) * NPIX, ch & 1,
                     w_local + (h * HD + ch) * 9, y, x, d);
        #pragma unroll
        for (int q = 0; q < 4; q++) acc[a][q] += d[q];
    }
    float* op = g_mid + (size_t)b * C * NPIX + (size_t)(h * HD) * NPIX + n0;
    #pragma unroll
    for (int a = 0; a < 3; a++)
        #pragma unroll
        for (int q = 0; q < 4; q++)
            op[(size_t)(i0 + a) * NPIX + nl + q] = acc[a][q];
}

// ---------------- launch ----------------
extern "C" void kernel_launch(void* const* d_in, const int* in_sizes, int n_in,
                              void* d_out, int out_size) {
    const float* x        = (const float*)d_in[0];
    const float* ctx      = (const float*)d_in[1];
    const float* ln1_w    = (const float*)d_in[2];
    const float* ln1_b    = (const float*)d_in[3];
    const float* ln2_w    = (const float*)d_in[4];
    const float* ln2_b    = (const float*)d_in[5];
    const float* w_qkv    = (const float*)d_in[6];
    const float* w_qkv_dw = (const float*)d_in[7];
    const float* w_proj   = (const float*)d_in[8];
    const float* base_temp= (const float*)d_in[9];
    const float* ta_w1    = (const float*)d_in[10];
    const float* ta_b1    = (const float*)d_in[11];
    const float* ta_w2    = (const float*)d_in[12];
    const float* ta_b2    = (const float*)d_in[13];
    const float* vg_w     = (const float*)d_in[14];
    const float* vg_b     = (const float*)d_in[15];
    const float* w_local  = (const float*)d_in[16];
    const float* w_ffn_in = (const float*)d_in[17];
    const float* w_ffn_dw = (const float*)d_in[18];
    const float* w_ffn_out= (const float*)d_in[19];
    float* out = (float*)d_out;

    unsigned *p_xn, *p_buf1, *p_buf2, *p_gelu, *p_wqkv, *p_wffin, *p_wout;
    float *p_mid, *p_x2;
    cudaGetSymbolAddress((void**)&p_xn,    g_xn_pk);
    cudaGetSymbolAddress((void**)&p_buf1,  g_buf1_pk);
    cudaGetSymbolAddress((void**)&p_buf2,  g_buf2_pk);
    cudaGetSymbolAddress((void**)&p_mid,   g_mid);
    cudaGetSymbolAddress((void**)&p_x2,    g_x2);
    cudaGetSymbolAddress((void**)&p_gelu,  g_gelu_pk);
    cudaGetSymbolAddress((void**)&p_wqkv,  g_wqkv_pk);
    cudaGetSymbolAddress((void**)&p_wffin, g_wffin_pk);
    cudaGetSymbolAddress((void**)&p_wout,  g_wout_pk);

    ctx_kernel<<<B, 256>>>(ctx, ta_w1, ta_b1, ta_w2, ta_b2, vg_w, vg_b, base_temp);
    pack_all_kernel<<<(NW1 + NW2 + NW3 + 255) / 256, 256>>>(w_qkv, w_ffn_in, w_ffn_out);

    // LN1 -> packed bf16 (smem staged)
    ln_kernel<<<B * NPIX / LNPX, 256>>>(x, ln1_w, ln1_b, p_xn);
    // qkv conv1x1 (576 x 192), bf16 -> packed pairs
    mma_gemm_bf16_pk<<<dim3(NPIX / 256, (3 * C) / 64, B), 256>>>(p_wqkv, p_xn, p_buf1, 3 * C, KPC);
    // qkv dwconv (HFMA2) + q/k sumsq partials
    dwconv_qkv_pk<<<(B * QKVP * NPIX / 4) / 256, 256>>>(p_buf1, w_qkv_dw, p_buf2);
    attn_part_kernel<<<B * HEADS * NSPLIT, 256>>>();
    softmax_kernel<<<B * HEADS * HD, 64>>>();
    // fused out_local + out_global -> g_mid (fp32)
    ogl_kernel<<<dim3(NPIX / 64, B * HEADS), 256>>>(w_local);
    // proj conv1x1 + residual(x), tf32 (fp32 inputs) -> g_x2
    mma_gemm<<<dim3(NPIX / 256, C / 64, B), 256>>>(w_proj, p_mid, p_x2, x, C, C);
    // LN2 -> packed bf16 (smem staged)
    ln_kernel<<<B * NPIX / LNPX, 256>>>(p_x2, ln2_w, ln2_b, p_xn);
    // ffn_in conv1x1 (1020 x 192), bf16 -> packed pairs
    mma_gemm_bf16_pk<<<dim3(NPIX / 256, (FFN2 + 63) / 64, B), 256>>>(p_wffin, p_xn, p_buf1, FFN2, KPC);
    // fused ffn dwconv (HFMA2) + gelu gate, packed -> packed
    dwgelu_pk_kernel<<<(B * KPH * NPIX / 4) / 256, 256>>>(p_buf1, w_ffn_dw, p_gelu);
    // ffn_out conv1x1 (192 x 512 padded) + residual(g_x2) -> fp32 out
    mma_gemm_bf16<<<dim3(NPIX / 256, C / 64, B), 256>>>(p_wout, p_gelu, out, p_x2, C, KPH);
}

// round 14
// speedup vs baseline: 1.1846x; 1.0248x over previous
#include <cuda_runtime.h>
#include <cuda_bf16.h>
#include <math.h>

#define B 8
#define C 192
#define HEADS 4
#define HD 48
#define HGT 128
#define WID 128
#define NPIX 16384
#define CTXD 256
#define HID 510
#define FFN2 1020
#define NSPLIT 32
#define KPC (C / 2)
#define KPH 256
#define QKVP (3 * C / 2)
#define FFP  (FFN2 / 2)
#define LNPX 64

// ---------------- scratch ----------------
__device__ unsigned g_xn_pk [B * KPC * NPIX];
__device__ unsigned g_buf1_pk[B * FFP * NPIX];
__device__ unsigned g_buf2_pk[B * QKVP * NPIX];
__device__ float    g_mid [B * C    * NPIX];
__device__ float    g_x2  [B * C    * NPIX];
__device__ unsigned g_gelu_pk[B * KPH * NPIX];
__device__ unsigned g_wqkv_pk [3 * C * KPC];
__device__ unsigned g_wffin_pk[FFN2  * KPC];
__device__ unsigned g_wout_pk [C * KPH];
__device__ float g_attn_part[B * HEADS * NSPLIT * HD * HD];
__device__ float g_attn[B * HEADS * HD * HD];
__device__ float g_temp [B * HEADS];
__device__ float g_vgate[B * C];
__device__ float g_ssq_part[B * 3 * C * 16];

// ---------------- helpers ----------------
__device__ __forceinline__ unsigned pack_bf2(float lo, float hi) {
    __nv_bfloat162 h = __floats2bfloat162_rn(lo, hi);
    return *reinterpret_cast<unsigned*>(&h);
}
__device__ __forceinline__ float2 up2(unsigned u) {
    __nv_bfloat162 h = *reinterpret_cast<__nv_bfloat162*>(&u);
    return make_float2(__bfloat162float(h.x), __bfloat162float(h.y));
}
__device__ __forceinline__ __nv_bfloat162 asbf2(unsigned u) {
    return *reinterpret_cast<__nv_bfloat162*>(&u);
}
__device__ __forceinline__ unsigned asu32(__nv_bfloat162 h) {
    return *reinterpret_cast<unsigned*>(&h);
}
__device__ __forceinline__ void mma_bf16(float* d, const unsigned* a, const unsigned* b) {
    asm volatile(
        "mma.sync.aligned.m16n8k16.row.col.f32.bf16.bf16.f32 "
        "{%0,%1,%2,%3}, {%4,%5,%6,%7}, {%8,%9}, {%0,%1,%2,%3};\n"
        : "+f"(d[0]), "+f"(d[1]), "+f"(d[2]), "+f"(d[3])
        : "r"(a[0]), "r"(a[1]), "r"(a[2]), "r"(a[3]), "r"(b[0]), "r"(b[1]));
}
__device__ __forceinline__ void mma_tf32(float* d, const unsigned* a, const unsigned* b) {
    asm volatile(
        "mma.sync.aligned.m16n8k8.row.col.f32.tf32.tf32.f32 "
        "{%0,%1,%2,%3}, {%4,%5,%6,%7}, {%8,%9}, {%0,%1,%2,%3};\n"
        : "+f"(d[0]), "+f"(d[1]), "+f"(d[2]), "+f"(d[3])
        : "r"(a[0]), "r"(a[1]), "r"(a[2]), "r"(a[3]), "r"(b[0]), "r"(b[1]));
}
__device__ __forceinline__ unsigned smem_u32(const void* p) {
    return (unsigned)__cvta_generic_to_shared(p);
}
__device__ __forceinline__ void cp16(unsigned dst, const void* src) {
    asm volatile("cp.async.cg.shared.global [%0], [%1], 16;" :: "r"(dst), "l"(src));
}
__device__ __forceinline__ void cp16p(unsigned dst, const void* src, bool pred) {
    int sz = pred ? 16 : 0;
    asm volatile("cp.async.cg.shared.global [%0], [%1], 16, %2;" :: "r"(dst), "l"(src), "r"(sz));
}
__device__ __forceinline__ void cp_commit() { asm volatile("cp.async.commit_group;"); }
template <int N>
__device__ __forceinline__ void cp_wait() { asm volatile("cp.async.wait_group %0;" :: "n"(N)); }

// ---------------- context adapters ----------------
__global__ void ctx_kernel(const float* __restrict__ ctx,
                           const float* __restrict__ ta_w1, const float* __restrict__ ta_b1,
                           const float* __restrict__ ta_w2, const float* __restrict__ ta_b2,
                           const float* __restrict__ vg_w,  const float* __restrict__ vg_b,
                           const float* __restrict__ base_temp) {
    __shared__ float sctx[CTXD];
    __shared__ float hid[HD];
    int b = blockIdx.x, t = threadIdx.x;
    sctx[t] = ctx[b * CTXD + t];
    __syncthreads();
    if (t < HD) {
        float s = ta_b1[t];
        for (int k = 0; k < CTXD; k++) s += sctx[k] * ta_w1[t * CTXD + k];
        hid[t] = fmaxf(s, 0.f);
    }
    __syncthreads();
    if (t < HEADS) {
        float s = ta_b2[t];
        for (int k = 0; k < HD; k++) s += hid[k] * ta_w2[t * HD + k];
        float f = 1.f / (1.f + expf(-s)) * 2.f + 0.5f;
        g_temp[b * HEADS + t] = base_temp[t] * f;
    }
    if (t < C) {
        float s = vg_b[t];
        for (int k = 0; k < CTXD; k++) s += sctx[k] * vg_w[t * CTXD + k];
        g_vgate[b * C + t] = 1.f / (1.f + expf(-s));
    }
}

// ---------------- pack ALL weights in one launch ----------------
#define NW1 (3 * C * KPC)
#define NW2 (FFN2 * KPC)
#define NW3 (C * KPH)
__global__ void pack_all_kernel(const float* __restrict__ wqkv,
                                const float* __restrict__ wffin,
                                const float* __restrict__ wout) {
    int i = blockIdx.x * 256 + threadIdx.x;
    if (i < NW1) {
        int o = i / KPC, p = i % KPC;
        g_wqkv_pk[i] = pack_bf2(wqkv[(size_t)o * C + 2 * p], wqkv[(size_t)o * C + 2 * p + 1]);
    } else if (i < NW1 + NW2) {
        int e = i - NW1;
        int o = e / KPC, p = e % KPC;
        g_wffin_pk[e] = pack_bf2(wffin[(size_t)o * C + 2 * p], wffin[(size_t)o * C + 2 * p + 1]);
    } else if (i < NW1 + NW2 + NW3) {
        int e = i - NW1 - NW2;
        int o = e / KPH, p = e % KPH;
        float f0 = (2 * p     < HID) ? wout[(size_t)o * HID + 2 * p]     : 0.f;
        float f1 = (2 * p + 1 < HID) ? wout[(size_t)o * HID + 2 * p + 1] : 0.f;
        g_wout_pk[e] = pack_bf2(f0, f1);
    }
}

// ---------------- layernorm: smem-staged, 64 px / block -> packed bf16 ----------------
__global__ void __launch_bounds__(256) ln_kernel(const float* __restrict__ x,
                                                 const float* __restrict__ w,
                                                 const float* __restrict__ bias,
                                                 unsigned* __restrict__ out) {
    __shared__ unsigned sXp[KPC][LNPX + 1];
    __shared__ float sRed[2][4][LNPX];
    __shared__ float sMu[LNPX], sRs[LNPX];
    int blk = blockIdx.x;
    int b = blk / (NPIX / LNPX);
    int n0 = (blk % (NPIX / LNPX)) * LNPX;
    int t = threadIdx.x;
    const float* xb = x + (size_t)b * C * NPIX + n0;
    for (int e = t; e < KPC * LNPX; e += 256) {
        int p = e >> 6, j = e & 63;
        float v0 = xb[(size_t)(2 * p)     * NPIX + j];
        float v1 = xb[(size_t)(2 * p + 1) * NPIX + j];
        sXp[p][j] = pack_bf2(v0, v1);
    }
    __syncthreads();
    {
        int j = t >> 2, part = t & 3;
        float s = 0.f, ss = 0.f;
        #pragma unroll 4
        for (int p = part * 24; p < part * 24 + 24; p++) {
            float2 v = up2(sXp[p][j]);
            s += v.x + v.y;
            ss += v.x * v.x + v.y * v.y;
        }
        sRed[0][part][j] = s;
        sRed[1][part][j] = ss;
    }
    __syncthreads();
    if ((t & 3) == 0) {
        int j = t >> 2;
        float st  = sRed[0][0][j] + sRed[0][1][j] + sRed[0][2][j] + sRed[0][3][j];
        float sst = sRed[1][0][j] + sRed[1][1][j] + sRed[1][2][j] + sRed[1][3][j];
        const float ic = 1.f / C;
        float mu = st * ic;
        sMu[j] = mu;
        sRs[j] = rsqrtf(sst * ic - mu * mu + 1e-5f);
    }
    __syncthreads();
    unsigned* ob = out + (size_t)b * KPC * NPIX + n0;
    for (int e = t; e < KPC * LNPX; e += 256) {
        int p = e >> 6, j = e & 63;
        float2 v = up2(sXp[p][j]);
        float mu = sMu[j], rs = sRs[j];
        float v0 = (v.x - mu) * rs * w[2 * p]     + bias[2 * p];
        float v1 = (v.y - mu) * rs * w[2 * p + 1] + bias[2 * p + 1];
        ob[(size_t)p * NPIX + j] = pack_bf2(v0, v1);
    }
}

// ============ GEMM core, 128 threads (4 warps, 2m x 2n), block 64(O) x 128(n) ============
#define GEMM_BODY128(MMAOP, ELT)                                                  \
    int b  = blockIdx.z;                                                          \
    int o0 = blockIdx.y * 64;                                                     \
    int n0 = blockIdx.x * 128;                                                    \
    const ELT* Xb = Xsrc + (size_t)b * Kdim * NPIX + n0;                          \
    int tid  = threadIdx.x;                                                       \
    int warp = tid >> 5, lane = tid & 31;                                         \
    int wm = warp >> 1, wn = warp & 1;                                            \
    int mrow = lane >> 2, kq = lane & 3;                                          \
    float acc[2][8][4];                                                           \
    _Pragma("unroll") for (int mt = 0; mt < 2; mt++)                              \
        _Pragma("unroll") for (int nt = 0; nt < 8; nt++)                          \
            _Pragma("unroll") for (int q = 0; q < 4; q++) acc[mt][nt][q] = 0.f;   \
    int am  = tid >> 1;                                                           \
    int ak8 = (tid & 1) * 8;                                                      \
    bool apred = (o0 + am) < O;                                                   \
    const ELT* aSrcBase = Asrc + (size_t)(o0 + am) * Kdim + ak8;                  \
    int ktiles = Kdim >> 4;                                                       \
    auto LOAD = [&](int kt, int buf) {                                            \
        int p0 = kt << 4;                                                         \
        cp16p(smem_u32(&sA[buf][am][ak8]),     aSrcBase + p0,     apred);         \
        cp16p(smem_u32(&sA[buf][am][ak8 + 4]), aSrcBase + p0 + 4, apred);         \
        _Pragma("unroll") for (int i = 0; i < 4; i++) {                           \
            int e = tid + i * 128;                                                \
            int kk = e >> 5;                                                      \
            int nn = (e & 31) * 4;                                                \
            cp16(smem_u32(&sB[buf][kk][nn]), Xb + (size_t)(p0 + kk) * NPIX + nn); \
        }                                                                         \
        cp_commit();                                                              \
    };                                                                            \
    LOAD(0, 0);                                                                   \
    for (int kt = 0; kt < ktiles; kt++) {                                         \
        int cur = kt & 1;                                                         \
        if (kt + 1 < ktiles) { LOAD(kt + 1, cur ^ 1); cp_wait<1>(); }             \
        else cp_wait<0>();                                                        \
        __syncthreads();                                                          \
        _Pragma("unroll") for (int ks = 0; ks < 2; ks++) {                        \
            const int p0 = ks * 8;                                                \
            unsigned afr[2][4], bfr[8][2];                                        \
            _Pragma("unroll") for (int mt = 0; mt < 2; mt++) {                    \
                int m = wm * 32 + mt * 16 + mrow;                                 \
                afr[mt][0] = sAu[cur][m    ][p0 + kq];                            \
                afr[mt][1] = sAu[cur][m + 8][p0 + kq];                            \
                afr[mt][2] = sAu[cur][m    ][p0 + kq + 4];                        \
                afr[mt][3] = sAu[cur][m + 8][p0 + kq + 4];                        \
            }                                                                     \
            _Pragma("unroll") for (int nt = 0; nt < 8; nt++) {                    \
                int n = wn * 64 + nt * 8 + mrow;                                  \
                bfr[nt][0] = sBu[cur][p0 + kq    ][n];                            \
                bfr[nt][1] = sBu[cur][p0 + kq + 4][n];                            \
            }                                                                     \
            _Pragma("unroll") for (int mt = 0; mt < 2; mt++)                      \
                _Pragma("unroll") for (int nt = 0; nt < 8; nt++)                  \
                    MMAOP(acc[mt][nt], afr[mt], bfr[nt]);                         \
        }                                                                         \
        __syncthreads();                                                          \
    }

// fp32 output + optional fp32 residual (ffn_out)
__global__ void __launch_bounds__(128) mma_gemm_bf16(const unsigned* __restrict__ Asrc,
                                                     const unsigned* __restrict__ Xsrc,
                                                     float* __restrict__ Y,
                                                     const float* __restrict__ Res,
                                                     int O, int Kdim) {
    __shared__ unsigned sA[2][64][20];
    __shared__ unsigned sB[2][16][136];
    const unsigned (*sAu)[64][20]  = sA;
    const unsigned (*sBu)[16][136] = sB;
    GEMM_BODY128(mma_bf16, unsigned)
    size_t base = (size_t)b * O * NPIX;
    #pragma unroll
    for (int mt = 0; mt < 2; mt++) {
        #pragma unroll
        for (int nt = 0; nt < 8; nt++) {
            int ncol = n0 + wn * 64 + nt * 8 + 2 * kq;
            int r0 = o0 + wm * 32 + mt * 16 + mrow;
            if (r0 < O) {
                size_t off = base + (size_t)r0 * NPIX + ncol;
                float2 rr = Res ? *reinterpret_cast<const float2*>(Res + off)
                                : make_float2(0.f, 0.f);
                *reinterpret_cast<float2*>(Y + off) =
                    make_float2(acc[mt][nt][0] + rr.x, acc[mt][nt][1] + rr.y);
            }
            int r1 = r0 + 8;
            if (r1 < O) {
                size_t off = base + (size_t)r1 * NPIX + ncol;
                float2 rr = Res ? *reinterpret_cast<const float2*>(Res + off)
                                : make_float2(0.f, 0.f);
                *reinterpret_cast<float2*>(Y + off) =
                    make_float2(acc[mt][nt][2] + rr.x, acc[mt][nt][3] + rr.y);
            }
        }
    }
}

// packed bf16 channel-pair output (qkv / ffn_in). O must be even.
__global__ void __launch_bounds__(128) mma_gemm_bf16_pk(const unsigned* __restrict__ Asrc,
                                                        const unsigned* __restrict__ Xsrc,
                                                        unsigned* __restrict__ Ypk,
                                                        int O, int Kdim) {
    __shared__ unsigned sA[2][64][20];
    __shared__ unsigned sB[2][16][136];
    const unsigned (*sAu)[64][20]  = sA;
    const unsigned (*sBu)[16][136] = sB;
    GEMM_BODY128(mma_bf16, unsigned)
    size_t base = (size_t)b * (O >> 1) * NPIX;
    bool writer = ((mrow & 1) == 0);
    #pragma unroll
    for (int mt = 0; mt < 2; mt++) {
        #pragma unroll
        for (int nt = 0; nt < 8; nt++) {
            int ncol = n0 + wn * 64 + nt * 8 + 2 * kq;
            int r0 = o0 + wm * 32 + mt * 16 + mrow;
            float p0 = __shfl_xor_sync(0xffffffffu, acc[mt][nt][0], 4);
            float p1 = __shfl_xor_sync(0xffffffffu, acc[mt][nt][1], 4);
            float p2 = __shfl_xor_sync(0xffffffffu, acc[mt][nt][2], 4);
            float p3 = __shfl_xor_sync(0xffffffffu, acc[mt][nt][3], 4);
            if (writer && r0 < O) {
                size_t off = base + (size_t)(r0 >> 1) * NPIX + ncol;
                *reinterpret_cast<uint2*>(Ypk + off) =
                    make_uint2(pack_bf2(acc[mt][nt][0], p0), pack_bf2(acc[mt][nt][1], p1));
            }
            if (writer && r0 + 8 < O) {
                size_t off = base + (size_t)((r0 + 8) >> 1) * NPIX + ncol;
                *reinterpret_cast<uint2*>(Ypk + off) =
                    make_uint2(pack_bf2(acc[mt][nt][2], p2), pack_bf2(acc[mt][nt][3], p3));
            }
        }
    }
}

// tf32 GEMM (fp32 inputs) — proj only
__global__ void __launch_bounds__(128) mma_gemm(const float* __restrict__ Asrc,
                                                const float* __restrict__ Xsrc,
                                                float* __restrict__ Y,
                                                const float* __restrict__ Res,
                                                int O, int Kdim) {
    __shared__ float sA[2][64][20];
    __shared__ float sB[2][16][136];
    const unsigned (*sAu)[64][20]  = reinterpret_cast<const unsigned (*)[64][20]>(sA);
    const unsigned (*sBu)[16][136] = reinterpret_cast<const unsigned (*)[16][136]>(sB);
    GEMM_BODY128(mma_tf32, float)
    size_t base = (size_t)b * O * NPIX;
    #pragma unroll
    for (int mt = 0; mt < 2; mt++) {
        #pragma unroll
        for (int nt = 0; nt < 8; nt++) {
            int ncol = n0 + wn * 64 + nt * 8 + 2 * kq;
            int r0 = o0 + wm * 32 + mt * 16 + mrow;
            if (r0 < O) {
                size_t off = base + (size_t)r0 * NPIX + ncol;
                float2 rr = Res ? *reinterpret_cast<const float2*>(Res + off)
                                : make_float2(0.f, 0.f);
                *reinterpret_cast<float2*>(Y + off) =
                    make_float2(acc[mt][nt][0] + rr.x, acc[mt][nt][1] + rr.y);
            }
            int r1 = r0 + 8;
            if (r1 < O) {
                size_t off = base + (size_t)r1 * NPIX + ncol;
                float2 rr = Res ? *reinterpret_cast<const float2*>(Res + off)
                                : make_float2(0.f, 0.f);
                *reinterpret_cast<float2*>(Y + off) =
                    make_float2(acc[mt][nt][2] + rr.x, acc[mt][nt][3] + rr.y);
            }
        }
    }
}

// NOTE: for tf32 the mma consumes fp32 bit patterns; tf32 MMA truncates mantissa in HW.
// (Inner loop uses 8 k-steps of the 16-wide float tile per ks, matching prior rounds.)

// ---------------- bf16x2 dual-channel 3x3 depthwise (HFMA2), 4 px / thread ----------------
__device__ __forceinline__ void dw3x3_h2_v4(const unsigned* __restrict__ ip,
                                            const __nv_bfloat162* __restrict__ sw,
                                            int y, int x, __nv_bfloat162* acc) {
    __nv_bfloat162 z = __float2bfloat162_rn(0.f);
    acc[0] = z; acc[1] = z; acc[2] = z; acc[3] = z;
    #pragma unroll
    for (int ky = 0; ky < 3; ky++) {
        int yy = y + ky - 1;
        if (yy < 0 || yy >= HGT) continue;
        const unsigned* row = ip + yy * WID + x;
        uint4 m = *reinterpret_cast<const uint4*>(row);
        unsigned lu = (x > 0)   ? row[-1] : 0u;
        unsigned ru = (x < 124) ? row[4]  : 0u;
        __nv_bfloat162 L = asbf2(lu), X0 = asbf2(m.x), X1 = asbf2(m.y),
                       X2 = asbf2(m.z), X3 = asbf2(m.w), R = asbf2(ru);
        __nv_bfloat162 w0 = sw[ky * 3], w1 = sw[ky * 3 + 1], w2 = sw[ky * 3 + 2];
        acc[0] = __hfma2(L,  w0, __hfma2(X0, w1, __hfma2(X1, w2, acc[0])));
        acc[1] = __hfma2(X0, w0, __hfma2(X1, w1, __hfma2(X2, w2, acc[1])));
        acc[2] = __hfma2(X1, w0, __hfma2(X2, w1, __hfma2(X3, w2, acc[2])));
        acc[3] = __hfma2(X2, w0, __hfma2(X3, w1, __hfma2(R,  w2, acc[3])));
    }
}

// single-channel from packed plane (for ogl local conv)
__device__ __forceinline__ void dw3x3_pk1_v4(const unsigned* __restrict__ ip, int hi,
                                             const float* __restrict__ wp,
                                             int y, int x, float* acc) {
    acc[0] = acc[1] = acc[2] = acc[3] = 0.f;
    #pragma unroll
    for (int ky = 0; ky < 3; ky++) {
        int yy = y + ky - 1;
        if (yy < 0 || yy >= HGT) continue;
        const unsigned* row = ip + yy * WID + x;
        uint4 m = *reinterpret_cast<const uint4*>(row);
        unsigned lu = (x > 0)   ? row[-1] : 0u;
        unsigned ru = (x < 124) ? row[4]  : 0u;
        float L, X0, X1, X2, X3, R;
        if (hi) {
            L = up2(lu).y; X0 = up2(m.x).y; X1 = up2(m.y).y; X2 = up2(m.z).y; X3 = up2(m.w).y; R = up2(ru).y;
        } else {
            L = up2(lu).x; X0 = up2(m.x).x; X1 = up2(m.y).x; X2 = up2(m.z).x; X3 = up2(m.w).x; R = up2(ru).x;
        }
        float w0 = wp[ky * 3], w1 = wp[ky * 3 + 1], w2 = wp[ky * 3 + 2];
        acc[0] += L  * w0 + X0 * w1 + X1 * w2;
        acc[1] += X0 * w0 + X1 * w1 + X2 * w2;
        acc[2] += X1 * w0 + X2 * w1 + X3 * w2;
        acc[3] += X2 * w0 + X3 * w1 + R  * w2;
    }
}

// ---------------- qkv dwconv (HFMA2) + q/k sumsq partials ----------------
__global__ void dwconv_qkv_pk(const unsigned* __restrict__ in, const float* __restrict__ w,
                              unsigned* __restrict__ out) {
    __shared__ float2 red2[256];
    __shared__ __nv_bfloat162 swt[9];
    int idx = blockIdx.x * 256 + threadIdx.x;
    int n = (idx & (NPIX / 4 - 1)) * 4;
    int bp = idx >> 12;
    int p = bp % QKVP;
    if (threadIdx.x < 9)
        swt[threadIdx.x] = __floats2bfloat162_rn(w[(2 * p) * 9 + threadIdx.x],
                                                 w[(2 * p + 1) * 9 + threadIdx.x]);
    __syncthreads();
    int y = n >> 7, x = n & 127;
    const unsigned* ip = in + (size_t)bp * NPIX;
    __nv_bfloat162 acc[4];
    dw3x3_h2_v4(ip, swt, y, x, acc);
    unsigned o4[4];
    #pragma unroll
    for (int j = 0; j < 4; j++) o4[j] = asu32(acc[j]);
    *reinterpret_cast<uint4*>(out + (size_t)bp * NPIX + n) =
        make_uint4(o4[0], o4[1], o4[2], o4[3]);
    if (p < 2 * KPC) {
        int b = bp / QKVP;
        float ss0 = 0.f, ss1 = 0.f;
        #pragma unroll
        for (int j = 0; j < 4; j++) {
            float2 v = up2(o4[j]);
            ss0 += v.x * v.x; ss1 += v.y * v.y;
        }
        red2[threadIdx.x] = make_float2(ss0, ss1);
        __syncthreads();
        for (int s = 128; s > 0; s >>= 1) {
            if (threadIdx.x < s) {
                red2[threadIdx.x].x += red2[threadIdx.x + s].x;
                red2[threadIdx.x].y += red2[threadIdx.x + s].y;
            }
            __syncthreads();
        }
        if (threadIdx.x == 0) {
            int blk = blockIdx.x & 15;
            g_ssq_part[((size_t)b * 3 * C + 2 * p) * 16 + blk]     = red2[0].x;
            g_ssq_part[((size_t)b * 3 * C + 2 * p + 1) * 16 + blk] = red2[0].y;
        }
    }
}

// ---------------- fused FFN dwconv (HFMA2) + gelu gate ----------------
__global__ void dwgelu_pk_kernel(const unsigned* __restrict__ in, const float* __restrict__ w,
                                 unsigned* __restrict__ outg) {
    __shared__ __nv_bfloat162 swA[9], swB[9];
    int idx = blockIdx.x * 256 + threadIdx.x;
    int n = (idx & (NPIX / 4 - 1)) * 4;
    int bc = idx >> 12;
    int p = bc & (KPH - 1), b = bc >> 8;
    unsigned* op = outg + (size_t)bc * NPIX + n;
    if (p == KPH - 1) {
        *reinterpret_cast<uint4*>(op) = make_uint4(0u, 0u, 0u, 0u);
        return;
    }
    int c = 2 * p;
    if (threadIdx.x < 9) {
        swA[threadIdx.x] = __floats2bfloat162_rn(w[c * 9 + threadIdx.x],
                                                 w[(c + 1) * 9 + threadIdx.x]);
        swB[threadIdx.x] = __floats2bfloat162_rn(w[(c + HID) * 9 + threadIdx.x],
                                                 w[(c + 1 + HID) * 9 + threadIdx.x]);
    }
    __syncthreads();
    int y = n >> 7, x = n & 127;
    const unsigned* base = in + (size_t)b * FFP * NPIX;
    __nv_bfloat162 a1[4], a2[4];
    dw3x3_h2_v4(base + (size_t)p * NPIX,         swA, y, x, a1);
    dw3x3_h2_v4(base + (size_t)(p + 255) * NPIX, swB, y, x, a2);
    unsigned o4[4];
    #pragma unroll
    for (int j = 0; j < 4; j++) {
        float2 y1 = up2(asu32(a1[j]));
        float2 y2 = up2(asu32(a2[j]));
        float ga = 0.5f * y1.x * (1.f + erff(y1.x * 0.70710678118654752f)) * y2.x;
        float gb = 0.5f * y1.y * (1.f + erff(y1.y * 0.70710678118654752f)) * y2.y;
        o4[j] = pack_bf2(ga, gb);
    }
    *reinterpret_cast<uint4*>(op) = make_uint4(o4[0], o4[1], o4[2], o4[3]);
}

// ---------------- attention gram partials (packed q,k) ----------------
__global__ void attn_part_kernel() {
    __shared__ float sQ[HD][33], sK[HD][33];
    int bh = blockIdx.x / NSPLIT, sp = blockIdx.x % NSPLIT;
    int b = bh / HEADS, h = bh % HEADS;
    const unsigned* qpk = g_buf2_pk + ((size_t)b * QKVP + h * (HD / 2)) * NPIX;
    const unsigned* kpk = qpk + (size_t)KPC * NPIX;
    int t = threadIdx.x;
    int i0 = (t >> 4) * 3, j0 = (t & 15) * 3;
    float acc[3][3];
    #pragma unroll
    for (int a = 0; a < 3; a++)
        #pragma unroll
        for (int c2 = 0; c2 < 3; c2++) acc[a][c2] = 0.f;
    int n0 = sp * (NPIX / NSPLIT);
    for (int ch = 0; ch < NPIX / NSPLIT; ch += 32) {
        for (int e = t; e < (HD / 2) * 32; e += 256) {
            int p = e >> 5, nn = e & 31;
            float2 q2 = up2(qpk[(size_t)p * NPIX + n0 + ch + nn]);
            float2 k2 = up2(kpk[(size_t)p * NPIX + n0 + ch + nn]);
            sQ[2 * p][nn] = q2.x; sQ[2 * p + 1][nn] = q2.y;
            sK[2 * p][nn] = k2.x; sK[2 * p + 1][nn] = k2.y;
        }
        __syncthreads();
        #pragma unroll 4
        for (int kk = 0; kk < 32; kk++) {
            float qa[3], ka[3];
            #pragma unroll
            for (int a = 0; a < 3; a++) { qa[a] = sQ[i0 + a][kk]; ka[a] = sK[j0 + a][kk]; }
            #pragma unroll
            for (int a = 0; a < 3; a++)
                #pragma unroll
                for (int c2 = 0; c2 < 3; c2++) acc[a][c2] += qa[a] * ka[c2];
        }
        __syncthreads();
    }
    float* outp = g_attn_part + (size_t)blockIdx.x * HD * HD;
    #pragma unroll
    for (int a = 0; a < 3; a++)
        #pragma unroll
        for (int c2 = 0; c2 < 3; c2++) outp[(i0 + a) * HD + j0 + c2] = acc[a][c2];
}

// ---------------- softmax + inline inverse norms + fold scale/temp/vgate ----------------
__global__ void softmax_kernel() {
    __shared__ float row[HD];
    __shared__ float kinv[HD];
    __shared__ float mx, sm, qinv;
    int rid = blockIdx.x;
    int i  = rid % HD;
    int bh = rid / HD;
    int b = bh / HEADS, h = bh % HEADS;
    int t = threadIdx.x;
    const float scale = 0.14433756729740643f;
    if (t < HD) {
        const float* pk = g_ssq_part + ((size_t)b * 3 * C + C + h * HD + t) * 16;
        float s = 0.f;
        #pragma unroll
        for (int j = 0; j < 16; j++) s += pk[j];
        kinv[t] = 1.f / fmaxf(sqrtf(s), 1e-12f);
    }
    if (t == 0) {
        const float* pq = g_ssq_part + ((size_t)b * 3 * C + h * HD + i) * 16;
        float s = 0.f;
        #pragma unroll
        for (int j = 0; j < 16; j++) s += pq[j];
        qinv = 1.f / fmaxf(sqrtf(s), 1e-12f);
    }
    __syncthreads();
    if (t < HD) {
        float s = 0.f;
        const float* pp = g_attn_part + (size_t)bh * NSPLIT * HD * HD + i * HD + t;
        for (int sp = 0; sp < NSPLIT; sp++) s += pp[(size_t)sp * HD * HD];
        row[t] = s * qinv * kinv[t] * scale * g_temp[b * HEADS + h];
    }
    __syncthreads();
    if (t == 0) { float m = -1e30f; for (int j = 0; j < HD; j++) m = fmaxf(m, row[j]); mx = m; }
    __syncthreads();
    if (t < HD) row[t] = expf(row[t] - mx);
    __syncthreads();
    if (t == 0) { float s2 = 0.f; for (int j = 0; j < HD; j++) s2 += row[j]; sm = s2; }
    __syncthreads();
    if (t < HD)
        g_attn[(size_t)bh * HD * HD + i * HD + t] = row[t] / sm * g_vgate[b * C + h * HD + t];
}

// ---------------- fused: g_mid = dwconv(v, w_local) + attn @ v ----------------
__global__ void ogl_kernel(const float* __restrict__ w_local) {
    __shared__ float sA[HD * HD];
    __shared__ float sV[HD][65];
    int bh = blockIdx.y;
    int b = bh / HEADS, h = bh % HEADS;
    int n0 = blockIdx.x * 64;
    const unsigned* vpk = g_buf2_pk + ((size_t)b * QKVP + 2 * KPC + h * (HD / 2)) * NPIX;
    int t = threadIdx.x;
    for (int e = t; e < HD * HD; e += 256) sA[e] = g_attn[(size_t)bh * HD * HD + e];
    for (int e = t; e < (HD / 2) * 64; e += 256) {
        int p = e >> 6, n = e & 63;
        float2 v2 = up2(vpk[(size_t)p * NPIX + n0 + n]);
        sV[2 * p][n] = v2.x; sV[2 * p + 1][n] = v2.y;
    }
    __syncthreads();
    int i0 = (t >> 4) * 3;
    int nl = (t & 15) * 4;
    float acc[3][4];
    #pragma unroll
    for (int a = 0; a < 3; a++)
        #pragma unroll
        for (int q = 0; q < 4; q++) acc[a][q] = 0.f;
    #pragma unroll 4
    for (int j = 0; j < HD; j++) {
        float vv[4];
        #pragma unroll
        for (int q = 0; q < 4; q++) vv[q] = sV[j][nl + q];
        #pragma unroll
        for (int a = 0; a < 3; a++) {
            float aa = sA[(i0 + a) * HD + j];
            #pragma unroll
            for (int q = 0; q < 4; q++) acc[a][q] += aa * vv[q];
        }
    }
    int y = (n0 + nl) >> 7, x = (n0 + nl) & 127;
    #pragma unroll
    for (int a = 0; a < 3; a++) {
        int ch = i0 + a;
        float d[4];
        dw3x3_pk1_v4(vpk + (size_t)(ch >> 1) * NPIX, ch & 1,
                     w_local + (h * HD + ch) * 9, y, x, d);
        #pragma unroll
        for (int q = 0; q < 4; q++) acc[a][q] += d[q];
    }
    float* op = g_mid + (size_t)b * C * NPIX + (size_t)(h * HD) * NPIX + n0;
    #pragma unroll
    for (int a = 0; a < 3; a++)
        #pragma unroll
        for (int q = 0; q < 4; q++)
            op[(size_t)(i0 + a) * NPIX + nl + q] = acc[a][q];
}

// ---------------- launch ----------------
extern "C" void kernel_launch(void* const* d_in, const int* in_sizes, int n_in,
                              void* d_out, int out_size) {
    const float* x        = (const float*)d_in[0];
    const float* ctx      = (const float*)d_in[1];
    const float* ln1_w    = (const float*)d_in[2];
    const float* ln1_b    = (const float*)d_in[3];
    const float* ln2_w    = (const float*)d_in[4];
    const float* ln2_b    = (const float*)d_in[5];
    const float* w_qkv    = (const float*)d_in[6];
    const float* w_qkv_dw = (const float*)d_in[7];
    const float* w_proj   = (const float*)d_in[8];
    const float* base_temp= (const float*)d_in[9];
    const float* ta_w1    = (const float*)d_in[10];
    const float* ta_b1    = (const float*)d_in[11];
    const float* ta_w2    = (const float*)d_in[12];
    const float* ta_b2    = (const float*)d_in[13];
    const float* vg_w     = (const float*)d_in[14];
    const float* vg_b     = (const float*)d_in[15];
    const float* w_local  = (const float*)d_in[16];
    const float* w_ffn_in = (const float*)d_in[17];
    const float* w_ffn_dw = (const float*)d_in[18];
    const float* w_ffn_out= (const float*)d_in[19];
    float* out = (float*)d_out;

    unsigned *p_xn, *p_buf1, *p_buf2, *p_gelu, *p_wqkv, *p_wffin, *p_wout;
    float *p_mid, *p_x2;
    cudaGetSymbolAddress((void**)&p_xn,    g_xn_pk);
    cudaGetSymbolAddress((void**)&p_buf1,  g_buf1_pk);
    cudaGetSymbolAddress((void**)&p_buf2,  g_buf2_pk);
    cudaGetSymbolAddress((void**)&p_mid,   g_mid);
    cudaGetSymbolAddress((void**)&p_x2,    g_x2);
    cudaGetSymbolAddress((void**)&p_gelu,  g_gelu_pk);
    cudaGetSymbolAddress((void**)&p_wqkv,  g_wqkv_pk);
    cudaGetSymbolAddress((void**)&p_wffin, g_wffin_pk);
    cudaGetSymbolAddress((void**)&p_wout,  g_wout_pk);

    ctx_kernel<<<B, 256>>>(ctx, ta_w1, ta_b1, ta_w2, ta_b2, vg_w, vg_b, base_temp);
    pack_all_kernel<<<(NW1 + NW2 + NW3 + 255) / 256, 256>>>(w_qkv, w_ffn_in, w_ffn_out);

    // LN1 -> packed bf16 (smem staged)
    ln_kernel<<<B * NPIX / LNPX, 256>>>(x, ln1_w, ln1_b, p_xn);
    // qkv conv1x1 (576 x 192), bf16 -> packed pairs
    mma_gemm_bf16_pk<<<dim3(NPIX / 128, (3 * C) / 64, B), 128>>>(p_wqkv, p_xn, p_buf1, 3 * C, KPC);
    // qkv dwconv (HFMA2) + q/k sumsq partials
    dwconv_qkv_pk<<<(B * QKVP * NPIX / 4) / 256, 256>>>(p_buf1, w_qkv_dw, p_buf2);
    attn_part_kernel<<<B * HEADS * NSPLIT, 256>>>();
    softmax_kernel<<<B * HEADS * HD, 64>>>();
    // fused out_local + out_global -> g_mid (fp32)
    ogl_kernel<<<dim3(NPIX / 64, B * HEADS), 256>>>(w_local);
    // proj conv1x1 + residual(x), tf32 -> g_x2
    mma_gemm<<<dim3(NPIX / 128, C / 64, B), 128>>>(w_proj, p_mid, p_x2, x, C, C);
    // LN2 -> packed bf16 (smem staged)
    ln_kernel<<<B * NPIX / LNPX, 256>>>(p_x2, ln2_w, ln2_b, p_xn);
    // ffn_in conv1x1 (1020 x 192), bf16 -> packed pairs
    mma_gemm_bf16_pk<<<dim3(NPIX / 128, (FFN2 + 63) / 64, B), 128>>>(p_wffin, p_xn, p_buf1, FFN2, KPC);
    // fused ffn dwconv (HFMA2) + gelu gate
    dwgelu_pk_kernel<<<(B * KPH * NPIX / 4) / 256, 256>>>(p_buf1, w_ffn_dw, p_gelu);
    // ffn_out conv1x1 (192 x 512 padded) + residual(g_x2) -> fp32 out
    mma_gemm_bf16<<<dim3(NPIX / 128, C / 64, B), 128>>>(p_wout, p_gelu, out, p_x2, C, KPH);
}

// round 15
// speedup vs baseline: 1.2063x; 1.0183x over previous
#include <cuda_runtime.h>
#include <cuda_bf16.h>
#include <math.h>

#define B 8
#define C 192
#define HEADS 4
#define HD 48
#define HGT 128
#define WID 128
#define NPIX 16384
#define CTXD 256
#define HID 510
#define FFN2 1020
#define NSPLIT 32
#define KPC (C / 2)
#define KPH 256
#define QKVP (3 * C / 2)
#define FFP  (FFN2 / 2)
#define LNPX 64

// ---------------- scratch ----------------
__device__ unsigned g_xn_pk [B * KPC * NPIX];
__device__ unsigned g_buf1_pk[B * FFP * NPIX];
__device__ unsigned g_buf2_pk[B * QKVP * NPIX];
__device__ float    g_mid [B * C    * NPIX];
__device__ float    g_x2  [B * C    * NPIX];
__device__ unsigned g_gelu_pk[B * KPH * NPIX];
__device__ unsigned g_wqkv_pk [3 * C * KPC];
__device__ unsigned g_wffin_pk[FFN2  * KPC];
__device__ unsigned g_wout_pk [C * KPH];
__device__ float g_attn_part[B * HEADS * NSPLIT * HD * HD];
__device__ float g_attn[B * HEADS * HD * HD];
__device__ float g_temp [B * HEADS];
__device__ float g_vgate[B * C];
__device__ float g_ssq_part[B * 3 * C * 16];

// ---------------- helpers ----------------
__device__ __forceinline__ unsigned pack_bf2(float lo, float hi) {
    __nv_bfloat162 h = __floats2bfloat162_rn(lo, hi);
    return *reinterpret_cast<unsigned*>(&h);
}
__device__ __forceinline__ float2 up2(unsigned u) {
    __nv_bfloat162 h = *reinterpret_cast<__nv_bfloat162*>(&u);
    return make_float2(__bfloat162float(h.x), __bfloat162float(h.y));
}
__device__ __forceinline__ __nv_bfloat162 asbf2(unsigned u) {
    return *reinterpret_cast<__nv_bfloat162*>(&u);
}
__device__ __forceinline__ unsigned asu32(__nv_bfloat162 h) {
    return *reinterpret_cast<unsigned*>(&h);
}
__device__ __forceinline__ void mma_bf16(float* d, const unsigned* a, const unsigned* b) {
    asm volatile(
        "mma.sync.aligned.m16n8k16.row.col.f32.bf16.bf16.f32 "
        "{%0,%1,%2,%3}, {%4,%5,%6,%7}, {%8,%9}, {%0,%1,%2,%3};\n"
        : "+f"(d[0]), "+f"(d[1]), "+f"(d[2]), "+f"(d[3])
        : "r"(a[0]), "r"(a[1]), "r"(a[2]), "r"(a[3]), "r"(b[0]), "r"(b[1]));
}
__device__ __forceinline__ void mma_tf32(float* d, const unsigned* a, const unsigned* b) {
    asm volatile(
        "mma.sync.aligned.m16n8k8.row.col.f32.tf32.tf32.f32 "
        "{%0,%1,%2,%3}, {%4,%5,%6,%7}, {%8,%9}, {%0,%1,%2,%3};\n"
        : "+f"(d[0]), "+f"(d[1]), "+f"(d[2]), "+f"(d[3])
        : "r"(a[0]), "r"(a[1]), "r"(a[2]), "r"(a[3]), "r"(b[0]), "r"(b[1]));
}
__device__ __forceinline__ void ldsm_x4(unsigned* r, unsigned saddr) {
    asm volatile("ldmatrix.sync.aligned.m8n8.x4.shared.b16 {%0,%1,%2,%3}, [%4];"
        : "=r"(r[0]), "=r"(r[1]), "=r"(r[2]), "=r"(r[3]) : "r"(saddr));
}
__device__ __forceinline__ unsigned smem_u32(const void* p) {
    return (unsigned)__cvta_generic_to_shared(p);
}
__device__ __forceinline__ void cp16(unsigned dst, const void* src) {
    asm volatile("cp.async.cg.shared.global [%0], [%1], 16;" :: "r"(dst), "l"(src));
}
__device__ __forceinline__ void cp16p(unsigned dst, const void* src, bool pred) {
    int sz = pred ? 16 : 0;
    asm volatile("cp.async.cg.shared.global [%0], [%1], 16, %2;" :: "r"(dst), "l"(src), "r"(sz));
}
__device__ __forceinline__ void cp_commit() { asm volatile("cp.async.commit_group;"); }
template <int N>
__device__ __forceinline__ void cp_wait() { asm volatile("cp.async.wait_group %0;" :: "n"(N)); }

// ---------------- context adapters ----------------
__global__ void ctx_kernel(const float* __restrict__ ctx,
                           const float* __restrict__ ta_w1, const float* __restrict__ ta_b1,
                           const float* __restrict__ ta_w2, const float* __restrict__ ta_b2,
                           const float* __restrict__ vg_w,  const float* __restrict__ vg_b,
                           const float* __restrict__ base_temp) {
    __shared__ float sctx[CTXD];
    __shared__ float hid[HD];
    int b = blockIdx.x, t = threadIdx.x;
    sctx[t] = ctx[b * CTXD + t];
    __syncthreads();
    if (t < HD) {
        float s = ta_b1[t];
        for (int k = 0; k < CTXD; k++) s += sctx[k] * ta_w1[t * CTXD + k];
        hid[t] = fmaxf(s, 0.f);
    }
    __syncthreads();
    if (t < HEADS) {
        float s = ta_b2[t];
        for (int k = 0; k < HD; k++) s += hid[k] * ta_w2[t * HD + k];
        float f = 1.f / (1.f + expf(-s)) * 2.f + 0.5f;
        g_temp[b * HEADS + t] = base_temp[t] * f;
    }
    if (t < C) {
        float s = vg_b[t];
        for (int k = 0; k < CTXD; k++) s += sctx[k] * vg_w[t * CTXD + k];
        g_vgate[b * C + t] = 1.f / (1.f + expf(-s));
    }
}

// ---------------- pack ALL weights in one launch ----------------
#define NW1 (3 * C * KPC)
#define NW2 (FFN2 * KPC)
#define NW3 (C * KPH)
__global__ void pack_all_kernel(const float* __restrict__ wqkv,
                                const float* __restrict__ wffin,
                                const float* __restrict__ wout) {
    int i = blockIdx.x * 256 + threadIdx.x;
    if (i < NW1) {
        int o = i / KPC, p = i % KPC;
        g_wqkv_pk[i] = pack_bf2(wqkv[(size_t)o * C + 2 * p], wqkv[(size_t)o * C + 2 * p + 1]);
    } else if (i < NW1 + NW2) {
        int e = i - NW1;
        int o = e / KPC, p = e % KPC;
        g_wffin_pk[e] = pack_bf2(wffin[(size_t)o * C + 2 * p], wffin[(size_t)o * C + 2 * p + 1]);
    } else if (i < NW1 + NW2 + NW3) {
        int e = i - NW1 - NW2;
        int o = e / KPH, p = e % KPH;
        float f0 = (2 * p     < HID) ? wout[(size_t)o * HID + 2 * p]     : 0.f;
        float f1 = (2 * p + 1 < HID) ? wout[(size_t)o * HID + 2 * p + 1] : 0.f;
        g_wout_pk[e] = pack_bf2(f0, f1);
    }
}

// ---------------- layernorm: smem-staged, 64 px / block -> packed bf16 ----------------
__global__ void __launch_bounds__(256) ln_kernel(const float* __restrict__ x,
                                                 const float* __restrict__ w,
                                                 const float* __restrict__ bias,
                                                 unsigned* __restrict__ out) {
    __shared__ unsigned sXp[KPC][LNPX + 1];
    __shared__ float sRed[2][4][LNPX];
    __shared__ float sMu[LNPX], sRs[LNPX];
    int blk = blockIdx.x;
    int b = blk / (NPIX / LNPX);
    int n0 = (blk % (NPIX / LNPX)) * LNPX;
    int t = threadIdx.x;
    const float* xb = x + (size_t)b * C * NPIX + n0;
    for (int e = t; e < KPC * LNPX; e += 256) {
        int p = e >> 6, j = e & 63;
        float v0 = xb[(size_t)(2 * p)     * NPIX + j];
        float v1 = xb[(size_t)(2 * p + 1) * NPIX + j];
        sXp[p][j] = pack_bf2(v0, v1);
    }
    __syncthreads();
    {
        int j = t >> 2, part = t & 3;
        float s = 0.f, ss = 0.f;
        #pragma unroll 4
        for (int p = part * 24; p < part * 24 + 24; p++) {
            float2 v = up2(sXp[p][j]);
            s += v.x + v.y;
            ss += v.x * v.x + v.y * v.y;
        }
        sRed[0][part][j] = s;
        sRed[1][part][j] = ss;
    }
    __syncthreads();
    if ((t & 3) == 0) {
        int j = t >> 2;
        float st  = sRed[0][0][j] + sRed[0][1][j] + sRed[0][2][j] + sRed[0][3][j];
        float sst = sRed[1][0][j] + sRed[1][1][j] + sRed[1][2][j] + sRed[1][3][j];
        const float ic = 1.f / C;
        float mu = st * ic;
        sMu[j] = mu;
        sRs[j] = rsqrtf(sst * ic - mu * mu + 1e-5f);
    }
    __syncthreads();
    unsigned* ob = out + (size_t)b * KPC * NPIX + n0;
    for (int e = t; e < KPC * LNPX; e += 256) {
        int p = e >> 6, j = e & 63;
        float2 v = up2(sXp[p][j]);
        float mu = sMu[j], rs = sRs[j];
        float v0 = (v.x - mu) * rs * w[2 * p]     + bias[2 * p];
        float v1 = (v.y - mu) * rs * w[2 * p + 1] + bias[2 * p + 1];
        ob[(size_t)p * NPIX + j] = pack_bf2(v0, v1);
    }
}

// ============ GEMM core, 128 threads (4 warps, 2m x 2n), block 64(O) x 128(n) ============
// A-fragments via ldmatrix.x4: lanes 0-7/8-15/16-23/24-31 address rows
// {m, m+8} x pair-offset {0, +4}; 16B chunks are aligned (row stride 80B).
#define GEMM_BODY128(MMAOP, ELT)                                                  \
    int b  = blockIdx.z;                                                          \
    int o0 = blockIdx.y * 64;                                                     \
    int n0 = blockIdx.x * 128;                                                    \
    const ELT* Xb = Xsrc + (size_t)b * Kdim * NPIX + n0;                          \
    int tid  = threadIdx.x;                                                       \
    int warp = tid >> 5, lane = tid & 31;                                         \
    int wm = warp >> 1, wn = warp & 1;                                            \
    int mrow = lane >> 2, kq = lane & 3;                                          \
    float acc[2][8][4];                                                           \
    _Pragma("unroll") for (int mt = 0; mt < 2; mt++)                              \
        _Pragma("unroll") for (int nt = 0; nt < 8; nt++)                          \
            _Pragma("unroll") for (int q = 0; q < 4; q++) acc[mt][nt][q] = 0.f;   \
    int lmi = lane >> 3;                                                          \
    unsigned aoff = (unsigned)((((lmi & 1) << 3) + (lane & 7)) * 20 +             \
                               ((lmi >> 1) << 2));                                \
    unsigned aBase = smem_u32(&sA[0][0][0]);                                      \
    int am  = tid >> 1;                                                           \
    int ak8 = (tid & 1) * 8;                                                      \
    bool apred = (o0 + am) < O;                                                   \
    const ELT* aSrcBase = Asrc + (size_t)(o0 + am) * Kdim + ak8;                  \
    int ktiles = Kdim >> 4;                                                       \
    auto LOAD = [&](int kt, int buf) {                                            \
        int p0 = kt << 4;                                                         \
        cp16p(smem_u32(&sA[buf][am][ak8]),     aSrcBase + p0,     apred);         \
        cp16p(smem_u32(&sA[buf][am][ak8 + 4]), aSrcBase + p0 + 4, apred);         \
        _Pragma("unroll") for (int i = 0; i < 4; i++) {                           \
            int e = tid + i * 128;                                                \
            int kk = e >> 5;                                                      \
            int nn = (e & 31) * 4;                                                \
            cp16(smem_u32(&sB[buf][kk][nn]), Xb + (size_t)(p0 + kk) * NPIX + nn); \
        }                                                                         \
        cp_commit();                                                              \
    };                                                                            \
    LOAD(0, 0);                                                                   \
    for (int kt = 0; kt < ktiles; kt++) {                                         \
        int cur = kt & 1;                                                         \
        if (kt + 1 < ktiles) { LOAD(kt + 1, cur ^ 1); cp_wait<1>(); }             \
        else cp_wait<0>();                                                        \
        __syncthreads();                                                          \
        unsigned aCur = aBase + 4u * ((unsigned)cur * 1280u + aoff);              \
        _Pragma("unroll") for (int ks = 0; ks < 2; ks++) {                        \
            const int p0 = ks * 8;                                                \
            unsigned afr[2][4], bfr[8][2];                                        \
            _Pragma("unroll") for (int mt = 0; mt < 2; mt++)                      \
                ldsm_x4(afr[mt],                                                  \
                        aCur + 4u * (unsigned)((wm * 32 + mt * 16) * 20 + p0));   \
            _Pragma("unroll") for (int nt = 0; nt < 8; nt++) {                    \
                int n = wn * 64 + nt * 8 + mrow;                                  \
                bfr[nt][0] = sBu[cur][p0 + kq    ][n];                            \
                bfr[nt][1] = sBu[cur][p0 + kq + 4][n];                            \
            }                                                                     \
            _Pragma("unroll") for (int mt = 0; mt < 2; mt++)                      \
                _Pragma("unroll") for (int nt = 0; nt < 8; nt++)                  \
                    MMAOP(acc[mt][nt], afr[mt], bfr[nt]);                         \
        }                                                                         \
        __syncthreads();                                                          \
    }

// fp32 output + optional fp32 residual (ffn_out)
__global__ void __launch_bounds__(128) mma_gemm_bf16(const unsigned* __restrict__ Asrc,
                                                     const unsigned* __restrict__ Xsrc,
                                                     float* __restrict__ Y,
                                                     const float* __restrict__ Res,
                                                     int O, int Kdim) {
    __shared__ unsigned sA[2][64][20];
    __shared__ unsigned sB[2][16][136];
    const unsigned (*sBu)[16][136] = sB;
    GEMM_BODY128(mma_bf16, unsigned)
    size_t base = (size_t)b * O * NPIX;
    #pragma unroll
    for (int mt = 0; mt < 2; mt++) {
        #pragma unroll
        for (int nt = 0; nt < 8; nt++) {
            int ncol = n0 + wn * 64 + nt * 8 + 2 * kq;
            int r0 = o0 + wm * 32 + mt * 16 + mrow;
            if (r0 < O) {
                size_t off = base + (size_t)r0 * NPIX + ncol;
                float2 rr = Res ? *reinterpret_cast<const float2*>(Res + off)
                                : make_float2(0.f, 0.f);
                *reinterpret_cast<float2*>(Y + off) =
                    make_float2(acc[mt][nt][0] + rr.x, acc[mt][nt][1] + rr.y);
            }
            int r1 = r0 + 8;
            if (r1 < O) {
                size_t off = base + (size_t)r1 * NPIX + ncol;
                float2 rr = Res ? *reinterpret_cast<const float2*>(Res + off)
                                : make_float2(0.f, 0.f);
                *reinterpret_cast<float2*>(Y + off) =
                    make_float2(acc[mt][nt][2] + rr.x, acc[mt][nt][3] + rr.y);
            }
        }
    }
}

// packed bf16 channel-pair output (qkv / ffn_in). O must be even.
__global__ void __launch_bounds__(128) mma_gemm_bf16_pk(const unsigned* __restrict__ Asrc,
                                                        const unsigned* __restrict__ Xsrc,
                                                        unsigned* __restrict__ Ypk,
                                                        int O, int Kdim) {
    __shared__ unsigned sA[2][64][20];
    __shared__ unsigned sB[2][16][136];
    const unsigned (*sBu)[16][136] = sB;
    GEMM_BODY128(mma_bf16, unsigned)
    size_t base = (size_t)b * (O >> 1) * NPIX;
    bool writer = ((mrow & 1) == 0);
    #pragma unroll
    for (int mt = 0; mt < 2; mt++) {
        #pragma unroll
        for (int nt = 0; nt < 8; nt++) {
            int ncol = n0 + wn * 64 + nt * 8 + 2 * kq;
            int r0 = o0 + wm * 32 + mt * 16 + mrow;
            float p0 = __shfl_xor_sync(0xffffffffu, acc[mt][nt][0], 4);
            float p1 = __shfl_xor_sync(0xffffffffu, acc[mt][nt][1], 4);
            float p2 = __shfl_xor_sync(0xffffffffu, acc[mt][nt][2], 4);
            float p3 = __shfl_xor_sync(0xffffffffu, acc[mt][nt][3], 4);
            if (writer && r0 < O) {
                size_t off = base + (size_t)(r0 >> 1) * NPIX + ncol;
                *reinterpret_cast<uint2*>(Ypk + off) =
                    make_uint2(pack_bf2(acc[mt][nt][0], p0), pack_bf2(acc[mt][nt][1], p1));
            }
            if (writer && r0 + 8 < O) {
                size_t off = base + (size_t)((r0 + 8) >> 1) * NPIX + ncol;
                *reinterpret_cast<uint2*>(Ypk + off) =
                    make_uint2(pack_bf2(acc[mt][nt][2], p2), pack_bf2(acc[mt][nt][3], p3));
            }
        }
    }
}

// tf32 GEMM (fp32 inputs) — proj only.  A-fragments also via ldmatrix
// (4 fp32 = 16B rows, identical lane->chunk mapping).
__global__ void __launch_bounds__(128) mma_gemm(const float* __restrict__ Asrc,
                                                const float* __restrict__ Xsrc,
                                                float* __restrict__ Y,
                                                const float* __restrict__ Res,
                                                int O, int Kdim) {
    __shared__ float sA[2][64][20];
    __shared__ float sB[2][16][136];
    const unsigned (*sBu)[16][136] = reinterpret_cast<const unsigned (*)[16][136]>(sB);
    GEMM_BODY128(mma_tf32, float)
    size_t base = (size_t)b * O * NPIX;
    #pragma unroll
    for (int mt = 0; mt < 2; mt++) {
        #pragma unroll
        for (int nt = 0; nt < 8; nt++) {
            int ncol = n0 + wn * 64 + nt * 8 + 2 * kq;
            int r0 = o0 + wm * 32 + mt * 16 + mrow;
            if (r0 < O) {
                size_t off = base + (size_t)r0 * NPIX + ncol;
                float2 rr = Res ? *reinterpret_cast<const float2*>(Res + off)
                                : make_float2(0.f, 0.f);
                *reinterpret_cast<float2*>(Y + off) =
                    make_float2(acc[mt][nt][0] + rr.x, acc[mt][nt][1] + rr.y);
            }
            int r1 = r0 + 8;
            if (r1 < O) {
                size_t off = base + (size_t)r1 * NPIX + ncol;
                float2 rr = Res ? *reinterpret_cast<const float2*>(Res + off)
                                : make_float2(0.f, 0.f);
                *reinterpret_cast<float2*>(Y + off) =
                    make_float2(acc[mt][nt][2] + rr.x, acc[mt][nt][3] + rr.y);
            }
        }
    }
}

// ---------------- bf16x2 dual-channel 3x3 depthwise (HFMA2), 4 px / thread ----------------
__device__ __forceinline__ void dw3x3_h2_v4(const unsigned* __restrict__ ip,
                                            const __nv_bfloat162* __restrict__ sw,
                                            int y, int x, __nv_bfloat162* acc) {
    __nv_bfloat162 z = __float2bfloat162_rn(0.f);
    acc[0] = z; acc[1] = z; acc[2] = z; acc[3] = z;
    #pragma unroll
    for (int ky = 0; ky < 3; ky++) {
        int yy = y + ky - 1;
        if (yy < 0 || yy >= HGT) continue;
        const unsigned* row = ip + yy * WID + x;
        uint4 m = *reinterpret_cast<const uint4*>(row);
        unsigned lu = (x > 0)   ? row[-1] : 0u;
        unsigned ru = (x < 124) ? row[4]  : 0u;
        __nv_bfloat162 L = asbf2(lu), X0 = asbf2(m.x), X1 = asbf2(m.y),
                       X2 = asbf2(m.z), X3 = asbf2(m.w), R = asbf2(ru);
        __nv_bfloat162 w0 = sw[ky * 3], w1 = sw[ky * 3 + 1], w2 = sw[ky * 3 + 2];
        acc[0] = __hfma2(L,  w0, __hfma2(X0, w1, __hfma2(X1, w2, acc[0])));
        acc[1] = __hfma2(X0, w0, __hfma2(X1, w1, __hfma2(X2, w2, acc[1])));
        acc[2] = __hfma2(X1, w0, __hfma2(X2, w1, __hfma2(X3, w2, acc[2])));
        acc[3] = __hfma2(X2, w0, __hfma2(X3, w1, __hfma2(R,  w2, acc[3])));
    }
}

// single-channel from packed plane (for ogl local conv)
__device__ __forceinline__ void dw3x3_pk1_v4(const unsigned* __restrict__ ip, int hi,
                                             const float* __restrict__ wp,
                                             int y, int x, float* acc) {
    acc[0] = acc[1] = acc[2] = acc[3] = 0.f;
    #pragma unroll
    for (int ky = 0; ky < 3; ky++) {
        int yy = y + ky - 1;
        if (yy < 0 || yy >= HGT) continue;
        const unsigned* row = ip + yy * WID + x;
        uint4 m = *reinterpret_cast<const uint4*>(row);
        unsigned lu = (x > 0)   ? row[-1] : 0u;
        unsigned ru = (x < 124) ? row[4]  : 0u;
        float L, X0, X1, X2, X3, R;
        if (hi) {
            L = up2(lu).y; X0 = up2(m.x).y; X1 = up2(m.y).y; X2 = up2(m.z).y; X3 = up2(m.w).y; R = up2(ru).y;
        } else {
            L = up2(lu).x; X0 = up2(m.x).x; X1 = up2(m.y).x; X2 = up2(m.z).x; X3 = up2(m.w).x; R = up2(ru).x;
        }
        float w0 = wp[ky * 3], w1 = wp[ky * 3 + 1], w2 = wp[ky * 3 + 2];
        acc[0] += L  * w0 + X0 * w1 + X1 * w2;
        acc[1] += X0 * w0 + X1 * w1 + X2 * w2;
        acc[2] += X1 * w0 + X2 * w1 + X3 * w2;
        acc[3] += X2 * w0 + X3 * w1 + R  * w2;
    }
}

// ---------------- qkv dwconv (HFMA2) + q/k sumsq partials ----------------
__global__ void dwconv_qkv_pk(const unsigned* __restrict__ in, const float* __restrict__ w,
                              unsigned* __restrict__ out) {
    __shared__ float2 red2[256];
    __shared__ __nv_bfloat162 swt[9];
    int idx = blockIdx.x * 256 + threadIdx.x;
    int n = (idx & (NPIX / 4 - 1)) * 4;
    int bp = idx >> 12;
    int p = bp % QKVP;
    if (threadIdx.x < 9)
        swt[threadIdx.x] = __floats2bfloat162_rn(w[(2 * p) * 9 + threadIdx.x],
                                                 w[(2 * p + 1) * 9 + threadIdx.x]);
    __syncthreads();
    int y = n >> 7, x = n & 127;
    const unsigned* ip = in + (size_t)bp * NPIX;
    __nv_bfloat162 acc[4];
    dw3x3_h2_v4(ip, swt, y, x, acc);
    unsigned o4[4];
    #pragma unroll
    for (int j = 0; j < 4; j++) o4[j] = asu32(acc[j]);
    *reinterpret_cast<uint4*>(out + (size_t)bp * NPIX + n) =
        make_uint4(o4[0], o4[1], o4[2], o4[3]);
    if (p < 2 * KPC) {
        int b = bp / QKVP;
        float ss0 = 0.f, ss1 = 0.f;
        #pragma unroll
        for (int j = 0; j < 4; j++) {
            float2 v = up2(o4[j]);
            ss0 += v.x * v.x; ss1 += v.y * v.y;
        }
        red2[threadIdx.x] = make_float2(ss0, ss1);
        __syncthreads();
        for (int s = 128; s > 0; s >>= 1) {
            if (threadIdx.x < s) {
                red2[threadIdx.x].x += red2[threadIdx.x + s].x;
                red2[threadIdx.x].y += red2[threadIdx.x + s].y;
            }
            __syncthreads();
        }
        if (threadIdx.x == 0) {
            int blk = blockIdx.x & 15;
            g_ssq_part[((size_t)b * 3 * C + 2 * p) * 16 + blk]     = red2[0].x;
            g_ssq_part[((size_t)b * 3 * C + 2 * p + 1) * 16 + blk] = red2[0].y;
        }
    }
}

// ---------------- fused FFN dwconv (HFMA2) + gelu gate ----------------
__global__ void dwgelu_pk_kernel(const unsigned* __restrict__ in, const float* __restrict__ w,
                                 unsigned* __restrict__ outg) {
    __shared__ __nv_bfloat162 swA[9], swB[9];
    int idx = blockIdx.x * 256 + threadIdx.x;
    int n = (idx & (NPIX / 4 - 1)) * 4;
    int bc = idx >> 12;
    int p = bc & (KPH - 1), b = bc >> 8;
    unsigned* op = outg + (size_t)bc * NPIX + n;
    if (p == KPH - 1) {
        *reinterpret_cast<uint4*>(op) = make_uint4(0u, 0u, 0u, 0u);
        return;
    }
    int c = 2 * p;
    if (threadIdx.x < 9) {
        swA[threadIdx.x] = __floats2bfloat162_rn(w[c * 9 + threadIdx.x],
                                                 w[(c + 1) * 9 + threadIdx.x]);
        swB[threadIdx.x] = __floats2bfloat162_rn(w[(c + HID) * 9 + threadIdx.x],
                                                 w[(c + 1 + HID) * 9 + threadIdx.x]);
    }
    __syncthreads();
    int y = n >> 7, x = n & 127;
    const unsigned* base = in + (size_t)b * FFP * NPIX;
    __nv_bfloat162 a1[4], a2[4];
    dw3x3_h2_v4(base + (size_t)p * NPIX,         swA, y, x, a1);
    dw3x3_h2_v4(base + (size_t)(p + 255) * NPIX, swB, y, x, a2);
    unsigned o4[4];
    #pragma unroll
    for (int j = 0; j < 4; j++) {
        float2 y1 = up2(asu32(a1[j]));
        float2 y2 = up2(asu32(a2[j]));
        float ga = 0.5f * y1.x * (1.f + erff(y1.x * 0.70710678118654752f)) * y2.x;
        float gb = 0.5f * y1.y * (1.f + erff(y1.y * 0.70710678118654752f)) * y2.y;
        o4[j] = pack_bf2(ga, gb);
    }
    *reinterpret_cast<uint4*>(op) = make_uint4(o4[0], o4[1], o4[2], o4[3]);
}

// ---------------- attention gram partials (packed q,k) ----------------
__global__ void attn_part_kernel() {
    __shared__ float sQ[HD][33], sK[HD][33];
    int bh = blockIdx.x / NSPLIT, sp = blockIdx.x % NSPLIT;
    int b = bh / HEADS, h = bh % HEADS;
    const unsigned* qpk = g_buf2_pk + ((size_t)b * QKVP + h * (HD / 2)) * NPIX;
    const unsigned* kpk = qpk + (size_t)KPC * NPIX;
    int t = threadIdx.x;
    int i0 = (t >> 4) * 3, j0 = (t & 15) * 3;
    float acc[3][3];
    #pragma unroll
    for (int a = 0; a < 3; a++)
        #pragma unroll
        for (int c2 = 0; c2 < 3; c2++) acc[a][c2] = 0.f;
    int n0 = sp * (NPIX / NSPLIT);
    for (int ch = 0; ch < NPIX / NSPLIT; ch += 32) {
        for (int e = t; e < (HD / 2) * 32; e += 256) {
            int p = e >> 5, nn = e & 31;
            float2 q2 = up2(qpk[(size_t)p * NPIX + n0 + ch + nn]);
            float2 k2 = up2(kpk[(size_t)p * NPIX + n0 + ch + nn]);
            sQ[2 * p][nn] = q2.x; sQ[2 * p + 1][nn] = q2.y;
            sK[2 * p][nn] = k2.x; sK[2 * p + 1][nn] = k2.y;
        }
        __syncthreads();
        #pragma unroll 4
        for (int kk = 0; kk < 32; kk++) {
            float qa[3], ka[3];
            #pragma unroll
            for (int a = 0; a < 3; a++) { qa[a] = sQ[i0 + a][kk]; ka[a] = sK[j0 + a][kk]; }
            #pragma unroll
            for (int a = 0; a < 3; a++)
                #pragma unroll
                for (int c2 = 0; c2 < 3; c2++) acc[a][c2] += qa[a] * ka[c2];
        }
        __syncthreads();
    }
    float* outp = g_attn_part + (size_t)blockIdx.x * HD * HD;
    #pragma unroll
    for (int a = 0; a < 3; a++)
        #pragma unroll
        for (int c2 = 0; c2 < 3; c2++) outp[(i0 + a) * HD + j0 + c2] = acc[a][c2];
}

// ---------------- softmax + inline inverse norms + fold scale/temp/vgate ----------------
__global__ void softmax_kernel() {
    __shared__ float row[HD];
    __shared__ float kinv[HD];
    __shared__ float mx, sm, qinv;
    int rid = blockIdx.x;
    int i  = rid % HD;
    int bh = rid / HD;
    int b = bh / HEADS, h = bh % HEADS;
    int t = threadIdx.x;
    const float scale = 0.14433756729740643f;
    if (t < HD) {
        const float* pk = g_ssq_part + ((size_t)b * 3 * C + C + h * HD + t) * 16;
        float s = 0.f;
        #pragma unroll
        for (int j = 0; j < 16; j++) s += pk[j];
        kinv[t] = 1.f / fmaxf(sqrtf(s), 1e-12f);
    }
    if (t == 0) {
        const float* pq = g_ssq_part + ((size_t)b * 3 * C + h * HD + i) * 16;
        float s = 0.f;
        #pragma unroll
        for (int j = 0; j < 16; j++) s += pq[j];
        qinv = 1.f / fmaxf(sqrtf(s), 1e-12f);
    }
    __syncthreads();
    if (t < HD) {
        float s = 0.f;
        const float* pp = g_attn_part + (size_t)bh * NSPLIT * HD * HD + i * HD + t;
        for (int sp = 0; sp < NSPLIT; sp++) s += pp[(size_t)sp * HD * HD];
        row[t] = s * qinv * kinv[t] * scale * g_temp[b * HEADS + h];
    }
    __syncthreads();
    if (t == 0) { float m = -1e30f; for (int j = 0; j < HD; j++) m = fmaxf(m, row[j]); mx = m; }
    __syncthreads();
    if (t < HD) row[t] = expf(row[t] - mx);
    __syncthreads();
    if (t == 0) { float s2 = 0.f; for (int j = 0; j < HD; j++) s2 += row[j]; sm = s2; }
    __syncthreads();
    if (t < HD)
        g_attn[(size_t)bh * HD * HD + i * HD + t] = row[t] / sm * g_vgate[b * C + h * HD + t];
}

// ---------------- fused: g_mid = dwconv(v, w_local) + attn @ v ----------------
__global__ void ogl_kernel(const float* __restrict__ w_local) {
    __shared__ float sA[HD * HD];
    __shared__ float sV[HD][65];
    int bh = blockIdx.y;
    int b = bh / HEADS, h = bh % HEADS;
    int n0 = blockIdx.x * 64;
    const unsigned* vpk = g_buf2_pk + ((size_t)b * QKVP + 2 * KPC + h * (HD / 2)) * NPIX;
    int t = threadIdx.x;
    for (int e = t; e < HD * HD; e += 256) sA[e] = g_attn[(size_t)bh * HD * HD + e];
    for (int e = t; e < (HD / 2) * 64; e += 256) {
        int p = e >> 6, n = e & 63;
        float2 v2 = up2(vpk[(size_t)p * NPIX + n0 + n]);
        sV[2 * p][n] = v2.x; sV[2 * p + 1][n] = v2.y;
    }
    __syncthreads();
    int i0 = (t >> 4) * 3;
    int nl = (t & 15) * 4;
    float acc[3][4];
    #pragma unroll
    for (int a = 0; a < 3; a++)
        #pragma unroll
        for (int q = 0; q < 4; q++) acc[a][q] = 0.f;
    #pragma unroll 4
    for (int j = 0; j < HD; j++) {
        float vv[4];
        #pragma unroll
        for (int q = 0; q < 4; q++) vv[q] = sV[j][nl + q];
        #pragma unroll
        for (int a = 0; a < 3; a++) {
            float aa = sA[(i0 + a) * HD + j];
            #pragma unroll
            for (int q = 0; q < 4; q++) acc[a][q] += aa * vv[q];
        }
    }
    int y = (n0 + nl) >> 7, x = (n0 + nl) & 127;
    #pragma unroll
    for (int a = 0; a < 3; a++) {
        int ch = i0 + a;
        float d[4];
        dw3x3_pk1_v4(vpk + (size_t)(ch >> 1) * NPIX, ch & 1,
                     w_local + (h * HD + ch) * 9, y, x, d);
        #pragma unroll
        for (int q = 0; q < 4; q++) acc[a][q] += d[q];
    }
    float* op = g_mid + (size_t)b * C * NPIX + (size_t)(h * HD) * NPIX + n0;
    #pragma unroll
    for (int a = 0; a < 3; a++)
        #pragma unroll
        for (int q = 0; q < 4; q++)
            op[(size_t)(i0 + a) * NPIX + nl + q] = acc[a][q];
}

// ---------------- launch ----------------
extern "C" void kernel_launch(void* const* d_in, const int* in_sizes, int n_in,
                              void* d_out, int out_size) {
    const float* x        = (const float*)d_in[0];
    const float* ctx      = (const float*)d_in[1];
    const float* ln1_w    = (const float*)d_in[2];
    const float* ln1_b    = (const float*)d_in[3];
    const float* ln2_w    = (const float*)d_in[4];
    const float* ln2_b    = (const float*)d_in[5];
    const float* w_qkv    = (const float*)d_in[6];
    const float* w_qkv_dw = (const float*)d_in[7];
    const float* w_proj   = (const float*)d_in[8];
    const float* base_temp= (const float*)d_in[9];
    const float* ta_w1    = (const float*)d_in[10];
    const float* ta_b1    = (const float*)d_in[11];
    const float* ta_w2    = (const float*)d_in[12];
    const float* ta_b2    = (const float*)d_in[13];
    const float* vg_w     = (const float*)d_in[14];
    const float* vg_b     = (const float*)d_in[15];
    const float* w_local  = (const float*)d_in[16];
    const float* w_ffn_in = (const float*)d_in[17];
    const float* w_ffn_dw = (const float*)d_in[18];
    const float* w_ffn_out= (const float*)d_in[19];
    float* out = (float*)d_out;

    unsigned *p_xn, *p_buf1, *p_buf2, *p_gelu, *p_wqkv, *p_wffin, *p_wout;
    float *p_mid, *p_x2;
    cudaGetSymbolAddress((void**)&p_xn,    g_xn_pk);
    cudaGetSymbolAddress((void**)&p_buf1,  g_buf1_pk);
    cudaGetSymbolAddress((void**)&p_buf2,  g_buf2_pk);
    cudaGetSymbolAddress((void**)&p_mid,   g_mid);
    cudaGetSymbolAddress((void**)&p_x2,    g_x2);
    cudaGetSymbolAddress((void**)&p_gelu,  g_gelu_pk);
    cudaGetSymbolAddress((void**)&p_wqkv,  g_wqkv_pk);
    cudaGetSymbolAddress((void**)&p_wffin, g_wffin_pk);
    cudaGetSymbolAddress((void**)&p_wout,  g_wout_pk);

    ctx_kernel<<<B, 256>>>(ctx, ta_w1, ta_b1, ta_w2, ta_b2, vg_w, vg_b, base_temp);
    pack_all_kernel<<<(NW1 + NW2 + NW3 + 255) / 256, 256>>>(w_qkv, w_ffn_in, w_ffn_out);

    // LN1 -> packed bf16 (smem staged)
    ln_kernel<<<B * NPIX / LNPX, 256>>>(x, ln1_w, ln1_b, p_xn);
    // qkv conv1x1 (576 x 192), bf16 -> packed pairs
    mma_gemm_bf16_pk<<<dim3(NPIX / 128, (3 * C) / 64, B), 128>>>(p_wqkv, p_xn, p_buf1, 3 * C, KPC);
    // qkv dwconv (HFMA2) + q/k sumsq partials
    dwconv_qkv_pk<<<(B * QKVP * NPIX / 4) / 256, 256>>>(p_buf1, w_qkv_dw, p_buf2);
    attn_part_kernel<<<B * HEADS * NSPLIT, 256>>>();
    softmax_kernel<<<B * HEADS * HD, 64>>>();
    // fused out_local + out_global -> g_mid (fp32)
    ogl_kernel<<<dim3(NPIX / 64, B * HEADS), 256>>>(w_local);
    // proj conv1x1 + residual(x), tf32 -> g_x2
    mma_gemm<<<dim3(NPIX / 128, C / 64, B), 128>>>(w_proj, p_mid, p_x2, x, C, C);
    // LN2 -> packed bf16 (smem staged)
    ln_kernel<<<B * NPIX / LNPX, 256>>>(p_x2, ln2_w, ln2_b, p_xn);
    // ffn_in conv1x1 (1020 x 192), bf16 -> packed pairs
    mma_gemm_bf16_pk<<<dim3(NPIX / 128, (FFN2 + 63) / 64, B), 128>>>(p_wffin, p_xn, p_buf1, FFN2, KPC);
    // fused ffn dwconv (HFMA2) + gelu gate
    dwgelu_pk_kernel<<<(B * KPH * NPIX / 4) / 256, 256>>>(p_buf1, w_ffn_dw, p_gelu);
    // ffn_out conv1x1 (192 x 512 padded) + residual(g_x2) -> fp32 out
    mma_gemm_bf16<<<dim3(NPIX / 128, C / 64, B), 128>>>(p_wout, p_gelu, out, p_x2, C, KPH);
}